// round 2
// baseline (speedup 1.0000x reference)
#include <cuda_runtime.h>
#include <cuda_bf16.h>
#include <cstdint>

// Problem constants
#define NPOS   32768          // B*L = 8*4096
#define LSEQ   4096
#define EDIM   128
#define HDIM   256
#define DDIM   64
#define KCODE  512
#define VOCAB  4096
#define LN_EPS 1e-5f

// ---------------- scratch (static device globals; no allocation) -------------
__device__ float g_emb[NPOS * EDIM];    // embedding / decoder-E reuse
__device__ float g_h1 [NPOS * HDIM];
__device__ float g_h2 [NPOS * HDIM];
__device__ float g_z  [NPOS * DDIM];    // z_e after LN
__device__ float g_zq [NPOS * DDIM];    // quantized
__device__ int   g_codes[NPOS];
__device__ float g_cnorm[KCODE];
__device__ float g_commit[NPOS / 64];   // per-block partial sums (512)

// ---------------- embedding lookup ------------------------------------------
__global__ void embed_kernel(const int* __restrict__ x,
                             const float* __restrict__ tok,
                             float* __restrict__ emb)
{
    int idx = blockIdx.x * blockDim.x + threadIdx.x;   // NPOS*32 float4s
    int n = idx >> 5;
    int j = idx & 31;
    int t = x[n];
    reinterpret_cast<float4*>(emb)[n * 32 + j] =
        reinterpret_cast<const float4*>(tok)[t * 32 + j];
}

// ---------------- generic implicit-im2col SGEMM conv -------------------------
// X: [NPOS, CIN] position-major.  W: [COUT, CIN, KW].  Y: [NPOS, COUT].
// y[p,o] = bias[o] + sum_{k,ci} w[o,ci,k] * x[p+k-PAD, ci]  (zero outside seq)
template<int CIN, int COUT, int KW, bool RELU>
__global__ void __launch_bounds__(256)
conv_gemm(const float* __restrict__ X, const float* __restrict__ W,
          const float* __restrict__ Bias, float* __restrict__ Y)
{
    constexpr int R   = CIN * KW;
    constexpr int PAD = (KW == 3) ? 1 : 0;
    __shared__ float As[32][66];   // As[r][m]  (reduction x positions)
    __shared__ float Bs[32][66];   // Bs[r][n]  (reduction x out-channels)

    const int pm0 = blockIdx.x * 64;
    const int on0 = blockIdx.y * 64;
    const int tid = threadIdx.x;
    const int tx = tid & 15, ty = tid >> 4;
    const int rr = tid & 31;        // reduction index within chunk
    const int mrow = tid >> 5;      // 0..7

    float acc[4][4];
#pragma unroll
    for (int i = 0; i < 4; i++)
#pragma unroll
        for (int j = 0; j < 4; j++) acc[i][j] = 0.f;

    for (int r0 = 0; r0 < R; r0 += 32) {
        const int r  = r0 + rr;
        const int k  = r / CIN;          // constant within chunk (CIN%32==0)
        const int ci = r - k * CIN;
#pragma unroll
        for (int i = 0; i < 8; i++) {
            const int m = mrow + i * 8;
            const int p = pm0 + m;
            float v = 0.f;
            if (PAD == 0) {
                v = X[(size_t)p * CIN + ci];
            } else {
                const int l  = p & (LSEQ - 1);
                const int ls = l + k - PAD;
                if ((unsigned)ls < (unsigned)LSEQ)
                    v = X[(size_t)(p + k - PAD) * CIN + ci];
            }
            As[rr][m] = v;
        }
#pragma unroll
        for (int i = 0; i < 8; i++) {
            const int n = mrow + i * 8;
            Bs[rr][n] = W[(size_t)(on0 + n) * R + ci * KW + k];
        }
        __syncthreads();
#pragma unroll
        for (int kk = 0; kk < 32; kk++) {
            float a[4], b[4];
#pragma unroll
            for (int i = 0; i < 4; i++) a[i] = As[kk][ty * 4 + i];
#pragma unroll
            for (int j = 0; j < 4; j++) b[j] = Bs[kk][tx * 4 + j];
#pragma unroll
            for (int i = 0; i < 4; i++)
#pragma unroll
                for (int j = 0; j < 4; j++)
                    acc[i][j] = fmaf(a[i], b[j], acc[i][j]);
        }
        __syncthreads();
    }
#pragma unroll
    for (int i = 0; i < 4; i++) {
        const int p = pm0 + ty * 4 + i;
#pragma unroll
        for (int j = 0; j < 4; j++) {
            const int o = on0 + tx * 4 + j;
            float v = acc[i][j] + Bias[o];
            if (RELU) v = fmaxf(v, 0.f);
            Y[(size_t)p * COUT + o] = v;
        }
    }
}

// ---------------- encoder head: conv1x1 (256->64) + LayerNorm(D=64) ---------
__global__ void __launch_bounds__(256)
enc_head_ln(const float* __restrict__ X, const float* __restrict__ W,
            const float* __restrict__ Bias,
            const float* __restrict__ G, const float* __restrict__ Bt,
            float* __restrict__ Z)
{
    constexpr int CIN = 256;
    __shared__ float As[32][66];
    __shared__ float Bs[32][66];
    __shared__ float Zs[64][66];

    const int pm0 = blockIdx.x * 64;
    const int tid = threadIdx.x;
    const int tx = tid & 15, ty = tid >> 4;
    const int rr = tid & 31;
    const int mrow = tid >> 5;

    float acc[4][4];
#pragma unroll
    for (int i = 0; i < 4; i++)
#pragma unroll
        for (int j = 0; j < 4; j++) acc[i][j] = 0.f;

    for (int r0 = 0; r0 < CIN; r0 += 32) {
        const int ci = r0 + rr;
#pragma unroll
        for (int i = 0; i < 8; i++) {
            const int m = mrow + i * 8;
            As[rr][m] = X[(size_t)(pm0 + m) * CIN + ci];
        }
#pragma unroll
        for (int i = 0; i < 8; i++) {
            const int n = mrow + i * 8;
            Bs[rr][n] = W[(size_t)n * CIN + ci];
        }
        __syncthreads();
#pragma unroll
        for (int kk = 0; kk < 32; kk++) {
            float a[4], b[4];
#pragma unroll
            for (int i = 0; i < 4; i++) a[i] = As[kk][ty * 4 + i];
#pragma unroll
            for (int j = 0; j < 4; j++) b[j] = Bs[kk][tx * 4 + j];
#pragma unroll
            for (int i = 0; i < 4; i++)
#pragma unroll
                for (int j = 0; j < 4; j++)
                    acc[i][j] = fmaf(a[i], b[j], acc[i][j]);
        }
        __syncthreads();
    }
#pragma unroll
    for (int i = 0; i < 4; i++)
#pragma unroll
        for (int j = 0; j < 4; j++)
            Zs[ty * 4 + i][tx * 4 + j] = acc[i][j] + Bias[tx * 4 + j];
    __syncthreads();

    // LayerNorm over D=64 (two-pass, matching reference formula): 8 warps x 8 rows
    const int lane = tid & 31, w = tid >> 5;
#pragma unroll
    for (int q = 0; q < 8; q++) {
        const int m = w * 8 + q;
        float v0 = Zs[m][lane];
        float v1 = Zs[m][lane + 32];
        float s = v0 + v1;
#pragma unroll
        for (int off = 16; off > 0; off >>= 1)
            s += __shfl_xor_sync(0xffffffffu, s, off);
        float mu = s * (1.f / 64.f);
        float d0 = v0 - mu, d1 = v1 - mu;
        float sq = __fadd_rn(__fmul_rn(d0, d0), __fmul_rn(d1, d1));
#pragma unroll
        for (int off = 16; off > 0; off >>= 1)
            sq += __shfl_xor_sync(0xffffffffu, sq, off);
        float var = sq * (1.f / 64.f);
        float rs  = rsqrtf(var + LN_EPS);
        const int p = pm0 + m;
        Z[(size_t)p * 64 + lane]      = d0 * rs * G[lane]      + Bt[lane];
        Z[(size_t)p * 64 + lane + 32] = d1 * rs * G[lane + 32] + Bt[lane + 32];
    }
}

// ---------------- codebook norms (no FMA: match sum(c*c)) --------------------
__global__ void cnorm_kernel(const float* __restrict__ CB, float* __restrict__ CN)
{
    int c = blockIdx.x * blockDim.x + threadIdx.x;
    if (c < KCODE) {
        float s = 0.f;
        for (int d = 0; d < DDIM; d++) {
            float v = CB[c * DDIM + d];
            s = __fadd_rn(s, __fmul_rn(v, v));
        }
        CN[c] = s;
    }
}

// ---------------- VQ: argmin over codes + commit-loss partials ---------------
// dist computed exactly like reference: (||z||^2 - 2*z.c) + ||c||^2
// so near-tie rounding/quantization matches jnp.argmin's decisions.
__global__ void __launch_bounds__(256)
vq_kernel(const float* __restrict__ Z, const float* __restrict__ CB,
          const float* __restrict__ CN, int* __restrict__ Codes,
          float* __restrict__ CommitPart)
{
    __shared__ float Zt[64][66];   // Zt[d][m]
    __shared__ float Cs[64][66];   // Cs[d][c] — reused for argmin reduce
    __shared__ float znS[64];
    __shared__ float cvals[64];

    const int pm0 = blockIdx.x * 64;
    const int tid = threadIdx.x;
    const int tx = tid & 15, ty = tid >> 4;

#pragma unroll
    for (int i = 0; i < 16; i++) {
        int idx = tid + i * 256;
        int m = idx >> 6, d = idx & 63;
        Zt[d][m] = Z[(size_t)(pm0 + m) * 64 + d];
    }
    __syncthreads();

    // per-row ||z||^2, sequential, no FMA (match sum(flat*flat, axis=1))
    if (tid < 64) {
        const int m = tid;
        float s = 0.f;
        for (int d = 0; d < 64; d++) {
            float v = Zt[d][m];
            s = __fadd_rn(s, __fmul_rn(v, v));
        }
        znS[m] = s;
    }
    __syncthreads();

    float zm[4];
#pragma unroll
    for (int i = 0; i < 4; i++) zm[i] = znS[ty * 4 + i];

    float minv[4]; int mini[4];
#pragma unroll
    for (int i = 0; i < 4; i++) { minv[i] = 3.4e38f; mini[i] = 0; }

    for (int c0 = 0; c0 < KCODE; c0 += 64) {
        __syncthreads();
#pragma unroll
        for (int i = 0; i < 16; i++) {
            int idx = tid + i * 256;
            int c = idx >> 6, d = idx & 63;
            Cs[d][c] = CB[(size_t)(c0 + c) * 64 + d];
        }
        __syncthreads();

        float dot[4][4];
#pragma unroll
        for (int i = 0; i < 4; i++)
#pragma unroll
            for (int j = 0; j < 4; j++) dot[i][j] = 0.f;
#pragma unroll
        for (int kk = 0; kk < 64; kk++) {
            float a[4], b[4];
#pragma unroll
            for (int i = 0; i < 4; i++) a[i] = Zt[kk][ty * 4 + i];
#pragma unroll
            for (int j = 0; j < 4; j++) b[j] = Cs[kk][tx * 4 + j];
#pragma unroll
            for (int i = 0; i < 4; i++)
#pragma unroll
                for (int j = 0; j < 4; j++)
                    dot[i][j] = fmaf(a[i], b[j], dot[i][j]);
        }
#pragma unroll
        for (int j = 0; j < 4; j++) {
            const int c = c0 + tx * 4 + j;
            const float cn = CN[c];
#pragma unroll
            for (int i = 0; i < 4; i++) {
                // reference op order: (zn - 2*dot) + cn  (quantized near ~64)
                float t    = __fadd_rn(zm[i], -__fmul_rn(2.f, dot[i][j]));
                float dist = __fadd_rn(t, cn);
                if (dist < minv[i]) { minv[i] = dist; mini[i] = c; }
            }
        }
    }
    __syncthreads();

    // cross-thread argmin reduce (deterministic, tie -> smallest index)
    float* redv = &Cs[0][0];                       // 64*16 floats
    int*   redi = reinterpret_cast<int*>(&Cs[0][0]) + 1024;
#pragma unroll
    for (int i = 0; i < 4; i++) {
        const int m = ty * 4 + i;
        redv[m * 16 + tx] = minv[i];
        redi[m * 16 + tx] = mini[i];
    }
    __syncthreads();
    if (tid < 64) {
        const int m = tid;
        float bv = redv[m * 16];
        int   bi = redi[m * 16];
        for (int t = 1; t < 16; t++) {
            float v = redv[m * 16 + t];
            int  ix = redi[m * 16 + t];
            if (v < bv || (v == bv && ix < bi)) { bv = v; bi = ix; }
        }
        Codes[pm0 + m] = bi;
        cvals[m] = bv;   // dist already includes ||z||^2
    }
    __syncthreads();
    if (tid == 0) {
        float s = 0.f;
        for (int m = 0; m < 64; m++) s += cvals[m];
        CommitPart[blockIdx.x] = s;
    }
}

// ---------------- gather z_q --------------------------------------------------
__global__ void gather_zq(const int* __restrict__ codes,
                          const float* __restrict__ CB,
                          float* __restrict__ zq)
{
    int idx = blockIdx.x * blockDim.x + threadIdx.x;  // NPOS*16 float4s
    int n = idx >> 4;
    int j = idx & 15;
    reinterpret_cast<float4*>(zq)[n * 16 + j] =
        reinterpret_cast<const float4*>(CB)[codes[n] * 16 + j];
}

// ---------------- LayerNorm over E=128 (in-place, warp per row, two-pass) ----
__global__ void ln128_kernel(float* __restrict__ X,
                             const float* __restrict__ G,
                             const float* __restrict__ B)
{
    const int w = threadIdx.x >> 5, lane = threadIdx.x & 31;
    const int p = blockIdx.x * 8 + w;
    float v[4];
#pragma unroll
    for (int i = 0; i < 4; i++) v[i] = X[(size_t)p * 128 + lane + 32 * i];
    float s = 0.f;
#pragma unroll
    for (int i = 0; i < 4; i++) s += v[i];
#pragma unroll
    for (int off = 16; off > 0; off >>= 1)
        s += __shfl_xor_sync(0xffffffffu, s, off);
    float mu = s * (1.f / 128.f);
    float d[4];
    float sq = 0.f;
#pragma unroll
    for (int i = 0; i < 4; i++) {
        d[i] = v[i] - mu;
        sq = __fadd_rn(sq, __fmul_rn(d[i], d[i]));
    }
#pragma unroll
    for (int off = 16; off > 0; off >>= 1)
        sq += __shfl_xor_sync(0xffffffffu, sq, off);
    float var = sq * (1.f / 128.f);
    float rs  = rsqrtf(var + LN_EPS);
#pragma unroll
    for (int i = 0; i < 4; i++) {
        const int c = lane + 32 * i;
        X[(size_t)p * 128 + c] = d[i] * rs * G[c] + B[c];
    }
}

// ---------------- tail: loss scalar + codes ----------------------------------
__global__ void commit_final(const float* __restrict__ Part, float* __restrict__ slot)
{
    if (threadIdx.x == 0 && blockIdx.x == 0) {
        float s = 0.f;
        for (int i = 0; i < NPOS / 64; i++) s += Part[i];
        *slot = 0.1f * s / ((float)NPOS * (float)DDIM);
    }
}

__global__ void write_codes(const int* __restrict__ codes, float* __restrict__ out)
{
    int n = blockIdx.x * blockDim.x + threadIdx.x;
    if (n < NPOS) out[n] = (float)codes[n];
}

// ---------------- launch ------------------------------------------------------
extern "C" void kernel_launch(void* const* d_in, const int* in_sizes, int n_in,
                              void* d_out, int out_size)
{
    (void)in_sizes; (void)n_in;
    const int*   x    = (const int*)  d_in[0];
    const float* tok  = (const float*)d_in[1];
    const float* ew1  = (const float*)d_in[2];
    const float* eb1  = (const float*)d_in[3];
    const float* ew2  = (const float*)d_in[4];
    const float* eb2  = (const float*)d_in[5];
    const float* ew3  = (const float*)d_in[6];
    const float* eb3  = (const float*)d_in[7];
    const float* elg  = (const float*)d_in[8];
    const float* elb  = (const float*)d_in[9];
    const float* cb   = (const float*)d_in[10];
    const float* dw1  = (const float*)d_in[11];
    const float* db1  = (const float*)d_in[12];
    const float* dw2  = (const float*)d_in[13];
    const float* db2  = (const float*)d_in[14];
    const float* dw3  = (const float*)d_in[15];
    const float* db3  = (const float*)d_in[16];
    const float* dlg  = (const float*)d_in[17];
    const float* dlb  = (const float*)d_in[18];
    const float* ow   = (const float*)d_in[19];
    const float* ob   = (const float*)d_in[20];
    float* out = (float*)d_out;

    float *emb, *h1, *h2, *z, *zq, *cn, *cp;
    int* codes;
    cudaGetSymbolAddress((void**)&emb,   g_emb);
    cudaGetSymbolAddress((void**)&h1,    g_h1);
    cudaGetSymbolAddress((void**)&h2,    g_h2);
    cudaGetSymbolAddress((void**)&z,     g_z);
    cudaGetSymbolAddress((void**)&zq,    g_zq);
    cudaGetSymbolAddress((void**)&codes, g_codes);
    cudaGetSymbolAddress((void**)&cn,    g_cnorm);
    cudaGetSymbolAddress((void**)&cp,    g_commit);

    // ---- encoder ----
    embed_kernel<<<NPOS * 32 / 256, 256>>>(x, tok, emb);
    conv_gemm<128, 256, 3, true ><<<dim3(NPOS / 64, 4), 256>>>(emb, ew1, eb1, h1);
    conv_gemm<256, 256, 3, true ><<<dim3(NPOS / 64, 4), 256>>>(h1, ew2, eb2, h2);
    enc_head_ln<<<NPOS / 64, 256>>>(h2, ew3, eb3, elg, elb, z);

    // ---- vector quantization ----
    cnorm_kernel<<<1, 512>>>(cb, cn);
    vq_kernel<<<NPOS / 64, 256>>>(z, cb, cn, codes, cp);
    gather_zq<<<NPOS * 16 / 256, 256>>>(codes, cb, zq);

    // ---- decoder ----
    conv_gemm< 64, 256, 1, true ><<<dim3(NPOS / 64, 4), 256>>>(zq, dw1, db1, h1);
    conv_gemm<256, 256, 3, true ><<<dim3(NPOS / 64, 4), 256>>>(h1, dw2, db2, h2);
    conv_gemm<256, 128, 1, true ><<<dim3(NPOS / 64, 2), 256>>>(h2, dw3, db3, emb);
    ln128_kernel<<<NPOS / 8, 256>>>(emb, dlg, dlb);

    // ---- vocab projection -> logits straight into d_out ----
    conv_gemm<128, VOCAB, 1, false><<<dim3(NPOS / 64, VOCAB / 64), 256>>>(emb, ow, ob, out);

    // ---- tail: loss scalar + codes ----
    const long long NV = (long long)NPOS * VOCAB;   // 134217728
    if ((long long)out_size >= NV + 1)
        commit_final<<<1, 32>>>(cp, out + NV);
    if ((long long)out_size >= NV + 1 + NPOS)
        write_codes<<<NPOS / 256, 256>>>(codes, out + NV + 1);
}

// round 4
// speedup vs baseline: 1.4942x; 1.4942x over previous
#include <cuda_runtime.h>
#include <cuda_bf16.h>
#include <cstdint>

// Problem constants
#define NPOS   32768          // B*L = 8*4096
#define LSEQ   4096
#define EDIM   128
#define HDIM   256
#define DDIM   64
#define KCODE  512
#define VOCAB  4096
#define LN_EPS 1e-5f

// ---------------- scratch (static device globals; no allocation) -------------
__device__ float g_emb[NPOS * EDIM];    // embedding / decoder-E reuse
__device__ float g_h1 [NPOS * HDIM];
__device__ float g_h2 [NPOS * HDIM];
__device__ float g_z  [NPOS * DDIM];    // z_e after LN
__device__ float g_zq [NPOS * DDIM];    // quantized
__device__ int   g_codes[NPOS];
__device__ float g_cnorm[KCODE];
__device__ float g_commit[NPOS / 64];   // per-block partial sums (512)
// bf16 split buffers for tensor-core logits GEMM
__device__ __nv_bfloat16 g_ahi[NPOS * EDIM];
__device__ __nv_bfloat16 g_alo[NPOS * EDIM];
__device__ __nv_bfloat16 g_bhi[VOCAB * EDIM];
__device__ __nv_bfloat16 g_blo[VOCAB * EDIM];

__device__ __forceinline__ uint32_t smem_to_u32(const void* smem_ptr) {
    uint32_t addr;
    asm("{ .reg .u64 tmp; cvta.to.shared.u64 tmp, %1; cvt.u32.u64 %0, tmp; }"
        : "=r"(addr) : "l"(smem_ptr));
    return addr;
}

// ---------------- embedding lookup ------------------------------------------
__global__ void embed_kernel(const int* __restrict__ x,
                             const float* __restrict__ tok,
                             float* __restrict__ emb)
{
    int idx = blockIdx.x * blockDim.x + threadIdx.x;   // NPOS*32 float4s
    int n = idx >> 5;
    int j = idx & 31;
    int t = x[n];
    reinterpret_cast<float4*>(emb)[n * 32 + j] =
        reinterpret_cast<const float4*>(tok)[t * 32 + j];
}

// ---------------- generic implicit-im2col SGEMM conv -------------------------
template<int CIN, int COUT, int KW, bool RELU>
__global__ void __launch_bounds__(256)
conv_gemm(const float* __restrict__ X, const float* __restrict__ W,
          const float* __restrict__ Bias, float* __restrict__ Y)
{
    constexpr int R   = CIN * KW;
    constexpr int PAD = (KW == 3) ? 1 : 0;
    __shared__ float As[32][66];
    __shared__ float Bs[32][66];

    const int pm0 = blockIdx.x * 64;
    const int on0 = blockIdx.y * 64;
    const int tid = threadIdx.x;
    const int tx = tid & 15, ty = tid >> 4;
    const int rr = tid & 31;
    const int mrow = tid >> 5;

    float acc[4][4];
#pragma unroll
    for (int i = 0; i < 4; i++)
#pragma unroll
        for (int j = 0; j < 4; j++) acc[i][j] = 0.f;

    for (int r0 = 0; r0 < R; r0 += 32) {
        const int r  = r0 + rr;
        const int k  = r / CIN;
        const int ci = r - k * CIN;
#pragma unroll
        for (int i = 0; i < 8; i++) {
            const int m = mrow + i * 8;
            const int p = pm0 + m;
            float v = 0.f;
            if (PAD == 0) {
                v = X[(size_t)p * CIN + ci];
            } else {
                const int l  = p & (LSEQ - 1);
                const int ls = l + k - PAD;
                if ((unsigned)ls < (unsigned)LSEQ)
                    v = X[(size_t)(p + k - PAD) * CIN + ci];
            }
            As[rr][m] = v;
        }
#pragma unroll
        for (int i = 0; i < 8; i++) {
            const int n = mrow + i * 8;
            Bs[rr][n] = W[(size_t)(on0 + n) * R + ci * KW + k];
        }
        __syncthreads();
#pragma unroll
        for (int kk = 0; kk < 32; kk++) {
            float a[4], b[4];
#pragma unroll
            for (int i = 0; i < 4; i++) a[i] = As[kk][ty * 4 + i];
#pragma unroll
            for (int j = 0; j < 4; j++) b[j] = Bs[kk][tx * 4 + j];
#pragma unroll
            for (int i = 0; i < 4; i++)
#pragma unroll
                for (int j = 0; j < 4; j++)
                    acc[i][j] = fmaf(a[i], b[j], acc[i][j]);
        }
        __syncthreads();
    }
#pragma unroll
    for (int i = 0; i < 4; i++) {
        const int p = pm0 + ty * 4 + i;
#pragma unroll
        for (int j = 0; j < 4; j++) {
            const int o = on0 + tx * 4 + j;
            float v = acc[i][j] + Bias[o];
            if (RELU) v = fmaxf(v, 0.f);
            Y[(size_t)p * COUT + o] = v;
        }
    }
}

// ---------------- encoder head: conv1x1 (256->64) + LayerNorm(D=64) ---------
__global__ void __launch_bounds__(256)
enc_head_ln(const float* __restrict__ X, const float* __restrict__ W,
            const float* __restrict__ Bias,
            const float* __restrict__ G, const float* __restrict__ Bt,
            float* __restrict__ Z)
{
    constexpr int CIN = 256;
    __shared__ float As[32][66];
    __shared__ float Bs[32][66];
    __shared__ float Zs[64][66];

    const int pm0 = blockIdx.x * 64;
    const int tid = threadIdx.x;
    const int tx = tid & 15, ty = tid >> 4;
    const int rr = tid & 31;
    const int mrow = tid >> 5;

    float acc[4][4];
#pragma unroll
    for (int i = 0; i < 4; i++)
#pragma unroll
        for (int j = 0; j < 4; j++) acc[i][j] = 0.f;

    for (int r0 = 0; r0 < CIN; r0 += 32) {
        const int ci = r0 + rr;
#pragma unroll
        for (int i = 0; i < 8; i++) {
            const int m = mrow + i * 8;
            As[rr][m] = X[(size_t)(pm0 + m) * CIN + ci];
        }
#pragma unroll
        for (int i = 0; i < 8; i++) {
            const int n = mrow + i * 8;
            Bs[rr][n] = W[(size_t)n * CIN + ci];
        }
        __syncthreads();
#pragma unroll
        for (int kk = 0; kk < 32; kk++) {
            float a[4], b[4];
#pragma unroll
            for (int i = 0; i < 4; i++) a[i] = As[kk][ty * 4 + i];
#pragma unroll
            for (int j = 0; j < 4; j++) b[j] = Bs[kk][tx * 4 + j];
#pragma unroll
            for (int i = 0; i < 4; i++)
#pragma unroll
                for (int j = 0; j < 4; j++)
                    acc[i][j] = fmaf(a[i], b[j], acc[i][j]);
        }
        __syncthreads();
    }
#pragma unroll
    for (int i = 0; i < 4; i++)
#pragma unroll
        for (int j = 0; j < 4; j++)
            Zs[ty * 4 + i][tx * 4 + j] = acc[i][j] + Bias[tx * 4 + j];
    __syncthreads();

    const int lane = tid & 31, w = tid >> 5;
#pragma unroll
    for (int q = 0; q < 8; q++) {
        const int m = w * 8 + q;
        float v0 = Zs[m][lane];
        float v1 = Zs[m][lane + 32];
        float s = v0 + v1;
#pragma unroll
        for (int off = 16; off > 0; off >>= 1)
            s += __shfl_xor_sync(0xffffffffu, s, off);
        float mu = s * (1.f / 64.f);
        float d0 = v0 - mu, d1 = v1 - mu;
        float sq = __fadd_rn(__fmul_rn(d0, d0), __fmul_rn(d1, d1));
#pragma unroll
        for (int off = 16; off > 0; off >>= 1)
            sq += __shfl_xor_sync(0xffffffffu, sq, off);
        float var = sq * (1.f / 64.f);
        float rs  = rsqrtf(var + LN_EPS);
        const int p = pm0 + m;
        Z[(size_t)p * 64 + lane]      = d0 * rs * G[lane]      + Bt[lane];
        Z[(size_t)p * 64 + lane + 32] = d1 * rs * G[lane + 32] + Bt[lane + 32];
    }
}

// ---------------- codebook norms (no FMA: match sum(c*c)) --------------------
__global__ void cnorm_kernel(const float* __restrict__ CB, float* __restrict__ CN)
{
    int c = blockIdx.x * blockDim.x + threadIdx.x;
    if (c < KCODE) {
        float s = 0.f;
        for (int d = 0; d < DDIM; d++) {
            float v = CB[c * DDIM + d];
            s = __fadd_rn(s, __fmul_rn(v, v));
        }
        CN[c] = s;
    }
}

// ---------------- VQ: argmin over codes + commit-loss partials ---------------
__global__ void __launch_bounds__(256)
vq_kernel(const float* __restrict__ Z, const float* __restrict__ CB,
          const float* __restrict__ CN, int* __restrict__ Codes,
          float* __restrict__ CommitPart)
{
    __shared__ float Zt[64][66];
    __shared__ float Cs[64][66];
    __shared__ float znS[64];
    __shared__ float cvals[64];

    const int pm0 = blockIdx.x * 64;
    const int tid = threadIdx.x;
    const int tx = tid & 15, ty = tid >> 4;

#pragma unroll
    for (int i = 0; i < 16; i++) {
        int idx = tid + i * 256;
        int m = idx >> 6, d = idx & 63;
        Zt[d][m] = Z[(size_t)(pm0 + m) * 64 + d];
    }
    __syncthreads();

    if (tid < 64) {
        const int m = tid;
        float s = 0.f;
        for (int d = 0; d < 64; d++) {
            float v = Zt[d][m];
            s = __fadd_rn(s, __fmul_rn(v, v));
        }
        znS[m] = s;
    }
    __syncthreads();

    float zm[4];
#pragma unroll
    for (int i = 0; i < 4; i++) zm[i] = znS[ty * 4 + i];

    float minv[4]; int mini[4];
#pragma unroll
    for (int i = 0; i < 4; i++) { minv[i] = 3.4e38f; mini[i] = 0; }

    for (int c0 = 0; c0 < KCODE; c0 += 64) {
        __syncthreads();
#pragma unroll
        for (int i = 0; i < 16; i++) {
            int idx = tid + i * 256;
            int c = idx >> 6, d = idx & 63;
            Cs[d][c] = CB[(size_t)(c0 + c) * 64 + d];
        }
        __syncthreads();

        float dot[4][4];
#pragma unroll
        for (int i = 0; i < 4; i++)
#pragma unroll
            for (int j = 0; j < 4; j++) dot[i][j] = 0.f;
#pragma unroll
        for (int kk = 0; kk < 64; kk++) {
            float a[4], b[4];
#pragma unroll
            for (int i = 0; i < 4; i++) a[i] = Zt[kk][ty * 4 + i];
#pragma unroll
            for (int j = 0; j < 4; j++) b[j] = Cs[kk][tx * 4 + j];
#pragma unroll
            for (int i = 0; i < 4; i++)
#pragma unroll
                for (int j = 0; j < 4; j++)
                    dot[i][j] = fmaf(a[i], b[j], dot[i][j]);
        }
#pragma unroll
        for (int j = 0; j < 4; j++) {
            const int c = c0 + tx * 4 + j;
            const float cn = CN[c];
#pragma unroll
            for (int i = 0; i < 4; i++) {
                float t    = __fadd_rn(zm[i], -__fmul_rn(2.f, dot[i][j]));
                float dist = __fadd_rn(t, cn);
                if (dist < minv[i]) { minv[i] = dist; mini[i] = c; }
            }
        }
    }
    __syncthreads();

    float* redv = &Cs[0][0];
    int*   redi = reinterpret_cast<int*>(&Cs[0][0]) + 1024;
#pragma unroll
    for (int i = 0; i < 4; i++) {
        const int m = ty * 4 + i;
        redv[m * 16 + tx] = minv[i];
        redi[m * 16 + tx] = mini[i];
    }
    __syncthreads();
    if (tid < 64) {
        const int m = tid;
        float bv = redv[m * 16];
        int   bi = redi[m * 16];
        for (int t = 1; t < 16; t++) {
            float v = redv[m * 16 + t];
            int  ix = redi[m * 16 + t];
            if (v < bv || (v == bv && ix < bi)) { bv = v; bi = ix; }
        }
        Codes[pm0 + m] = bi;
        cvals[m] = bv;
    }
    __syncthreads();
    if (tid == 0) {
        float s = 0.f;
        for (int m = 0; m < 64; m++) s += cvals[m];
        CommitPart[blockIdx.x] = s;
    }
}

// ---------------- gather z_q --------------------------------------------------
__global__ void gather_zq(const int* __restrict__ codes,
                          const float* __restrict__ CB,
                          float* __restrict__ zq)
{
    int idx = blockIdx.x * blockDim.x + threadIdx.x;
    int n = idx >> 4;
    int j = idx & 15;
    reinterpret_cast<float4*>(zq)[n * 16 + j] =
        reinterpret_cast<const float4*>(CB)[codes[n] * 16 + j];
}

// ---------------- LayerNorm over E=128 (in-place, warp per row, two-pass) ----
__global__ void ln128_kernel(float* __restrict__ X,
                             const float* __restrict__ G,
                             const float* __restrict__ B)
{
    const int w = threadIdx.x >> 5, lane = threadIdx.x & 31;
    const int p = blockIdx.x * 8 + w;
    float v[4];
#pragma unroll
    for (int i = 0; i < 4; i++) v[i] = X[(size_t)p * 128 + lane + 32 * i];
    float s = 0.f;
#pragma unroll
    for (int i = 0; i < 4; i++) s += v[i];
#pragma unroll
    for (int off = 16; off > 0; off >>= 1)
        s += __shfl_xor_sync(0xffffffffu, s, off);
    float mu = s * (1.f / 128.f);
    float d[4];
    float sq = 0.f;
#pragma unroll
    for (int i = 0; i < 4; i++) {
        d[i] = v[i] - mu;
        sq = __fadd_rn(sq, __fmul_rn(d[i], d[i]));
    }
#pragma unroll
    for (int off = 16; off > 0; off >>= 1)
        sq += __shfl_xor_sync(0xffffffffu, sq, off);
    float var = sq * (1.f / 128.f);
    float rs  = rsqrtf(var + LN_EPS);
#pragma unroll
    for (int i = 0; i < 4; i++) {
        const int c = lane + 32 * i;
        X[(size_t)p * 128 + c] = d[i] * rs * G[c] + B[c];
    }
}

// ---------------- bf16 hi/lo split -------------------------------------------
__global__ void split_bf16(const float* __restrict__ X,
                           __nv_bfloat16* __restrict__ Hi,
                           __nv_bfloat16* __restrict__ Lo)
{
    int i = blockIdx.x * blockDim.x + threadIdx.x;   // one float each
    float x = X[i];
    __nv_bfloat16 h = __float2bfloat16(x);
    float r = x - __bfloat162float(h);
    Hi[i] = h;
    Lo[i] = __float2bfloat16(r);
}

// ---------------- mma.sync bf16x3 logits GEMM --------------------------------
// C[128 pos x 128 vocab] per CTA = Ahi*Bhi + Ahi*Blo + Alo*Bhi (fp32 accum).
// A: [NPOS,128] bf16 K-major; B: [VOCAB,128] bf16 K-major.
// Smem tiles: 128 rows x 256B (16 chunks of 16B), chunk-xor swizzle for ldmatrix.

#define LG_SMEM (4 * 32768)

__device__ __forceinline__ void ldsm_x4(uint32_t* r, uint32_t addr) {
    asm volatile("ldmatrix.sync.aligned.m8n8.x4.shared.b16 {%0,%1,%2,%3}, [%4];"
                 : "=r"(r[0]), "=r"(r[1]), "=r"(r[2]), "=r"(r[3]) : "r"(addr));
}
__device__ __forceinline__ void mma16816(float* d, const uint32_t* a,
                                         uint32_t b0, uint32_t b1) {
    asm volatile(
        "mma.sync.aligned.m16n8k16.row.col.f32.bf16.bf16.f32 "
        "{%0,%1,%2,%3}, {%4,%5,%6,%7}, {%8,%9}, {%0,%1,%2,%3};"
        : "+f"(d[0]), "+f"(d[1]), "+f"(d[2]), "+f"(d[3])
        : "r"(a[0]), "r"(a[1]), "r"(a[2]), "r"(a[3]), "r"(b0), "r"(b1));
}

__global__ void __launch_bounds__(256, 1)
logits_hmma(const __nv_bfloat16* __restrict__ Ahi, const __nv_bfloat16* __restrict__ Alo,
            const __nv_bfloat16* __restrict__ Bhi, const __nv_bfloat16* __restrict__ Blo,
            const float* __restrict__ Bias, float* __restrict__ Out)
{
    extern __shared__ char smem[];
    char* sAhi = smem;
    char* sAlo = smem + 32768;
    char* sBhi = smem + 65536;
    char* sBlo = smem + 98304;

    const int tid = threadIdx.x;
    const int pm0 = blockIdx.x * 128;
    const int nv0 = blockIdx.y * 128;

    // ---- load 4 tiles (global -> swizzled smem) ----
    {
        const uint4* srcs[4] = {
            reinterpret_cast<const uint4*>(Ahi), reinterpret_cast<const uint4*>(Alo),
            reinterpret_cast<const uint4*>(Bhi), reinterpret_cast<const uint4*>(Blo) };
        char* dsts[4] = { sAhi, sAlo, sBhi, sBlo };
        const int r0s[4] = { pm0, pm0, nv0, nv0 };
#pragma unroll
        for (int t4 = 0; t4 < 4; t4++) {
            const uint4* s4 = srcs[t4];
            char* dst = dsts[t4];
            const int row0 = r0s[t4];
#pragma unroll
            for (int i = 0; i < 8; i++) {
                int idx = tid + i * 256;         // 0..2047
                int row = idx >> 4;
                int c   = idx & 15;
                uint4 v = s4[(size_t)(row0 + row) * 16 + c];
                int pc = (c & 8) | ((c ^ row) & 7);
                *reinterpret_cast<uint4*>(dst + row * 256 + pc * 16) = v;
            }
        }
    }
    __syncthreads();

    const int wid = tid >> 5, lane = tid & 31;
    const int wm = (wid >> 1) * 32;     // warp m offset (0,32,64,96)
    const int wn = (wid & 1) * 64;      // warp n offset (0,64)
    const int lr = lane & 7, lq = lane >> 3;

    float acc[2][8][4];
#pragma unroll
    for (int mi = 0; mi < 2; mi++)
#pragma unroll
        for (int ni = 0; ni < 8; ni++)
#pragma unroll
            for (int e = 0; e < 4; e++) acc[mi][ni][e] = 0.f;

    const uint32_t sb = smem_to_u32(smem);
    const uint32_t aOff[3] = { 0u, 0u, 32768u };        // hi, hi, lo
    const uint32_t bOff[3] = { 65536u, 98304u, 65536u };// hi, lo, hi

#pragma unroll
    for (int s = 0; s < 3; s++) {
        const uint32_t aB = sb + aOff[s];
        const uint32_t bB = sb + bOff[s];
#pragma unroll
        for (int k16 = 0; k16 < 8; k16++) {
            const int kc0 = k16 * 2;
            uint32_t a[2][4];
#pragma unroll
            for (int mi = 0; mi < 2; mi++) {
                int row = wm + mi * 16 + lr + (lq & 1) * 8;
                int kc  = kc0 + (lq >> 1);
                int pc  = (kc & 8) | ((kc ^ row) & 7);
                ldsm_x4(a[mi], aB + row * 256 + pc * 16);
            }
            uint32_t b[4][4];
#pragma unroll
            for (int nc = 0; nc < 4; nc++) {
                int row = wn + nc * 16 + lr + (lq >> 1) * 8;
                int kc  = kc0 + (lq & 1);
                int pc  = (kc & 8) | ((kc ^ row) & 7);
                ldsm_x4(b[nc], bB + row * 256 + pc * 16);
            }
#pragma unroll
            for (int mi = 0; mi < 2; mi++)
#pragma unroll
                for (int ni = 0; ni < 8; ni++)
                    mma16816(acc[mi][ni], a[mi],
                             b[ni >> 1][(ni & 1) * 2 + 0],
                             b[ni >> 1][(ni & 1) * 2 + 1]);
        }
    }

    // ---- epilogue: bias + direct global stores ----
    const int gid = lane >> 2, tig = lane & 3;
#pragma unroll
    for (int mi = 0; mi < 2; mi++) {
        const int m0 = pm0 + wm + mi * 16 + gid;
#pragma unroll
        for (int ni = 0; ni < 8; ni++) {
            const int n = nv0 + wn + ni * 8 + tig * 2;
            const float2 bv = *reinterpret_cast<const float2*>(Bias + n);
            float2 v0, v1;
            v0.x = acc[mi][ni][0] + bv.x;  v0.y = acc[mi][ni][1] + bv.y;
            v1.x = acc[mi][ni][2] + bv.x;  v1.y = acc[mi][ni][3] + bv.y;
            *reinterpret_cast<float2*>(Out + (size_t)m0 * VOCAB + n)       = v0;
            *reinterpret_cast<float2*>(Out + (size_t)(m0 + 8) * VOCAB + n) = v1;
        }
    }
}

// ---------------- tail: loss scalar + codes ----------------------------------
__global__ void commit_final(const float* __restrict__ Part, float* __restrict__ slot)
{
    if (threadIdx.x == 0 && blockIdx.x == 0) {
        float s = 0.f;
        for (int i = 0; i < NPOS / 64; i++) s += Part[i];
        *slot = 0.1f * s / ((float)NPOS * (float)DDIM);
    }
}

__global__ void write_codes(const int* __restrict__ codes, float* __restrict__ out)
{
    int n = blockIdx.x * blockDim.x + threadIdx.x;
    if (n < NPOS) out[n] = (float)codes[n];
}

// ---------------- launch ------------------------------------------------------
extern "C" void kernel_launch(void* const* d_in, const int* in_sizes, int n_in,
                              void* d_out, int out_size)
{
    (void)in_sizes; (void)n_in;
    const int*   x    = (const int*)  d_in[0];
    const float* tok  = (const float*)d_in[1];
    const float* ew1  = (const float*)d_in[2];
    const float* eb1  = (const float*)d_in[3];
    const float* ew2  = (const float*)d_in[4];
    const float* eb2  = (const float*)d_in[5];
    const float* ew3  = (const float*)d_in[6];
    const float* eb3  = (const float*)d_in[7];
    const float* elg  = (const float*)d_in[8];
    const float* elb  = (const float*)d_in[9];
    const float* cb   = (const float*)d_in[10];
    const float* dw1  = (const float*)d_in[11];
    const float* db1  = (const float*)d_in[12];
    const float* dw2  = (const float*)d_in[13];
    const float* db2  = (const float*)d_in[14];
    const float* dw3  = (const float*)d_in[15];
    const float* db3  = (const float*)d_in[16];
    const float* dlg  = (const float*)d_in[17];
    const float* dlb  = (const float*)d_in[18];
    const float* ow   = (const float*)d_in[19];
    const float* ob   = (const float*)d_in[20];
    float* out = (float*)d_out;

    float *emb, *h1, *h2, *z, *zq, *cn, *cp;
    int* codes;
    __nv_bfloat16 *ahi, *alo, *bhi, *blo;
    cudaGetSymbolAddress((void**)&emb,   g_emb);
    cudaGetSymbolAddress((void**)&h1,    g_h1);
    cudaGetSymbolAddress((void**)&h2,    g_h2);
    cudaGetSymbolAddress((void**)&z,     g_z);
    cudaGetSymbolAddress((void**)&zq,    g_zq);
    cudaGetSymbolAddress((void**)&codes, g_codes);
    cudaGetSymbolAddress((void**)&cn,    g_cnorm);
    cudaGetSymbolAddress((void**)&cp,    g_commit);
    cudaGetSymbolAddress((void**)&ahi,   g_ahi);
    cudaGetSymbolAddress((void**)&alo,   g_alo);
    cudaGetSymbolAddress((void**)&bhi,   g_bhi);
    cudaGetSymbolAddress((void**)&blo,   g_blo);

    cudaFuncSetAttribute(logits_hmma, cudaFuncAttributeMaxDynamicSharedMemorySize, LG_SMEM);

    // ---- encoder ----
    embed_kernel<<<NPOS * 32 / 256, 256>>>(x, tok, emb);
    conv_gemm<128, 256, 3, true ><<<dim3(NPOS / 64, 4), 256>>>(emb, ew1, eb1, h1);
    conv_gemm<256, 256, 3, true ><<<dim3(NPOS / 64, 4), 256>>>(h1, ew2, eb2, h2);
    enc_head_ln<<<NPOS / 64, 256>>>(h2, ew3, eb3, elg, elb, z);

    // ---- vector quantization ----
    cnorm_kernel<<<1, 512>>>(cb, cn);
    vq_kernel<<<NPOS / 64, 256>>>(z, cb, cn, codes, cp);
    gather_zq<<<NPOS * 16 / 256, 256>>>(codes, cb, zq);

    // ---- decoder ----
    conv_gemm< 64, 256, 1, true ><<<dim3(NPOS / 64, 4), 256>>>(zq, dw1, db1, h1);
    conv_gemm<256, 256, 3, true ><<<dim3(NPOS / 64, 4), 256>>>(h1, dw2, db2, h2);
    conv_gemm<256, 128, 1, true ><<<dim3(NPOS / 64, 2), 256>>>(h2, dw3, db3, emb);
    ln128_kernel<<<NPOS / 8, 256>>>(emb, dlg, dlb);

    // ---- bf16 hi/lo splits for tensor-core logits GEMM ----
    split_bf16<<<NPOS * EDIM / 256, 256>>>(emb, ahi, alo);
    split_bf16<<<VOCAB * EDIM / 256, 256>>>(ow, bhi, blo);

    // ---- vocab projection via mma.sync bf16x3 -> d_out ----
    logits_hmma<<<dim3(NPOS / 128, VOCAB / 128), 256, LG_SMEM>>>(ahi, alo, bhi, blo, ob, out);

    // ---- tail: loss scalar + codes ----
    const long long NV = (long long)NPOS * VOCAB;   // 134217728
    if ((long long)out_size >= NV + 1)
        commit_final<<<1, 32>>>(cp, out + NV);
    if ((long long)out_size >= NV + 1 + NPOS)
        write_codes<<<NPOS / 256, 256>>>(codes, out + NV + 1);
}

// round 5
// speedup vs baseline: 1.7900x; 1.1980x over previous
#include <cuda_runtime.h>
#include <cuda_bf16.h>
#include <cstdint>

// Problem constants
#define NPOS   32768          // B*L = 8*4096
#define LSEQ   4096
#define EDIM   128
#define HDIM   256
#define DDIM   64
#define KCODE  512
#define VOCAB  4096
#define LN_EPS 1e-5f

typedef __nv_bfloat16 bf16;

// ---------------- scratch (static device globals; no allocation) -------------
__device__ float g_emb[NPOS * EDIM];    // embedding / decoder-E reuse
__device__ float g_h1 [NPOS * HDIM];    // encoder fp32 activations
__device__ float g_h2 [NPOS * HDIM];
__device__ float g_z  [NPOS * DDIM];    // z_e after LN
__device__ int   g_codes[NPOS];
__device__ float g_cnorm[KCODE];
__device__ float g_commit[NPOS / 64];
// bf16 split activations (decoder path)
__device__ __align__(16) bf16 g_zqhi[NPOS * DDIM];
__device__ __align__(16) bf16 g_zqlo[NPOS * DDIM];
__device__ __align__(16) bf16 g_d1hi[NPOS * HDIM];
__device__ __align__(16) bf16 g_d1lo[NPOS * HDIM];
__device__ __align__(16) bf16 g_d2hi[NPOS * HDIM];
__device__ __align__(16) bf16 g_d2lo[NPOS * HDIM];
__device__ __align__(16) bf16 g_ahi[NPOS * EDIM];
__device__ __align__(16) bf16 g_alo[NPOS * EDIM];
// bf16 split packed weights
__device__ __align__(16) bf16 g_w1hi[HDIM * DDIM];
__device__ __align__(16) bf16 g_w1lo[HDIM * DDIM];
__device__ __align__(16) bf16 g_w2hi[HDIM * HDIM * 3];
__device__ __align__(16) bf16 g_w2lo[HDIM * HDIM * 3];
__device__ __align__(16) bf16 g_w3hi[EDIM * HDIM];
__device__ __align__(16) bf16 g_w3lo[EDIM * HDIM];
__device__ __align__(16) bf16 g_bhi[VOCAB * EDIM];
__device__ __align__(16) bf16 g_blo[VOCAB * EDIM];

__device__ __forceinline__ uint32_t smem_to_u32(const void* smem_ptr) {
    uint32_t addr;
    asm("{ .reg .u64 tmp; cvta.to.shared.u64 tmp, %1; cvt.u32.u64 %0, tmp; }"
        : "=r"(addr) : "l"(smem_ptr));
    return addr;
}

// ---------------- embedding lookup ------------------------------------------
__global__ void embed_kernel(const int* __restrict__ x,
                             const float* __restrict__ tok,
                             float* __restrict__ emb)
{
    int idx = blockIdx.x * blockDim.x + threadIdx.x;
    int n = idx >> 5;
    int j = idx & 31;
    int t = x[n];
    reinterpret_cast<float4*>(emb)[n * 32 + j] =
        reinterpret_cast<const float4*>(tok)[t * 32 + j];
}

// ---------------- generic implicit-im2col SGEMM conv (encoder, fp32) ---------
template<int CIN, int COUT, int KW, bool RELU>
__global__ void __launch_bounds__(256)
conv_gemm(const float* __restrict__ X, const float* __restrict__ W,
          const float* __restrict__ Bias, float* __restrict__ Y)
{
    constexpr int R   = CIN * KW;
    constexpr int PAD = (KW == 3) ? 1 : 0;
    __shared__ float As[32][66];
    __shared__ float Bs[32][66];

    const int pm0 = blockIdx.x * 64;
    const int on0 = blockIdx.y * 64;
    const int tid = threadIdx.x;
    const int tx = tid & 15, ty = tid >> 4;
    const int rr = tid & 31;
    const int mrow = tid >> 5;

    float acc[4][4];
#pragma unroll
    for (int i = 0; i < 4; i++)
#pragma unroll
        for (int j = 0; j < 4; j++) acc[i][j] = 0.f;

    for (int r0 = 0; r0 < R; r0 += 32) {
        const int r  = r0 + rr;
        const int k  = r / CIN;
        const int ci = r - k * CIN;
#pragma unroll
        for (int i = 0; i < 8; i++) {
            const int m = mrow + i * 8;
            const int p = pm0 + m;
            float v = 0.f;
            if (PAD == 0) {
                v = X[(size_t)p * CIN + ci];
            } else {
                const int l  = p & (LSEQ - 1);
                const int ls = l + k - PAD;
                if ((unsigned)ls < (unsigned)LSEQ)
                    v = X[(size_t)(p + k - PAD) * CIN + ci];
            }
            As[rr][m] = v;
        }
#pragma unroll
        for (int i = 0; i < 8; i++) {
            const int n = mrow + i * 8;
            Bs[rr][n] = W[(size_t)(on0 + n) * R + ci * KW + k];
        }
        __syncthreads();
#pragma unroll
        for (int kk = 0; kk < 32; kk++) {
            float a[4], b[4];
#pragma unroll
            for (int i = 0; i < 4; i++) a[i] = As[kk][ty * 4 + i];
#pragma unroll
            for (int j = 0; j < 4; j++) b[j] = Bs[kk][tx * 4 + j];
#pragma unroll
            for (int i = 0; i < 4; i++)
#pragma unroll
                for (int j = 0; j < 4; j++)
                    acc[i][j] = fmaf(a[i], b[j], acc[i][j]);
        }
        __syncthreads();
    }
#pragma unroll
    for (int i = 0; i < 4; i++) {
        const int p = pm0 + ty * 4 + i;
#pragma unroll
        for (int j = 0; j < 4; j++) {
            const int o = on0 + tx * 4 + j;
            float v = acc[i][j] + Bias[o];
            if (RELU) v = fmaxf(v, 0.f);
            Y[(size_t)p * COUT + o] = v;
        }
    }
}

// ---------------- encoder head: conv1x1 (256->64) + LayerNorm(D=64) ---------
__global__ void __launch_bounds__(256)
enc_head_ln(const float* __restrict__ X, const float* __restrict__ W,
            const float* __restrict__ Bias,
            const float* __restrict__ G, const float* __restrict__ Bt,
            float* __restrict__ Z)
{
    constexpr int CIN = 256;
    __shared__ float As[32][66];
    __shared__ float Bs[32][66];
    __shared__ float Zs[64][66];

    const int pm0 = blockIdx.x * 64;
    const int tid = threadIdx.x;
    const int tx = tid & 15, ty = tid >> 4;
    const int rr = tid & 31;
    const int mrow = tid >> 5;

    float acc[4][4];
#pragma unroll
    for (int i = 0; i < 4; i++)
#pragma unroll
        for (int j = 0; j < 4; j++) acc[i][j] = 0.f;

    for (int r0 = 0; r0 < CIN; r0 += 32) {
        const int ci = r0 + rr;
#pragma unroll
        for (int i = 0; i < 8; i++) {
            const int m = mrow + i * 8;
            As[rr][m] = X[(size_t)(pm0 + m) * CIN + ci];
        }
#pragma unroll
        for (int i = 0; i < 8; i++) {
            const int n = mrow + i * 8;
            Bs[rr][n] = W[(size_t)n * CIN + ci];
        }
        __syncthreads();
#pragma unroll
        for (int kk = 0; kk < 32; kk++) {
            float a[4], b[4];
#pragma unroll
            for (int i = 0; i < 4; i++) a[i] = As[kk][ty * 4 + i];
#pragma unroll
            for (int j = 0; j < 4; j++) b[j] = Bs[kk][tx * 4 + j];
#pragma unroll
            for (int i = 0; i < 4; i++)
#pragma unroll
                for (int j = 0; j < 4; j++)
                    acc[i][j] = fmaf(a[i], b[j], acc[i][j]);
        }
        __syncthreads();
    }
#pragma unroll
    for (int i = 0; i < 4; i++)
#pragma unroll
        for (int j = 0; j < 4; j++)
            Zs[ty * 4 + i][tx * 4 + j] = acc[i][j] + Bias[tx * 4 + j];
    __syncthreads();

    const int lane = tid & 31, w = tid >> 5;
#pragma unroll
    for (int q = 0; q < 8; q++) {
        const int m = w * 8 + q;
        float v0 = Zs[m][lane];
        float v1 = Zs[m][lane + 32];
        float s = v0 + v1;
#pragma unroll
        for (int off = 16; off > 0; off >>= 1)
            s += __shfl_xor_sync(0xffffffffu, s, off);
        float mu = s * (1.f / 64.f);
        float d0 = v0 - mu, d1 = v1 - mu;
        float sq = __fadd_rn(__fmul_rn(d0, d0), __fmul_rn(d1, d1));
#pragma unroll
        for (int off = 16; off > 0; off >>= 1)
            sq += __shfl_xor_sync(0xffffffffu, sq, off);
        float var = sq * (1.f / 64.f);
        float rs  = rsqrtf(var + LN_EPS);
        const int p = pm0 + m;
        Z[(size_t)p * 64 + lane]      = d0 * rs * G[lane]      + Bt[lane];
        Z[(size_t)p * 64 + lane + 32] = d1 * rs * G[lane + 32] + Bt[lane + 32];
    }
}

// ---------------- codebook norms (no FMA: match sum(c*c)) --------------------
__global__ void cnorm_kernel(const float* __restrict__ CB, float* __restrict__ CN)
{
    int c = blockIdx.x * blockDim.x + threadIdx.x;
    if (c < KCODE) {
        float s = 0.f;
        for (int d = 0; d < DDIM; d++) {
            float v = CB[c * DDIM + d];
            s = __fadd_rn(s, __fmul_rn(v, v));
        }
        CN[c] = s;
    }
}

// ---------------- VQ: argmin over codes + commit-loss partials ---------------
__global__ void __launch_bounds__(256)
vq_kernel(const float* __restrict__ Z, const float* __restrict__ CB,
          const float* __restrict__ CN, int* __restrict__ Codes,
          float* __restrict__ CommitPart)
{
    __shared__ float Zt[64][66];
    __shared__ float Cs[64][66];
    __shared__ float znS[64];
    __shared__ float cvals[64];

    const int pm0 = blockIdx.x * 64;
    const int tid = threadIdx.x;
    const int tx = tid & 15, ty = tid >> 4;

#pragma unroll
    for (int i = 0; i < 16; i++) {
        int idx = tid + i * 256;
        int m = idx >> 6, d = idx & 63;
        Zt[d][m] = Z[(size_t)(pm0 + m) * 64 + d];
    }
    __syncthreads();

    if (tid < 64) {
        const int m = tid;
        float s = 0.f;
        for (int d = 0; d < 64; d++) {
            float v = Zt[d][m];
            s = __fadd_rn(s, __fmul_rn(v, v));
        }
        znS[m] = s;
    }
    __syncthreads();

    float zm[4];
#pragma unroll
    for (int i = 0; i < 4; i++) zm[i] = znS[ty * 4 + i];

    float minv[4]; int mini[4];
#pragma unroll
    for (int i = 0; i < 4; i++) { minv[i] = 3.4e38f; mini[i] = 0; }

    for (int c0 = 0; c0 < KCODE; c0 += 64) {
        __syncthreads();
#pragma unroll
        for (int i = 0; i < 16; i++) {
            int idx = tid + i * 256;
            int c = idx >> 6, d = idx & 63;
            Cs[d][c] = CB[(size_t)(c0 + c) * 64 + d];
        }
        __syncthreads();

        float dot[4][4];
#pragma unroll
        for (int i = 0; i < 4; i++)
#pragma unroll
            for (int j = 0; j < 4; j++) dot[i][j] = 0.f;
#pragma unroll
        for (int kk = 0; kk < 64; kk++) {
            float a[4], b[4];
#pragma unroll
            for (int i = 0; i < 4; i++) a[i] = Zt[kk][ty * 4 + i];
#pragma unroll
            for (int j = 0; j < 4; j++) b[j] = Cs[kk][tx * 4 + j];
#pragma unroll
            for (int i = 0; i < 4; i++)
#pragma unroll
                for (int j = 0; j < 4; j++)
                    dot[i][j] = fmaf(a[i], b[j], dot[i][j]);
        }
#pragma unroll
        for (int j = 0; j < 4; j++) {
            const int c = c0 + tx * 4 + j;
            const float cn = CN[c];
#pragma unroll
            for (int i = 0; i < 4; i++) {
                float t    = __fadd_rn(zm[i], -__fmul_rn(2.f, dot[i][j]));
                float dist = __fadd_rn(t, cn);
                if (dist < minv[i]) { minv[i] = dist; mini[i] = c; }
            }
        }
    }
    __syncthreads();

    float* redv = &Cs[0][0];
    int*   redi = reinterpret_cast<int*>(&Cs[0][0]) + 1024;
#pragma unroll
    for (int i = 0; i < 4; i++) {
        const int m = ty * 4 + i;
        redv[m * 16 + tx] = minv[i];
        redi[m * 16 + tx] = mini[i];
    }
    __syncthreads();
    if (tid < 64) {
        const int m = tid;
        float bv = redv[m * 16];
        int   bi = redi[m * 16];
        for (int t = 1; t < 16; t++) {
            float v = redv[m * 16 + t];
            int  ix = redi[m * 16 + t];
            if (v < bv || (v == bv && ix < bi)) { bv = v; bi = ix; }
        }
        Codes[pm0 + m] = bi;
        cvals[m] = bv;
    }
    __syncthreads();
    if (tid == 0) {
        float s = 0.f;
        for (int m = 0; m < 64; m++) s += cvals[m];
        CommitPart[blockIdx.x] = s;
    }
}

// ---------------- gather z_q with fused bf16 hi/lo split ----------------------
__global__ void gather_zq_split(const int* __restrict__ codes,
                                const float* __restrict__ CB,
                                bf16* __restrict__ Hi, bf16* __restrict__ Lo)
{
    int idx = blockIdx.x * blockDim.x + threadIdx.x;   // NPOS*16 float4s
    int n = idx >> 4;
    int j = idx & 15;
    float4 v = reinterpret_cast<const float4*>(CB)[codes[n] * 16 + j];
    bf16 h0 = __float2bfloat16(v.x), h1 = __float2bfloat16(v.y);
    bf16 h2 = __float2bfloat16(v.z), h3 = __float2bfloat16(v.w);
    __nv_bfloat162 hh0; hh0.x = h0; hh0.y = h1;
    __nv_bfloat162 hh1; hh1.x = h2; hh1.y = h3;
    __nv_bfloat162 ll0; ll0.x = __float2bfloat16(v.x - __bfloat162float(h0));
    ll0.y = __float2bfloat16(v.y - __bfloat162float(h1));
    __nv_bfloat162 ll1; ll1.x = __float2bfloat16(v.z - __bfloat162float(h2));
    ll1.y = __float2bfloat16(v.w - __bfloat162float(h3));
    reinterpret_cast<__nv_bfloat162*>(Hi)[n * 32 + j * 2 + 0] = hh0;
    reinterpret_cast<__nv_bfloat162*>(Hi)[n * 32 + j * 2 + 1] = hh1;
    reinterpret_cast<__nv_bfloat162*>(Lo)[n * 32 + j * 2 + 0] = ll0;
    reinterpret_cast<__nv_bfloat162*>(Lo)[n * 32 + j * 2 + 1] = ll1;
}

// ---------------- LayerNorm over E=128 + fused split --------------------------
__global__ void ln128_split(const float* __restrict__ X,
                            const float* __restrict__ G,
                            const float* __restrict__ B,
                            bf16* __restrict__ Hi, bf16* __restrict__ Lo)
{
    const int w = threadIdx.x >> 5, lane = threadIdx.x & 31;
    const int p = blockIdx.x * 8 + w;
    float v[4];
#pragma unroll
    for (int i = 0; i < 4; i++) v[i] = X[(size_t)p * 128 + lane + 32 * i];
    float s = 0.f;
#pragma unroll
    for (int i = 0; i < 4; i++) s += v[i];
#pragma unroll
    for (int off = 16; off > 0; off >>= 1)
        s += __shfl_xor_sync(0xffffffffu, s, off);
    float mu = s * (1.f / 128.f);
    float d[4];
    float sq = 0.f;
#pragma unroll
    for (int i = 0; i < 4; i++) {
        d[i] = v[i] - mu;
        sq = __fadd_rn(sq, __fmul_rn(d[i], d[i]));
    }
#pragma unroll
    for (int off = 16; off > 0; off >>= 1)
        sq += __shfl_xor_sync(0xffffffffu, sq, off);
    float var = sq * (1.f / 128.f);
    float rs  = rsqrtf(var + LN_EPS);
#pragma unroll
    for (int i = 0; i < 4; i++) {
        const int c = lane + 32 * i;
        float y = d[i] * rs * G[c] + B[c];
        bf16 h = __float2bfloat16(y);
        Hi[(size_t)p * 128 + c] = h;
        Lo[(size_t)p * 128 + c] = __float2bfloat16(y - __bfloat162float(h));
    }
}

// ---------------- weight pack + split -----------------------------------------
// W[COUT][CIN][KW] -> Wp[COUT][tap*CIN + ci] in bf16 hi/lo
template<int CIN, int KW, int COUT>
__global__ void pack_split(const float* __restrict__ W,
                           bf16* __restrict__ Hi, bf16* __restrict__ Lo)
{
    int idx = blockIdx.x * blockDim.x + threadIdx.x;
    if (idx >= COUT * KW * CIN) return;
    int o   = idx / (KW * CIN);
    int rem = idx - o * (KW * CIN);
    int tap = rem / CIN;
    int ci  = rem - tap * CIN;
    float w = W[(size_t)o * CIN * KW + ci * KW + tap];
    bf16 h = __float2bfloat16(w);
    Hi[idx] = h;
    Lo[idx] = __float2bfloat16(w - __bfloat162float(h));
}

// ---------------- generic bf16x3 tensor conv/GEMM ----------------------------
// A (im2col source): bf16 hi/lo [NPOS, CIN]; W packed [COUT, KW*CIN] hi/lo.
// Per CTA: 128 pos x 128 out. K streamed in chunks of 64.
#define TC_SMEM 65536

__device__ __forceinline__ void ldsm_x4(uint32_t* r, uint32_t addr) {
    asm volatile("ldmatrix.sync.aligned.m8n8.x4.shared.b16 {%0,%1,%2,%3}, [%4];"
                 : "=r"(r[0]), "=r"(r[1]), "=r"(r[2]), "=r"(r[3]) : "r"(addr));
}
__device__ __forceinline__ void mma16816(float* d, const uint32_t* a,
                                         uint32_t b0, uint32_t b1) {
    asm volatile(
        "mma.sync.aligned.m16n8k16.row.col.f32.bf16.bf16.f32 "
        "{%0,%1,%2,%3}, {%4,%5,%6,%7}, {%8,%9}, {%0,%1,%2,%3};"
        : "+f"(d[0]), "+f"(d[1]), "+f"(d[2]), "+f"(d[3])
        : "r"(a[0]), "r"(a[1]), "r"(a[2]), "r"(a[3]), "r"(b0), "r"(b1));
}

template<int CIN, int KW, int COUT, bool RELU, bool WF32, bool WSPLIT>
__global__ void __launch_bounds__(256)
tconv(const bf16* __restrict__ Ahi, const bf16* __restrict__ Alo,
      const bf16* __restrict__ Whi, const bf16* __restrict__ Wlo,
      const float* __restrict__ Bias,
      float* __restrict__ Yf, bf16* __restrict__ Yhi, bf16* __restrict__ Ylo)
{
    constexpr int KTOT = CIN * KW;
    constexpr int NCH  = KTOT / 64;
    constexpr int PAD  = (KW == 3) ? 1 : 0;

    extern __shared__ char smem[];
    char* sAhi = smem;
    char* sAlo = smem + 16384;
    char* sBhi = smem + 32768;
    char* sBlo = smem + 49152;

    const int tid = threadIdx.x;
    const int pm0 = blockIdx.x * 128;
    const int nv0 = blockIdx.y * 128;

    const int wid = tid >> 5, lane = tid & 31;
    const int wm = (wid >> 1) * 32;
    const int wn = (wid & 1) * 64;
    const int lr = lane & 7, lq = lane >> 3;

    float acc[2][8][4];
#pragma unroll
    for (int mi = 0; mi < 2; mi++)
#pragma unroll
        for (int ni = 0; ni < 8; ni++)
#pragma unroll
            for (int e = 0; e < 4; e++) acc[mi][ni][e] = 0.f;

    const uint4* A4h = reinterpret_cast<const uint4*>(Ahi);
    const uint4* A4l = reinterpret_cast<const uint4*>(Alo);
    const uint4* B4h = reinterpret_cast<const uint4*>(Whi);
    const uint4* B4l = reinterpret_cast<const uint4*>(Wlo);

    const uint32_t sb = smem_to_u32(smem);
    const uint32_t aB3[3] = { sb + 0u, sb + 0u, sb + 16384u };       // hi, hi, lo
    const uint32_t bB3[3] = { sb + 32768u, sb + 49152u, sb + 32768u }; // hi, lo, hi

    for (int ch = 0; ch < NCH; ch++) {
        const int tap = (ch * 64) / CIN;
        const int ci0 = (ch * 64) % CIN;
        // ---- A chunk: 128 rows x 64 cols (row-shifted by tap for KW=3) ----
#pragma unroll
        for (int i = 0; i < 4; i++) {
            int idx = tid + i * 256;            // 0..1023
            int row = idx >> 3, c = idx & 7;
            int p = pm0 + row;
            bool ok = true;
            if (KW == 3) {
                int ls = (p & (LSEQ - 1)) + tap - PAD;
                ok = ((unsigned)ls < (unsigned)LSEQ);
            }
            uint4 zz = make_uint4(0u, 0u, 0u, 0u);
            size_t gi = (size_t)(p + tap - PAD) * (CIN / 8) + (ci0 / 8) + c;
            uint4 vh = ok ? A4h[gi] : zz;
            uint4 vl = ok ? A4l[gi] : zz;
            int pc = (c ^ row) & 7;
            *reinterpret_cast<uint4*>(sAhi + row * 128 + pc * 16) = vh;
            *reinterpret_cast<uint4*>(sAlo + row * 128 + pc * 16) = vl;
        }
        // ---- B chunk: 128 out rows x 64 red cols ----
#pragma unroll
        for (int i = 0; i < 4; i++) {
            int idx = tid + i * 256;
            int row = idx >> 3, c = idx & 7;
            size_t gi = (size_t)(nv0 + row) * (KTOT / 8) + ch * 8 + c;
            uint4 vh = B4h[gi];
            uint4 vl = B4l[gi];
            int pc = (c ^ row) & 7;
            *reinterpret_cast<uint4*>(sBhi + row * 128 + pc * 16) = vh;
            *reinterpret_cast<uint4*>(sBlo + row * 128 + pc * 16) = vl;
        }
        __syncthreads();

#pragma unroll
        for (int s = 0; s < 3; s++) {
            const uint32_t aB = aB3[s];
            const uint32_t bB = bB3[s];
#pragma unroll
            for (int k16 = 0; k16 < 4; k16++) {
                const int kc0 = k16 * 2;
                uint32_t a[2][4];
#pragma unroll
                for (int mi = 0; mi < 2; mi++) {
                    int row = wm + mi * 16 + lr + (lq & 1) * 8;
                    int kc  = kc0 + (lq >> 1);
                    int pc  = (kc ^ row) & 7;
                    ldsm_x4(a[mi], aB + row * 128 + pc * 16);
                }
                uint32_t b[4][4];
#pragma unroll
                for (int nc = 0; nc < 4; nc++) {
                    int row = wn + nc * 16 + lr + (lq >> 1) * 8;
                    int kc  = kc0 + (lq & 1);
                    int pc  = (kc ^ row) & 7;
                    ldsm_x4(b[nc], bB + row * 128 + pc * 16);
                }
#pragma unroll
                for (int mi = 0; mi < 2; mi++)
#pragma unroll
                    for (int ni = 0; ni < 8; ni++)
                        mma16816(acc[mi][ni], a[mi],
                                 b[ni >> 1][(ni & 1) * 2 + 0],
                                 b[ni >> 1][(ni & 1) * 2 + 1]);
            }
        }
        __syncthreads();
    }

    // ---- epilogue: bias (+relu), fp32 and/or bf16-split stores ----
    const int gid = lane >> 2, tig = lane & 3;
#pragma unroll
    for (int mi = 0; mi < 2; mi++) {
        const int m0 = pm0 + wm + mi * 16 + gid;
#pragma unroll
        for (int ni = 0; ni < 8; ni++) {
            const int n = nv0 + wn + ni * 8 + tig * 2;
            const float2 bv = *reinterpret_cast<const float2*>(Bias + n);
            float v00 = acc[mi][ni][0] + bv.x;
            float v01 = acc[mi][ni][1] + bv.y;
            float v10 = acc[mi][ni][2] + bv.x;
            float v11 = acc[mi][ni][3] + bv.y;
            if (RELU) {
                v00 = fmaxf(v00, 0.f); v01 = fmaxf(v01, 0.f);
                v10 = fmaxf(v10, 0.f); v11 = fmaxf(v11, 0.f);
            }
            if (WF32) {
                float2 a0; a0.x = v00; a0.y = v01;
                float2 a1; a1.x = v10; a1.y = v11;
                *reinterpret_cast<float2*>(Yf + (size_t)m0 * COUT + n)       = a0;
                *reinterpret_cast<float2*>(Yf + (size_t)(m0 + 8) * COUT + n) = a1;
            }
            if (WSPLIT) {
                bf16 h00 = __float2bfloat16(v00), h01 = __float2bfloat16(v01);
                bf16 h10 = __float2bfloat16(v10), h11 = __float2bfloat16(v11);
                __nv_bfloat162 hh0; hh0.x = h00; hh0.y = h01;
                __nv_bfloat162 hh1; hh1.x = h10; hh1.y = h11;
                __nv_bfloat162 ll0;
                ll0.x = __float2bfloat16(v00 - __bfloat162float(h00));
                ll0.y = __float2bfloat16(v01 - __bfloat162float(h01));
                __nv_bfloat162 ll1;
                ll1.x = __float2bfloat16(v10 - __bfloat162float(h10));
                ll1.y = __float2bfloat16(v11 - __bfloat162float(h11));
                *reinterpret_cast<__nv_bfloat162*>(Yhi + (size_t)m0 * COUT + n)       = hh0;
                *reinterpret_cast<__nv_bfloat162*>(Yhi + (size_t)(m0 + 8) * COUT + n) = hh1;
                *reinterpret_cast<__nv_bfloat162*>(Ylo + (size_t)m0 * COUT + n)       = ll0;
                *reinterpret_cast<__nv_bfloat162*>(Ylo + (size_t)(m0 + 8) * COUT + n) = ll1;
            }
        }
    }
}

// ---------------- tail: loss scalar + codes ----------------------------------
__global__ void commit_final(const float* __restrict__ Part, float* __restrict__ slot)
{
    if (threadIdx.x == 0 && blockIdx.x == 0) {
        float s = 0.f;
        for (int i = 0; i < NPOS / 64; i++) s += Part[i];
        *slot = 0.1f * s / ((float)NPOS * (float)DDIM);
    }
}

__global__ void write_codes(const int* __restrict__ codes, float* __restrict__ out)
{
    int n = blockIdx.x * blockDim.x + threadIdx.x;
    if (n < NPOS) out[n] = (float)codes[n];
}

// ---------------- launch ------------------------------------------------------
extern "C" void kernel_launch(void* const* d_in, const int* in_sizes, int n_in,
                              void* d_out, int out_size)
{
    (void)in_sizes; (void)n_in;
    const int*   x    = (const int*)  d_in[0];
    const float* tok  = (const float*)d_in[1];
    const float* ew1  = (const float*)d_in[2];
    const float* eb1  = (const float*)d_in[3];
    const float* ew2  = (const float*)d_in[4];
    const float* eb2  = (const float*)d_in[5];
    const float* ew3  = (const float*)d_in[6];
    const float* eb3  = (const float*)d_in[7];
    const float* elg  = (const float*)d_in[8];
    const float* elb  = (const float*)d_in[9];
    const float* cb   = (const float*)d_in[10];
    const float* dw1  = (const float*)d_in[11];
    const float* db1  = (const float*)d_in[12];
    const float* dw2  = (const float*)d_in[13];
    const float* db2  = (const float*)d_in[14];
    const float* dw3  = (const float*)d_in[15];
    const float* db3  = (const float*)d_in[16];
    const float* dlg  = (const float*)d_in[17];
    const float* dlb  = (const float*)d_in[18];
    const float* ow   = (const float*)d_in[19];
    const float* ob   = (const float*)d_in[20];
    float* out = (float*)d_out;

    float *emb, *h1, *h2, *z, *cn, *cp;
    int* codes;
    bf16 *zqhi, *zqlo, *d1hi, *d1lo, *d2hi, *d2lo, *ahi, *alo;
    bf16 *w1hi, *w1lo, *w2hi, *w2lo, *w3hi, *w3lo, *bhi, *blo;
    cudaGetSymbolAddress((void**)&emb,   g_emb);
    cudaGetSymbolAddress((void**)&h1,    g_h1);
    cudaGetSymbolAddress((void**)&h2,    g_h2);
    cudaGetSymbolAddress((void**)&z,     g_z);
    cudaGetSymbolAddress((void**)&codes, g_codes);
    cudaGetSymbolAddress((void**)&cn,    g_cnorm);
    cudaGetSymbolAddress((void**)&cp,    g_commit);
    cudaGetSymbolAddress((void**)&zqhi,  g_zqhi);
    cudaGetSymbolAddress((void**)&zqlo,  g_zqlo);
    cudaGetSymbolAddress((void**)&d1hi,  g_d1hi);
    cudaGetSymbolAddress((void**)&d1lo,  g_d1lo);
    cudaGetSymbolAddress((void**)&d2hi,  g_d2hi);
    cudaGetSymbolAddress((void**)&d2lo,  g_d2lo);
    cudaGetSymbolAddress((void**)&ahi,   g_ahi);
    cudaGetSymbolAddress((void**)&alo,   g_alo);
    cudaGetSymbolAddress((void**)&w1hi,  g_w1hi);
    cudaGetSymbolAddress((void**)&w1lo,  g_w1lo);
    cudaGetSymbolAddress((void**)&w2hi,  g_w2hi);
    cudaGetSymbolAddress((void**)&w2lo,  g_w2lo);
    cudaGetSymbolAddress((void**)&w3hi,  g_w3hi);
    cudaGetSymbolAddress((void**)&w3lo,  g_w3lo);
    cudaGetSymbolAddress((void**)&bhi,   g_bhi);
    cudaGetSymbolAddress((void**)&blo,   g_blo);

    cudaFuncSetAttribute((const void*)tconv< 64, 1, 256, true,  false, true >,
                         cudaFuncAttributeMaxDynamicSharedMemorySize, TC_SMEM);
    cudaFuncSetAttribute((const void*)tconv<256, 3, 256, true,  false, true >,
                         cudaFuncAttributeMaxDynamicSharedMemorySize, TC_SMEM);
    cudaFuncSetAttribute((const void*)tconv<256, 1, 128, true,  true,  false>,
                         cudaFuncAttributeMaxDynamicSharedMemorySize, TC_SMEM);
    cudaFuncSetAttribute((const void*)tconv<128, 1, VOCAB, false, true, false>,
                         cudaFuncAttributeMaxDynamicSharedMemorySize, TC_SMEM);

    // ---- weight packing/splitting (cheap, every call for determinism) ----
    pack_split< 64, 1, 256>  <<<(256*64)      / 256, 256>>>(dw1, w1hi, w1lo);
    pack_split<256, 3, 256>  <<<(256*768)     / 256, 256>>>(dw2, w2hi, w2lo);
    pack_split<256, 1, 128>  <<<(128*256)     / 256, 256>>>(dw3, w3hi, w3lo);
    pack_split<128, 1, VOCAB><<<(VOCAB*128)   / 256, 256>>>(ow,  bhi,  blo);

    // ---- encoder (fp32; untouched — protects VQ code decisions) ----
    embed_kernel<<<NPOS * 32 / 256, 256>>>(x, tok, emb);
    conv_gemm<128, 256, 3, true ><<<dim3(NPOS / 64, 4), 256>>>(emb, ew1, eb1, h1);
    conv_gemm<256, 256, 3, true ><<<dim3(NPOS / 64, 4), 256>>>(h1, ew2, eb2, h2);
    enc_head_ln<<<NPOS / 64, 256>>>(h2, ew3, eb3, elg, elb, z);

    // ---- vector quantization ----
    cnorm_kernel<<<1, 512>>>(cb, cn);
    vq_kernel<<<NPOS / 64, 256>>>(z, cb, cn, codes, cp);
    gather_zq_split<<<NPOS * 16 / 256, 256>>>(codes, cb, zqhi, zqlo);

    // ---- decoder (bf16x3 tensor cores, fused split epilogues) ----
    tconv< 64, 1, 256, true,  false, true ><<<dim3(NPOS/128, 2),  256, TC_SMEM>>>(
        zqhi, zqlo, w1hi, w1lo, db1, nullptr, d1hi, d1lo);
    tconv<256, 3, 256, true,  false, true ><<<dim3(NPOS/128, 2),  256, TC_SMEM>>>(
        d1hi, d1lo, w2hi, w2lo, db2, nullptr, d2hi, d2lo);
    tconv<256, 1, 128, true,  true,  false><<<dim3(NPOS/128, 1),  256, TC_SMEM>>>(
        d2hi, d2lo, w3hi, w3lo, db3, emb, nullptr, nullptr);
    ln128_split<<<NPOS / 8, 256>>>(emb, dlg, dlb, ahi, alo);

    // ---- vocab projection (bf16x3) -> d_out ----
    tconv<128, 1, VOCAB, false, true, false><<<dim3(NPOS/128, VOCAB/128), 256, TC_SMEM>>>(
        ahi, alo, bhi, blo, ob, out, nullptr, nullptr);

    // ---- tail: loss scalar + codes ----
    const long long NV = (long long)NPOS * VOCAB;   // 134217728
    if ((long long)out_size >= NV + 1)
        commit_final<<<1, 32>>>(cp, out + NV);
    if ((long long)out_size >= NV + 1 + NPOS)
        write_codes<<<NPOS / 256, 256>>>(codes, out + NV + 1);
}

// round 6
// speedup vs baseline: 2.1767x; 1.2161x over previous
#include <cuda_runtime.h>
#include <cuda_bf16.h>
#include <cstdint>

// Problem constants
#define NPOS   32768          // B*L = 8*4096
#define LSEQ   4096
#define EDIM   128
#define HDIM   256
#define DDIM   64
#define KCODE  512
#define VOCAB  4096
#define LN_EPS 1e-5f

typedef __nv_bfloat16 bf16;

// ---------------- scratch (static device globals; no allocation) -------------
__device__ float g_emb[NPOS * EDIM];    // decoder conv3 output (fp32)
__device__ float g_h2 [NPOS * HDIM];    // encoder conv2 output (fp32)
__device__ float g_z  [NPOS * DDIM];    // z_e after LN
__device__ int   g_codes[NPOS];
__device__ float g_cnorm[KCODE];
__device__ float g_commit[NPOS / 64];
// encoder triple-split activations
__device__ __align__(16) bf16 g_ebh[NPOS * EDIM];
__device__ __align__(16) bf16 g_ebm[NPOS * EDIM];
__device__ __align__(16) bf16 g_ebl[NPOS * EDIM];
__device__ __align__(16) bf16 g_e1h[NPOS * HDIM];
__device__ __align__(16) bf16 g_e1m[NPOS * HDIM];
__device__ __align__(16) bf16 g_e1l[NPOS * HDIM];
// encoder triple-split packed weights
__device__ __align__(16) bf16 g_w1eh[HDIM * EDIM * 3];
__device__ __align__(16) bf16 g_w1em[HDIM * EDIM * 3];
__device__ __align__(16) bf16 g_w1el[HDIM * EDIM * 3];
__device__ __align__(16) bf16 g_w2eh[HDIM * HDIM * 3];
__device__ __align__(16) bf16 g_w2em[HDIM * HDIM * 3];
__device__ __align__(16) bf16 g_w2el[HDIM * HDIM * 3];
// decoder bf16 hi/lo split activations
__device__ __align__(16) bf16 g_zqhi[NPOS * DDIM];
__device__ __align__(16) bf16 g_zqlo[NPOS * DDIM];
__device__ __align__(16) bf16 g_d1hi[NPOS * HDIM];
__device__ __align__(16) bf16 g_d1lo[NPOS * HDIM];
__device__ __align__(16) bf16 g_d2hi[NPOS * HDIM];
__device__ __align__(16) bf16 g_d2lo[NPOS * HDIM];
__device__ __align__(16) bf16 g_ahi[NPOS * EDIM];
__device__ __align__(16) bf16 g_alo[NPOS * EDIM];
// decoder bf16 hi/lo split packed weights
__device__ __align__(16) bf16 g_w1hi[HDIM * DDIM];
__device__ __align__(16) bf16 g_w1lo[HDIM * DDIM];
__device__ __align__(16) bf16 g_w2hi[HDIM * HDIM * 3];
__device__ __align__(16) bf16 g_w2lo[HDIM * HDIM * 3];
__device__ __align__(16) bf16 g_w3hi[EDIM * HDIM];
__device__ __align__(16) bf16 g_w3lo[EDIM * HDIM];
__device__ __align__(16) bf16 g_bhi[VOCAB * EDIM];
__device__ __align__(16) bf16 g_blo[VOCAB * EDIM];

__device__ __forceinline__ uint32_t smem_to_u32(const void* smem_ptr) {
    uint32_t addr;
    asm("{ .reg .u64 tmp; cvta.to.shared.u64 tmp, %1; cvt.u32.u64 %0, tmp; }"
        : "=r"(addr) : "l"(smem_ptr));
    return addr;
}

__device__ __forceinline__ void split3(float x, bf16& h, bf16& m, bf16& l) {
    h = __float2bfloat16(x);
    float r = x - __bfloat162float(h);
    m = __float2bfloat16(r);
    float r2 = r - __bfloat162float(m);
    l = __float2bfloat16(r2);
}

// ---------------- embedding lookup with fused triple split -------------------
__global__ void embed_split3(const int* __restrict__ x,
                             const float* __restrict__ tok,
                             bf16* __restrict__ H, bf16* __restrict__ M,
                             bf16* __restrict__ L)
{
    int idx = blockIdx.x * blockDim.x + threadIdx.x;   // NPOS*32 float4s
    int n = idx >> 5;
    int j = idx & 31;
    int t = x[n];
    float4 v = reinterpret_cast<const float4*>(tok)[t * 32 + j];
    bf16 h0,m0,l0,h1,m1,l1,h2,m2,l2,h3,m3,l3;
    split3(v.x,h0,m0,l0); split3(v.y,h1,m1,l1);
    split3(v.z,h2,m2,l2); split3(v.w,h3,m3,l3);
    __nv_bfloat162 p;
    p.x=h0; p.y=h1; reinterpret_cast<__nv_bfloat162*>(H)[n*64+j*2+0]=p;
    p.x=h2; p.y=h3; reinterpret_cast<__nv_bfloat162*>(H)[n*64+j*2+1]=p;
    p.x=m0; p.y=m1; reinterpret_cast<__nv_bfloat162*>(M)[n*64+j*2+0]=p;
    p.x=m2; p.y=m3; reinterpret_cast<__nv_bfloat162*>(M)[n*64+j*2+1]=p;
    p.x=l0; p.y=l1; reinterpret_cast<__nv_bfloat162*>(L)[n*64+j*2+0]=p;
    p.x=l2; p.y=l3; reinterpret_cast<__nv_bfloat162*>(L)[n*64+j*2+1]=p;
}

// ---------------- weight pack + splits ----------------------------------------
// W[COUT][CIN][KW] -> Wp[COUT][tap*CIN + ci]
template<int CIN, int KW, int COUT>
__global__ void pack_split(const float* __restrict__ W,
                           bf16* __restrict__ Hi, bf16* __restrict__ Lo)
{
    int idx = blockIdx.x * blockDim.x + threadIdx.x;
    if (idx >= COUT * KW * CIN) return;
    int o   = idx / (KW * CIN);
    int rem = idx - o * (KW * CIN);
    int tap = rem / CIN;
    int ci  = rem - tap * CIN;
    float w = W[(size_t)o * CIN * KW + ci * KW + tap];
    bf16 h = __float2bfloat16(w);
    Hi[idx] = h;
    Lo[idx] = __float2bfloat16(w - __bfloat162float(h));
}

template<int CIN, int KW, int COUT>
__global__ void pack_split3(const float* __restrict__ W,
                            bf16* __restrict__ H, bf16* __restrict__ M,
                            bf16* __restrict__ L)
{
    int idx = blockIdx.x * blockDim.x + threadIdx.x;
    if (idx >= COUT * KW * CIN) return;
    int o   = idx / (KW * CIN);
    int rem = idx - o * (KW * CIN);
    int tap = rem / CIN;
    int ci  = rem - tap * CIN;
    float w = W[(size_t)o * CIN * KW + ci * KW + tap];
    bf16 h, m, l;
    split3(w, h, m, l);
    H[idx] = h; M[idx] = m; L[idx] = l;
}

// ---------------- encoder head: conv1x1 (256->64) + LayerNorm(D=64) ---------
__global__ void __launch_bounds__(256)
enc_head_ln(const float* __restrict__ X, const float* __restrict__ W,
            const float* __restrict__ Bias,
            const float* __restrict__ G, const float* __restrict__ Bt,
            float* __restrict__ Z)
{
    constexpr int CIN = 256;
    __shared__ float As[32][66];
    __shared__ float Bs[32][66];
    __shared__ float Zs[64][66];

    const int pm0 = blockIdx.x * 64;
    const int tid = threadIdx.x;
    const int tx = tid & 15, ty = tid >> 4;
    const int rr = tid & 31;
    const int mrow = tid >> 5;

    float acc[4][4];
#pragma unroll
    for (int i = 0; i < 4; i++)
#pragma unroll
        for (int j = 0; j < 4; j++) acc[i][j] = 0.f;

    for (int r0 = 0; r0 < CIN; r0 += 32) {
        const int ci = r0 + rr;
#pragma unroll
        for (int i = 0; i < 8; i++) {
            const int m = mrow + i * 8;
            As[rr][m] = X[(size_t)(pm0 + m) * CIN + ci];
        }
#pragma unroll
        for (int i = 0; i < 8; i++) {
            const int n = mrow + i * 8;
            Bs[rr][n] = W[(size_t)n * CIN + ci];
        }
        __syncthreads();
#pragma unroll
        for (int kk = 0; kk < 32; kk++) {
            float a[4], b[4];
#pragma unroll
            for (int i = 0; i < 4; i++) a[i] = As[kk][ty * 4 + i];
#pragma unroll
            for (int j = 0; j < 4; j++) b[j] = Bs[kk][tx * 4 + j];
#pragma unroll
            for (int i = 0; i < 4; i++)
#pragma unroll
                for (int j = 0; j < 4; j++)
                    acc[i][j] = fmaf(a[i], b[j], acc[i][j]);
        }
        __syncthreads();
    }
#pragma unroll
    for (int i = 0; i < 4; i++)
#pragma unroll
        for (int j = 0; j < 4; j++)
            Zs[ty * 4 + i][tx * 4 + j] = acc[i][j] + Bias[tx * 4 + j];
    __syncthreads();

    const int lane = tid & 31, w = tid >> 5;
#pragma unroll
    for (int q = 0; q < 8; q++) {
        const int m = w * 8 + q;
        float v0 = Zs[m][lane];
        float v1 = Zs[m][lane + 32];
        float s = v0 + v1;
#pragma unroll
        for (int off = 16; off > 0; off >>= 1)
            s += __shfl_xor_sync(0xffffffffu, s, off);
        float mu = s * (1.f / 64.f);
        float d0 = v0 - mu, d1 = v1 - mu;
        float sq = __fadd_rn(__fmul_rn(d0, d0), __fmul_rn(d1, d1));
#pragma unroll
        for (int off = 16; off > 0; off >>= 1)
            sq += __shfl_xor_sync(0xffffffffu, sq, off);
        float var = sq * (1.f / 64.f);
        float rs  = rsqrtf(var + LN_EPS);
        const int p = pm0 + m;
        Z[(size_t)p * 64 + lane]      = d0 * rs * G[lane]      + Bt[lane];
        Z[(size_t)p * 64 + lane + 32] = d1 * rs * G[lane + 32] + Bt[lane + 32];
    }
}

// ---------------- codebook norms (no FMA: match sum(c*c)) --------------------
__global__ void cnorm_kernel(const float* __restrict__ CB, float* __restrict__ CN)
{
    int c = blockIdx.x * blockDim.x + threadIdx.x;
    if (c < KCODE) {
        float s = 0.f;
        for (int d = 0; d < DDIM; d++) {
            float v = CB[c * DDIM + d];
            s = __fadd_rn(s, __fmul_rn(v, v));
        }
        CN[c] = s;
    }
}

// ---------------- VQ: argmin over codes + commit-loss partials ---------------
__global__ void __launch_bounds__(256)
vq_kernel(const float* __restrict__ Z, const float* __restrict__ CB,
          const float* __restrict__ CN, int* __restrict__ Codes,
          float* __restrict__ CommitPart)
{
    __shared__ float Zt[64][66];
    __shared__ float Cs[64][66];
    __shared__ float znS[64];
    __shared__ float cvals[64];

    const int pm0 = blockIdx.x * 64;
    const int tid = threadIdx.x;
    const int tx = tid & 15, ty = tid >> 4;

#pragma unroll
    for (int i = 0; i < 16; i++) {
        int idx = tid + i * 256;
        int m = idx >> 6, d = idx & 63;
        Zt[d][m] = Z[(size_t)(pm0 + m) * 64 + d];
    }
    __syncthreads();

    if (tid < 64) {
        const int m = tid;
        float s = 0.f;
        for (int d = 0; d < 64; d++) {
            float v = Zt[d][m];
            s = __fadd_rn(s, __fmul_rn(v, v));
        }
        znS[m] = s;
    }
    __syncthreads();

    float zm[4];
#pragma unroll
    for (int i = 0; i < 4; i++) zm[i] = znS[ty * 4 + i];

    float minv[4]; int mini[4];
#pragma unroll
    for (int i = 0; i < 4; i++) { minv[i] = 3.4e38f; mini[i] = 0; }

    for (int c0 = 0; c0 < KCODE; c0 += 64) {
        __syncthreads();
#pragma unroll
        for (int i = 0; i < 16; i++) {
            int idx = tid + i * 256;
            int c = idx >> 6, d = idx & 63;
            Cs[d][c] = CB[(size_t)(c0 + c) * 64 + d];
        }
        __syncthreads();

        float dot[4][4];
#pragma unroll
        for (int i = 0; i < 4; i++)
#pragma unroll
            for (int j = 0; j < 4; j++) dot[i][j] = 0.f;
#pragma unroll
        for (int kk = 0; kk < 64; kk++) {
            float a[4], b[4];
#pragma unroll
            for (int i = 0; i < 4; i++) a[i] = Zt[kk][ty * 4 + i];
#pragma unroll
            for (int j = 0; j < 4; j++) b[j] = Cs[kk][tx * 4 + j];
#pragma unroll
            for (int i = 0; i < 4; i++)
#pragma unroll
                for (int j = 0; j < 4; j++)
                    dot[i][j] = fmaf(a[i], b[j], dot[i][j]);
        }
#pragma unroll
        for (int j = 0; j < 4; j++) {
            const int c = c0 + tx * 4 + j;
            const float cn = CN[c];
#pragma unroll
            for (int i = 0; i < 4; i++) {
                float t    = __fadd_rn(zm[i], -__fmul_rn(2.f, dot[i][j]));
                float dist = __fadd_rn(t, cn);
                if (dist < minv[i]) { minv[i] = dist; mini[i] = c; }
            }
        }
    }
    __syncthreads();

    float* redv = &Cs[0][0];
    int*   redi = reinterpret_cast<int*>(&Cs[0][0]) + 1024;
#pragma unroll
    for (int i = 0; i < 4; i++) {
        const int m = ty * 4 + i;
        redv[m * 16 + tx] = minv[i];
        redi[m * 16 + tx] = mini[i];
    }
    __syncthreads();
    if (tid < 64) {
        const int m = tid;
        float bv = redv[m * 16];
        int   bi = redi[m * 16];
        for (int t = 1; t < 16; t++) {
            float v = redv[m * 16 + t];
            int  ix = redi[m * 16 + t];
            if (v < bv || (v == bv && ix < bi)) { bv = v; bi = ix; }
        }
        Codes[pm0 + m] = bi;
        cvals[m] = bv;
    }
    __syncthreads();
    if (tid == 0) {
        float s = 0.f;
        for (int m = 0; m < 64; m++) s += cvals[m];
        CommitPart[blockIdx.x] = s;
    }
}

// ---------------- gather z_q with fused bf16 hi/lo split ----------------------
__global__ void gather_zq_split(const int* __restrict__ codes,
                                const float* __restrict__ CB,
                                bf16* __restrict__ Hi, bf16* __restrict__ Lo)
{
    int idx = blockIdx.x * blockDim.x + threadIdx.x;   // NPOS*16 float4s
    int n = idx >> 4;
    int j = idx & 15;
    float4 v = reinterpret_cast<const float4*>(CB)[codes[n] * 16 + j];
    bf16 h0 = __float2bfloat16(v.x), h1 = __float2bfloat16(v.y);
    bf16 h2 = __float2bfloat16(v.z), h3 = __float2bfloat16(v.w);
    __nv_bfloat162 hh0; hh0.x = h0; hh0.y = h1;
    __nv_bfloat162 hh1; hh1.x = h2; hh1.y = h3;
    __nv_bfloat162 ll0; ll0.x = __float2bfloat16(v.x - __bfloat162float(h0));
    ll0.y = __float2bfloat16(v.y - __bfloat162float(h1));
    __nv_bfloat162 ll1; ll1.x = __float2bfloat16(v.z - __bfloat162float(h2));
    ll1.y = __float2bfloat16(v.w - __bfloat162float(h3));
    reinterpret_cast<__nv_bfloat162*>(Hi)[n * 32 + j * 2 + 0] = hh0;
    reinterpret_cast<__nv_bfloat162*>(Hi)[n * 32 + j * 2 + 1] = hh1;
    reinterpret_cast<__nv_bfloat162*>(Lo)[n * 32 + j * 2 + 0] = ll0;
    reinterpret_cast<__nv_bfloat162*>(Lo)[n * 32 + j * 2 + 1] = ll1;
}

// ---------------- LayerNorm over E=128 + fused split --------------------------
__global__ void ln128_split(const float* __restrict__ X,
                            const float* __restrict__ G,
                            const float* __restrict__ B,
                            bf16* __restrict__ Hi, bf16* __restrict__ Lo)
{
    const int w = threadIdx.x >> 5, lane = threadIdx.x & 31;
    const int p = blockIdx.x * 8 + w;
    float v[4];
#pragma unroll
    for (int i = 0; i < 4; i++) v[i] = X[(size_t)p * 128 + lane + 32 * i];
    float s = 0.f;
#pragma unroll
    for (int i = 0; i < 4; i++) s += v[i];
#pragma unroll
    for (int off = 16; off > 0; off >>= 1)
        s += __shfl_xor_sync(0xffffffffu, s, off);
    float mu = s * (1.f / 128.f);
    float d[4];
    float sq = 0.f;
#pragma unroll
    for (int i = 0; i < 4; i++) {
        d[i] = v[i] - mu;
        sq = __fadd_rn(sq, __fmul_rn(d[i], d[i]));
    }
#pragma unroll
    for (int off = 16; off > 0; off >>= 1)
        sq += __shfl_xor_sync(0xffffffffu, sq, off);
    float var = sq * (1.f / 128.f);
    float rs  = rsqrtf(var + LN_EPS);
#pragma unroll
    for (int i = 0; i < 4; i++) {
        const int c = lane + 32 * i;
        float y = d[i] * rs * G[c] + B[c];
        bf16 h = __float2bfloat16(y);
        Hi[(size_t)p * 128 + c] = h;
        Lo[(size_t)p * 128 + c] = __float2bfloat16(y - __bfloat162float(h));
    }
}

// ---------------- mma helpers -------------------------------------------------
__device__ __forceinline__ void ldsm_x4(uint32_t* r, uint32_t addr) {
    asm volatile("ldmatrix.sync.aligned.m8n8.x4.shared.b16 {%0,%1,%2,%3}, [%4];"
                 : "=r"(r[0]), "=r"(r[1]), "=r"(r[2]), "=r"(r[3]) : "r"(addr));
}
__device__ __forceinline__ void mma16816(float* d, const uint32_t* a,
                                         uint32_t b0, uint32_t b1) {
    asm volatile(
        "mma.sync.aligned.m16n8k16.row.col.f32.bf16.bf16.f32 "
        "{%0,%1,%2,%3}, {%4,%5,%6,%7}, {%8,%9}, {%0,%1,%2,%3};"
        : "+f"(d[0]), "+f"(d[1]), "+f"(d[2]), "+f"(d[3])
        : "r"(a[0]), "r"(a[1]), "r"(a[2]), "r"(a[3]), "r"(b0), "r"(b1));
}

// ---------------- generic bf16x3 (hi/lo) tensor conv/GEMM --------------------
#define TC_SMEM 65536

template<int CIN, int KW, int COUT, bool RELU, bool WF32, bool WSPLIT>
__global__ void __launch_bounds__(256)
tconv(const bf16* __restrict__ Ahi, const bf16* __restrict__ Alo,
      const bf16* __restrict__ Whi, const bf16* __restrict__ Wlo,
      const float* __restrict__ Bias,
      float* __restrict__ Yf, bf16* __restrict__ Yhi, bf16* __restrict__ Ylo)
{
    constexpr int KTOT = CIN * KW;
    constexpr int NCH  = KTOT / 64;
    constexpr int PAD  = (KW == 3) ? 1 : 0;

    extern __shared__ char smem[];
    char* sAhi = smem;
    char* sAlo = smem + 16384;
    char* sBhi = smem + 32768;
    char* sBlo = smem + 49152;

    const int tid = threadIdx.x;
    const int pm0 = blockIdx.x * 128;
    const int nv0 = blockIdx.y * 128;

    const int wid = tid >> 5, lane = tid & 31;
    const int wm = (wid >> 1) * 32;
    const int wn = (wid & 1) * 64;
    const int lr = lane & 7, lq = lane >> 3;

    float acc[2][8][4];
#pragma unroll
    for (int mi = 0; mi < 2; mi++)
#pragma unroll
        for (int ni = 0; ni < 8; ni++)
#pragma unroll
            for (int e = 0; e < 4; e++) acc[mi][ni][e] = 0.f;

    const uint4* A4h = reinterpret_cast<const uint4*>(Ahi);
    const uint4* A4l = reinterpret_cast<const uint4*>(Alo);
    const uint4* B4h = reinterpret_cast<const uint4*>(Whi);
    const uint4* B4l = reinterpret_cast<const uint4*>(Wlo);

    const uint32_t sb = smem_to_u32(smem);
    const uint32_t aB3[3] = { sb + 0u, sb + 0u, sb + 16384u };         // hi, hi, lo
    const uint32_t bB3[3] = { sb + 32768u, sb + 49152u, sb + 32768u }; // hi, lo, hi

    for (int ch = 0; ch < NCH; ch++) {
        const int tap = (ch * 64) / CIN;
        const int ci0 = (ch * 64) % CIN;
#pragma unroll
        for (int i = 0; i < 4; i++) {
            int idx = tid + i * 256;
            int row = idx >> 3, c = idx & 7;
            int p = pm0 + row;
            bool ok = true;
            if (KW == 3) {
                int ls = (p & (LSEQ - 1)) + tap - PAD;
                ok = ((unsigned)ls < (unsigned)LSEQ);
            }
            uint4 zz = make_uint4(0u, 0u, 0u, 0u);
            size_t gi = (size_t)(p + tap - PAD) * (CIN / 8) + (ci0 / 8) + c;
            uint4 vh = ok ? A4h[gi] : zz;
            uint4 vl = ok ? A4l[gi] : zz;
            int pc = (c ^ row) & 7;
            *reinterpret_cast<uint4*>(sAhi + row * 128 + pc * 16) = vh;
            *reinterpret_cast<uint4*>(sAlo + row * 128 + pc * 16) = vl;
        }
#pragma unroll
        for (int i = 0; i < 4; i++) {
            int idx = tid + i * 256;
            int row = idx >> 3, c = idx & 7;
            size_t gi = (size_t)(nv0 + row) * (KTOT / 8) + ch * 8 + c;
            uint4 vh = B4h[gi];
            uint4 vl = B4l[gi];
            int pc = (c ^ row) & 7;
            *reinterpret_cast<uint4*>(sBhi + row * 128 + pc * 16) = vh;
            *reinterpret_cast<uint4*>(sBlo + row * 128 + pc * 16) = vl;
        }
        __syncthreads();

#pragma unroll
        for (int s = 0; s < 3; s++) {
            const uint32_t aB = aB3[s];
            const uint32_t bB = bB3[s];
#pragma unroll
            for (int k16 = 0; k16 < 4; k16++) {
                const int kc0 = k16 * 2;
                uint32_t a[2][4];
#pragma unroll
                for (int mi = 0; mi < 2; mi++) {
                    int row = wm + mi * 16 + lr + (lq & 1) * 8;
                    int kc  = kc0 + (lq >> 1);
                    int pc  = (kc ^ row) & 7;
                    ldsm_x4(a[mi], aB + row * 128 + pc * 16);
                }
                uint32_t b[4][4];
#pragma unroll
                for (int nc = 0; nc < 4; nc++) {
                    int row = wn + nc * 16 + lr + (lq >> 1) * 8;
                    int kc  = kc0 + (lq & 1);
                    int pc  = (kc ^ row) & 7;
                    ldsm_x4(b[nc], bB + row * 128 + pc * 16);
                }
#pragma unroll
                for (int mi = 0; mi < 2; mi++)
#pragma unroll
                    for (int ni = 0; ni < 8; ni++)
                        mma16816(acc[mi][ni], a[mi],
                                 b[ni >> 1][(ni & 1) * 2 + 0],
                                 b[ni >> 1][(ni & 1) * 2 + 1]);
            }
        }
        __syncthreads();
    }

    const int gid = lane >> 2, tig = lane & 3;
#pragma unroll
    for (int mi = 0; mi < 2; mi++) {
        const int m0 = pm0 + wm + mi * 16 + gid;
#pragma unroll
        for (int ni = 0; ni < 8; ni++) {
            const int n = nv0 + wn + ni * 8 + tig * 2;
            const float2 bv = *reinterpret_cast<const float2*>(Bias + n);
            float v00 = acc[mi][ni][0] + bv.x;
            float v01 = acc[mi][ni][1] + bv.y;
            float v10 = acc[mi][ni][2] + bv.x;
            float v11 = acc[mi][ni][3] + bv.y;
            if (RELU) {
                v00 = fmaxf(v00, 0.f); v01 = fmaxf(v01, 0.f);
                v10 = fmaxf(v10, 0.f); v11 = fmaxf(v11, 0.f);
            }
            if (WF32) {
                float2 a0; a0.x = v00; a0.y = v01;
                float2 a1; a1.x = v10; a1.y = v11;
                *reinterpret_cast<float2*>(Yf + (size_t)m0 * COUT + n)       = a0;
                *reinterpret_cast<float2*>(Yf + (size_t)(m0 + 8) * COUT + n) = a1;
            }
            if (WSPLIT) {
                bf16 h00 = __float2bfloat16(v00), h01 = __float2bfloat16(v01);
                bf16 h10 = __float2bfloat16(v10), h11 = __float2bfloat16(v11);
                __nv_bfloat162 hh0; hh0.x = h00; hh0.y = h01;
                __nv_bfloat162 hh1; hh1.x = h10; hh1.y = h11;
                __nv_bfloat162 ll0;
                ll0.x = __float2bfloat16(v00 - __bfloat162float(h00));
                ll0.y = __float2bfloat16(v01 - __bfloat162float(h01));
                __nv_bfloat162 ll1;
                ll1.x = __float2bfloat16(v10 - __bfloat162float(h10));
                ll1.y = __float2bfloat16(v11 - __bfloat162float(h11));
                *reinterpret_cast<__nv_bfloat162*>(Yhi + (size_t)m0 * COUT + n)       = hh0;
                *reinterpret_cast<__nv_bfloat162*>(Yhi + (size_t)(m0 + 8) * COUT + n) = hh1;
                *reinterpret_cast<__nv_bfloat162*>(Ylo + (size_t)m0 * COUT + n)       = ll0;
                *reinterpret_cast<__nv_bfloat162*>(Ylo + (size_t)(m0 + 8) * COUT + n) = ll1;
            }
        }
    }
}

// ---------------- bf16x6 (triple-split) tensor conv — encoder ----------------
// 6 product terms: hh, hm, mh, hl, lh, mm -> error ~2^-24 (fp32-level)
#define TC6_SMEM 98304

template<int CIN, int KW, int COUT, bool WF32>
__global__ void __launch_bounds__(256)
tconv6(const bf16* __restrict__ Ah, const bf16* __restrict__ Am, const bf16* __restrict__ Al,
       const bf16* __restrict__ Wh, const bf16* __restrict__ Wm, const bf16* __restrict__ Wl,
       const float* __restrict__ Bias, float* __restrict__ Yf,
       bf16* __restrict__ Yh, bf16* __restrict__ Ym, bf16* __restrict__ Yl)
{
    constexpr int KTOT = CIN * KW;
    constexpr int NCH  = KTOT / 64;
    constexpr int PAD  = (KW == 3) ? 1 : 0;

    extern __shared__ char smem[];
    const int tid = threadIdx.x;
    const int pm0 = blockIdx.x * 128;
    const int nv0 = blockIdx.y * 128;

    const int wid = tid >> 5, lane = tid & 31;
    const int wm = (wid >> 1) * 32;
    const int wn = (wid & 1) * 64;
    const int lr = lane & 7, lq = lane >> 3;

    float acc[2][8][4];
#pragma unroll
    for (int mi = 0; mi < 2; mi++)
#pragma unroll
        for (int ni = 0; ni < 8; ni++)
#pragma unroll
            for (int e = 0; e < 4; e++) acc[mi][ni][e] = 0.f;

    const uint4* A4[3] = { reinterpret_cast<const uint4*>(Ah),
                           reinterpret_cast<const uint4*>(Am),
                           reinterpret_cast<const uint4*>(Al) };
    const uint4* B4[3] = { reinterpret_cast<const uint4*>(Wh),
                           reinterpret_cast<const uint4*>(Wm),
                           reinterpret_cast<const uint4*>(Wl) };

    const uint32_t sb = smem_to_u32(smem);
    // product pairs: (h,h) (h,m) (m,h) (h,l) (l,h) (m,m)
    const int AI[6] = { 0, 0, 1, 0, 2, 1 };
    const int BI[6] = { 0, 1, 0, 2, 0, 1 };

    for (int ch = 0; ch < NCH; ch++) {
        const int tap = (ch * 64) / CIN;
        const int ci0 = (ch * 64) % CIN;
#pragma unroll
        for (int i = 0; i < 4; i++) {
            int idx = tid + i * 256;
            int row = idx >> 3, c = idx & 7;
            int p = pm0 + row;
            bool ok = true;
            if (KW == 3) {
                int ls = (p & (LSEQ - 1)) + tap - PAD;
                ok = ((unsigned)ls < (unsigned)LSEQ);
            }
            uint4 zz = make_uint4(0u, 0u, 0u, 0u);
            size_t gi = (size_t)(p + tap - PAD) * (CIN / 8) + (ci0 / 8) + c;
            int pc = (c ^ row) & 7;
#pragma unroll
            for (int sp = 0; sp < 3; sp++) {
                uint4 v = ok ? A4[sp][gi] : zz;
                *reinterpret_cast<uint4*>(smem + sp * 16384 + row * 128 + pc * 16) = v;
            }
        }
#pragma unroll
        for (int i = 0; i < 4; i++) {
            int idx = tid + i * 256;
            int row = idx >> 3, c = idx & 7;
            size_t gi = (size_t)(nv0 + row) * (KTOT / 8) + ch * 8 + c;
            int pc = (c ^ row) & 7;
#pragma unroll
            for (int sp = 0; sp < 3; sp++) {
                uint4 v = B4[sp][gi];
                *reinterpret_cast<uint4*>(smem + 49152 + sp * 16384 + row * 128 + pc * 16) = v;
            }
        }
        __syncthreads();

#pragma unroll
        for (int s = 0; s < 6; s++) {
            const uint32_t aB = sb + AI[s] * 16384u;
            const uint32_t bB = sb + 49152u + BI[s] * 16384u;
#pragma unroll
            for (int k16 = 0; k16 < 4; k16++) {
                const int kc0 = k16 * 2;
                uint32_t a[2][4];
#pragma unroll
                for (int mi = 0; mi < 2; mi++) {
                    int row = wm + mi * 16 + lr + (lq & 1) * 8;
                    int kc  = kc0 + (lq >> 1);
                    int pc  = (kc ^ row) & 7;
                    ldsm_x4(a[mi], aB + row * 128 + pc * 16);
                }
                uint32_t b[4][4];
#pragma unroll
                for (int nc = 0; nc < 4; nc++) {
                    int row = wn + nc * 16 + lr + (lq >> 1) * 8;
                    int kc  = kc0 + (lq & 1);
                    int pc  = (kc ^ row) & 7;
                    ldsm_x4(b[nc], bB + row * 128 + pc * 16);
                }
#pragma unroll
                for (int mi = 0; mi < 2; mi++)
#pragma unroll
                    for (int ni = 0; ni < 8; ni++)
                        mma16816(acc[mi][ni], a[mi],
                                 b[ni >> 1][(ni & 1) * 2 + 0],
                                 b[ni >> 1][(ni & 1) * 2 + 1]);
            }
        }
        __syncthreads();
    }

    // epilogue: bias + relu; fp32 or triple-split stores
    const int gid = lane >> 2, tig = lane & 3;
#pragma unroll
    for (int mi = 0; mi < 2; mi++) {
        const int m0 = pm0 + wm + mi * 16 + gid;
#pragma unroll
        for (int ni = 0; ni < 8; ni++) {
            const int n = nv0 + wn + ni * 8 + tig * 2;
            const float2 bv = *reinterpret_cast<const float2*>(Bias + n);
            float v00 = fmaxf(acc[mi][ni][0] + bv.x, 0.f);
            float v01 = fmaxf(acc[mi][ni][1] + bv.y, 0.f);
            float v10 = fmaxf(acc[mi][ni][2] + bv.x, 0.f);
            float v11 = fmaxf(acc[mi][ni][3] + bv.y, 0.f);
            if (WF32) {
                float2 a0; a0.x = v00; a0.y = v01;
                float2 a1; a1.x = v10; a1.y = v11;
                *reinterpret_cast<float2*>(Yf + (size_t)m0 * COUT + n)       = a0;
                *reinterpret_cast<float2*>(Yf + (size_t)(m0 + 8) * COUT + n) = a1;
            } else {
                bf16 h00,m00,l00,h01,m01,l01,h10,m10,l10,h11,m11,l11;
                split3(v00,h00,m00,l00); split3(v01,h01,m01,l01);
                split3(v10,h10,m10,l10); split3(v11,h11,m11,l11);
                __nv_bfloat162 p0, p1;
                p0.x=h00; p0.y=h01; p1.x=h10; p1.y=h11;
                *reinterpret_cast<__nv_bfloat162*>(Yh + (size_t)m0 * COUT + n)       = p0;
                *reinterpret_cast<__nv_bfloat162*>(Yh + (size_t)(m0 + 8) * COUT + n) = p1;
                p0.x=m00; p0.y=m01; p1.x=m10; p1.y=m11;
                *reinterpret_cast<__nv_bfloat162*>(Ym + (size_t)m0 * COUT + n)       = p0;
                *reinterpret_cast<__nv_bfloat162*>(Ym + (size_t)(m0 + 8) * COUT + n) = p1;
                p0.x=l00; p0.y=l01; p1.x=l10; p1.y=l11;
                *reinterpret_cast<__nv_bfloat162*>(Yl + (size_t)m0 * COUT + n)       = p0;
                *reinterpret_cast<__nv_bfloat162*>(Yl + (size_t)(m0 + 8) * COUT + n) = p1;
            }
        }
    }
}

// ---------------- tail: loss scalar + codes ----------------------------------
__global__ void commit_final(const float* __restrict__ Part, float* __restrict__ slot)
{
    if (threadIdx.x == 0 && blockIdx.x == 0) {
        float s = 0.f;
        for (int i = 0; i < NPOS / 64; i++) s += Part[i];
        *slot = 0.1f * s / ((float)NPOS * (float)DDIM);
    }
}

__global__ void write_codes(const int* __restrict__ codes, float* __restrict__ out)
{
    int n = blockIdx.x * blockDim.x + threadIdx.x;
    if (n < NPOS) out[n] = (float)codes[n];
}

// ---------------- launch ------------------------------------------------------
extern "C" void kernel_launch(void* const* d_in, const int* in_sizes, int n_in,
                              void* d_out, int out_size)
{
    (void)in_sizes; (void)n_in;
    const int*   x    = (const int*)  d_in[0];
    const float* tok  = (const float*)d_in[1];
    const float* ew1  = (const float*)d_in[2];
    const float* eb1  = (const float*)d_in[3];
    const float* ew2  = (const float*)d_in[4];
    const float* eb2  = (const float*)d_in[5];
    const float* ew3  = (const float*)d_in[6];
    const float* eb3  = (const float*)d_in[7];
    const float* elg  = (const float*)d_in[8];
    const float* elb  = (const float*)d_in[9];
    const float* cb   = (const float*)d_in[10];
    const float* dw1  = (const float*)d_in[11];
    const float* db1  = (const float*)d_in[12];
    const float* dw2  = (const float*)d_in[13];
    const float* db2  = (const float*)d_in[14];
    const float* dw3  = (const float*)d_in[15];
    const float* db3  = (const float*)d_in[16];
    const float* dlg  = (const float*)d_in[17];
    const float* dlb  = (const float*)d_in[18];
    const float* ow   = (const float*)d_in[19];
    const float* ob   = (const float*)d_in[20];
    float* out = (float*)d_out;

    float *emb, *h2, *z, *cn, *cp;
    int* codes;
    bf16 *ebh,*ebm,*ebl,*e1h,*e1m,*e1l,*w1eh,*w1em,*w1el,*w2eh,*w2em,*w2el;
    bf16 *zqhi,*zqlo,*d1hi,*d1lo,*d2hi,*d2lo,*ahi,*alo;
    bf16 *w1hi,*w1lo,*w2hi,*w2lo,*w3hi,*w3lo,*bhi,*blo;
    cudaGetSymbolAddress((void**)&emb,   g_emb);
    cudaGetSymbolAddress((void**)&h2,    g_h2);
    cudaGetSymbolAddress((void**)&z,     g_z);
    cudaGetSymbolAddress((void**)&codes, g_codes);
    cudaGetSymbolAddress((void**)&cn,    g_cnorm);
    cudaGetSymbolAddress((void**)&cp,    g_commit);
    cudaGetSymbolAddress((void**)&ebh,   g_ebh);
    cudaGetSymbolAddress((void**)&ebm,   g_ebm);
    cudaGetSymbolAddress((void**)&ebl,   g_ebl);
    cudaGetSymbolAddress((void**)&e1h,   g_e1h);
    cudaGetSymbolAddress((void**)&e1m,   g_e1m);
    cudaGetSymbolAddress((void**)&e1l,   g_e1l);
    cudaGetSymbolAddress((void**)&w1eh,  g_w1eh);
    cudaGetSymbolAddress((void**)&w1em,  g_w1em);
    cudaGetSymbolAddress((void**)&w1el,  g_w1el);
    cudaGetSymbolAddress((void**)&w2eh,  g_w2eh);
    cudaGetSymbolAddress((void**)&w2em,  g_w2em);
    cudaGetSymbolAddress((void**)&w2el,  g_w2el);
    cudaGetSymbolAddress((void**)&zqhi,  g_zqhi);
    cudaGetSymbolAddress((void**)&zqlo,  g_zqlo);
    cudaGetSymbolAddress((void**)&d1hi,  g_d1hi);
    cudaGetSymbolAddress((void**)&d1lo,  g_d1lo);
    cudaGetSymbolAddress((void**)&d2hi,  g_d2hi);
    cudaGetSymbolAddress((void**)&d2lo,  g_d2lo);
    cudaGetSymbolAddress((void**)&ahi,   g_ahi);
    cudaGetSymbolAddress((void**)&alo,   g_alo);
    cudaGetSymbolAddress((void**)&w1hi,  g_w1hi);
    cudaGetSymbolAddress((void**)&w1lo,  g_w1lo);
    cudaGetSymbolAddress((void**)&w2hi,  g_w2hi);
    cudaGetSymbolAddress((void**)&w2lo,  g_w2lo);
    cudaGetSymbolAddress((void**)&w3hi,  g_w3hi);
    cudaGetSymbolAddress((void**)&w3lo,  g_w3lo);
    cudaGetSymbolAddress((void**)&bhi,   g_bhi);
    cudaGetSymbolAddress((void**)&blo,   g_blo);

    cudaFuncSetAttribute((const void*)tconv6<128, 3, 256, false>,
                         cudaFuncAttributeMaxDynamicSharedMemorySize, TC6_SMEM);
    cudaFuncSetAttribute((const void*)tconv6<256, 3, 256, true>,
                         cudaFuncAttributeMaxDynamicSharedMemorySize, TC6_SMEM);
    cudaFuncSetAttribute((const void*)tconv< 64, 1, 256, true,  false, true >,
                         cudaFuncAttributeMaxDynamicSharedMemorySize, TC_SMEM);
    cudaFuncSetAttribute((const void*)tconv<256, 3, 256, true,  false, true >,
                         cudaFuncAttributeMaxDynamicSharedMemorySize, TC_SMEM);
    cudaFuncSetAttribute((const void*)tconv<256, 1, 128, true,  true,  false>,
                         cudaFuncAttributeMaxDynamicSharedMemorySize, TC_SMEM);
    cudaFuncSetAttribute((const void*)tconv<128, 1, VOCAB, false, true, false>,
                         cudaFuncAttributeMaxDynamicSharedMemorySize, TC_SMEM);

    // ---- weight packing/splitting ----
    pack_split3<128, 3, 256> <<<(256*384)  / 256, 256>>>(ew1, w1eh, w1em, w1el);
    pack_split3<256, 3, 256> <<<(256*768)  / 256, 256>>>(ew2, w2eh, w2em, w2el);
    pack_split< 64, 1, 256>  <<<(256*64)   / 256, 256>>>(dw1, w1hi, w1lo);
    pack_split<256, 3, 256>  <<<(256*768)  / 256, 256>>>(dw2, w2hi, w2lo);
    pack_split<256, 1, 128>  <<<(128*256)  / 256, 256>>>(dw3, w3hi, w3lo);
    pack_split<128, 1, VOCAB><<<(VOCAB*128)/ 256, 256>>>(ow,  bhi,  blo);

    // ---- encoder (bf16x6 tensor cores; fp32-level accuracy protects VQ) ----
    embed_split3<<<NPOS * 32 / 256, 256>>>(x, tok, ebh, ebm, ebl);
    tconv6<128, 3, 256, false><<<dim3(NPOS/128, 2), 256, TC6_SMEM>>>(
        ebh, ebm, ebl, w1eh, w1em, w1el, eb1, nullptr, e1h, e1m, e1l);
    tconv6<256, 3, 256, true ><<<dim3(NPOS/128, 2), 256, TC6_SMEM>>>(
        e1h, e1m, e1l, w2eh, w2em, w2el, eb2, h2, nullptr, nullptr, nullptr);
    enc_head_ln<<<NPOS / 64, 256>>>(h2, ew3, eb3, elg, elb, z);

    // ---- vector quantization ----
    cnorm_kernel<<<1, 512>>>(cb, cn);
    vq_kernel<<<NPOS / 64, 256>>>(z, cb, cn, codes, cp);
    gather_zq_split<<<NPOS * 16 / 256, 256>>>(codes, cb, zqhi, zqlo);

    // ---- decoder (bf16x3 tensor cores, fused split epilogues) ----
    tconv< 64, 1, 256, true,  false, true ><<<dim3(NPOS/128, 2),  256, TC_SMEM>>>(
        zqhi, zqlo, w1hi, w1lo, db1, nullptr, d1hi, d1lo);
    tconv<256, 3, 256, true,  false, true ><<<dim3(NPOS/128, 2),  256, TC_SMEM>>>(
        d1hi, d1lo, w2hi, w2lo, db2, nullptr, d2hi, d2lo);
    tconv<256, 1, 128, true,  true,  false><<<dim3(NPOS/128, 1),  256, TC_SMEM>>>(
        d2hi, d2lo, w3hi, w3lo, db3, emb, nullptr, nullptr);
    ln128_split<<<NPOS / 8, 256>>>(emb, dlg, dlb, ahi, alo);

    // ---- vocab projection (bf16x3) -> d_out ----
    tconv<128, 1, VOCAB, false, true, false><<<dim3(NPOS/128, VOCAB/128), 256, TC_SMEM>>>(
        ahi, alo, bhi, blo, ob, out, nullptr, nullptr);

    // ---- tail: loss scalar + codes ----
    const long long NV = (long long)NPOS * VOCAB;   // 134217728
    if ((long long)out_size >= NV + 1)
        commit_final<<<1, 32>>>(cp, out + NV);
    if ((long long)out_size >= NV + 1 + NPOS)
        write_codes<<<NPOS / 256, 256>>>(codes, out + NV + 1);
}

// round 7
// speedup vs baseline: 2.5427x; 1.1682x over previous
#include <cuda_runtime.h>
#include <cuda_bf16.h>
#include <cuda_fp16.h>
#include <cstdint>

// Problem constants
#define NPOS   32768          // B*L = 8*4096
#define LSEQ   4096
#define EDIM   128
#define HDIM   256
#define DDIM   64
#define KCODE  512
#define VOCAB  4096
#define LN_EPS 1e-5f

typedef __nv_bfloat16 bf16;

#define LO_SCALE   2048.0f
#define LO_INV     (1.0f / 2048.0f)

// ---------------- scratch (static device globals; no allocation) -------------
__device__ float g_emb[NPOS * EDIM];    // decoder conv3 output (fp32)
__device__ float g_h2 [NPOS * HDIM];    // encoder conv2 output (fp32)
__device__ float g_z  [NPOS * DDIM];    // z_e after LN
__device__ int   g_codes[NPOS];
__device__ float g_cnorm[KCODE];
__device__ float g_commit[NPOS / 64];
// encoder fp16 two-split activations (lo scaled by 2048)
__device__ __align__(16) half g_ebh[NPOS * EDIM];
__device__ __align__(16) half g_ebm[NPOS * EDIM];
__device__ __align__(16) half g_e1h[NPOS * HDIM];
__device__ __align__(16) half g_e1m[NPOS * HDIM];
// encoder fp16 two-split packed weights
__device__ __align__(16) half g_w1eh[HDIM * EDIM * 3];
__device__ __align__(16) half g_w1em[HDIM * EDIM * 3];
__device__ __align__(16) half g_w2eh[HDIM * HDIM * 3];
__device__ __align__(16) half g_w2em[HDIM * HDIM * 3];
// decoder bf16 hi/lo split activations
__device__ __align__(16) bf16 g_zqhi[NPOS * DDIM];
__device__ __align__(16) bf16 g_zqlo[NPOS * DDIM];
__device__ __align__(16) bf16 g_d1hi[NPOS * HDIM];
__device__ __align__(16) bf16 g_d1lo[NPOS * HDIM];
__device__ __align__(16) bf16 g_d2hi[NPOS * HDIM];
__device__ __align__(16) bf16 g_d2lo[NPOS * HDIM];
__device__ __align__(16) bf16 g_ahi[NPOS * EDIM];
__device__ __align__(16) bf16 g_alo[NPOS * EDIM];
// decoder bf16 hi/lo split packed weights
__device__ __align__(16) bf16 g_w1hi[HDIM * DDIM];
__device__ __align__(16) bf16 g_w1lo[HDIM * DDIM];
__device__ __align__(16) bf16 g_w2hi[HDIM * HDIM * 3];
__device__ __align__(16) bf16 g_w2lo[HDIM * HDIM * 3];
__device__ __align__(16) bf16 g_w3hi[EDIM * HDIM];
__device__ __align__(16) bf16 g_w3lo[EDIM * HDIM];
__device__ __align__(16) bf16 g_bhi[VOCAB * EDIM];
__device__ __align__(16) bf16 g_blo[VOCAB * EDIM];

__device__ __forceinline__ uint32_t smem_to_u32(const void* smem_ptr) {
    uint32_t addr;
    asm("{ .reg .u64 tmp; cvta.to.shared.u64 tmp, %1; cvt.u32.u64 %0, tmp; }"
        : "=r"(addr) : "l"(smem_ptr));
    return addr;
}

// fp16 two-split: x = h + (m/2048); m kept in normal fp16 range
__device__ __forceinline__ void split2h(float x, half& h, half& m) {
    h = __float2half_rn(x);
    m = __float2half_rn((x - __half2float(h)) * LO_SCALE);
}

// ---------------- embedding lookup with fused fp16 two-split ------------------
__global__ void embed_split2h(const int* __restrict__ x,
                              const float* __restrict__ tok,
                              half* __restrict__ H, half* __restrict__ M)
{
    int idx = blockIdx.x * blockDim.x + threadIdx.x;   // NPOS*32 float4s
    int n = idx >> 5;
    int j = idx & 31;
    int t = x[n];
    float4 v = reinterpret_cast<const float4*>(tok)[t * 32 + j];
    half h0,m0,h1,m1,h2,m2,h3,m3;
    split2h(v.x,h0,m0); split2h(v.y,h1,m1);
    split2h(v.z,h2,m2); split2h(v.w,h3,m3);
    __half2 p;
    p.x=h0; p.y=h1; reinterpret_cast<__half2*>(H)[n*64+j*2+0]=p;
    p.x=h2; p.y=h3; reinterpret_cast<__half2*>(H)[n*64+j*2+1]=p;
    p.x=m0; p.y=m1; reinterpret_cast<__half2*>(M)[n*64+j*2+0]=p;
    p.x=m2; p.y=m3; reinterpret_cast<__half2*>(M)[n*64+j*2+1]=p;
}

// ---------------- weight pack + splits ----------------------------------------
template<int CIN, int KW, int COUT>
__global__ void pack_split(const float* __restrict__ W,
                           bf16* __restrict__ Hi, bf16* __restrict__ Lo)
{
    int idx = blockIdx.x * blockDim.x + threadIdx.x;
    if (idx >= COUT * KW * CIN) return;
    int o   = idx / (KW * CIN);
    int rem = idx - o * (KW * CIN);
    int tap = rem / CIN;
    int ci  = rem - tap * CIN;
    float w = W[(size_t)o * CIN * KW + ci * KW + tap];
    bf16 h = __float2bfloat16(w);
    Hi[idx] = h;
    Lo[idx] = __float2bfloat16(w - __bfloat162float(h));
}

template<int CIN, int KW, int COUT>
__global__ void pack_split2h(const float* __restrict__ W,
                             half* __restrict__ H, half* __restrict__ M)
{
    int idx = blockIdx.x * blockDim.x + threadIdx.x;
    if (idx >= COUT * KW * CIN) return;
    int o   = idx / (KW * CIN);
    int rem = idx - o * (KW * CIN);
    int tap = rem / CIN;
    int ci  = rem - tap * CIN;
    float w = W[(size_t)o * CIN * KW + ci * KW + tap];
    half h, m;
    split2h(w, h, m);
    H[idx] = h; M[idx] = m;
}

// ---------------- encoder head: conv1x1 (256->64) + LayerNorm(D=64) ---------
__global__ void __launch_bounds__(256)
enc_head_ln(const float* __restrict__ X, const float* __restrict__ W,
            const float* __restrict__ Bias,
            const float* __restrict__ G, const float* __restrict__ Bt,
            float* __restrict__ Z)
{
    constexpr int CIN = 256;
    __shared__ float As[32][66];
    __shared__ float Bs[32][66];
    __shared__ float Zs[64][66];

    const int pm0 = blockIdx.x * 64;
    const int tid = threadIdx.x;
    const int tx = tid & 15, ty = tid >> 4;
    const int rr = tid & 31;
    const int mrow = tid >> 5;

    float acc[4][4];
#pragma unroll
    for (int i = 0; i < 4; i++)
#pragma unroll
        for (int j = 0; j < 4; j++) acc[i][j] = 0.f;

    for (int r0 = 0; r0 < CIN; r0 += 32) {
        const int ci = r0 + rr;
#pragma unroll
        for (int i = 0; i < 8; i++) {
            const int m = mrow + i * 8;
            As[rr][m] = X[(size_t)(pm0 + m) * CIN + ci];
        }
#pragma unroll
        for (int i = 0; i < 8; i++) {
            const int n = mrow + i * 8;
            Bs[rr][n] = W[(size_t)n * CIN + ci];
        }
        __syncthreads();
#pragma unroll
        for (int kk = 0; kk < 32; kk++) {
            float a[4], b[4];
#pragma unroll
            for (int i = 0; i < 4; i++) a[i] = As[kk][ty * 4 + i];
#pragma unroll
            for (int j = 0; j < 4; j++) b[j] = Bs[kk][tx * 4 + j];
#pragma unroll
            for (int i = 0; i < 4; i++)
#pragma unroll
                for (int j = 0; j < 4; j++)
                    acc[i][j] = fmaf(a[i], b[j], acc[i][j]);
        }
        __syncthreads();
    }
#pragma unroll
    for (int i = 0; i < 4; i++)
#pragma unroll
        for (int j = 0; j < 4; j++)
            Zs[ty * 4 + i][tx * 4 + j] = acc[i][j] + Bias[tx * 4 + j];
    __syncthreads();

    const int lane = tid & 31, w = tid >> 5;
#pragma unroll
    for (int q = 0; q < 8; q++) {
        const int m = w * 8 + q;
        float v0 = Zs[m][lane];
        float v1 = Zs[m][lane + 32];
        float s = v0 + v1;
#pragma unroll
        for (int off = 16; off > 0; off >>= 1)
            s += __shfl_xor_sync(0xffffffffu, s, off);
        float mu = s * (1.f / 64.f);
        float d0 = v0 - mu, d1 = v1 - mu;
        float sq = __fadd_rn(__fmul_rn(d0, d0), __fmul_rn(d1, d1));
#pragma unroll
        for (int off = 16; off > 0; off >>= 1)
            sq += __shfl_xor_sync(0xffffffffu, sq, off);
        float var = sq * (1.f / 64.f);
        float rs  = rsqrtf(var + LN_EPS);
        const int p = pm0 + m;
        Z[(size_t)p * 64 + lane]      = d0 * rs * G[lane]      + Bt[lane];
        Z[(size_t)p * 64 + lane + 32] = d1 * rs * G[lane + 32] + Bt[lane + 32];
    }
}

// ---------------- codebook norms (no FMA: match sum(c*c)) --------------------
__global__ void cnorm_kernel(const float* __restrict__ CB, float* __restrict__ CN)
{
    int c = blockIdx.x * blockDim.x + threadIdx.x;
    if (c < KCODE) {
        float s = 0.f;
        for (int d = 0; d < DDIM; d++) {
            float v = CB[c * DDIM + d];
            s = __fadd_rn(s, __fmul_rn(v, v));
        }
        CN[c] = s;
    }
}

// ---------------- VQ: argmin over codes + commit-loss partials ---------------
__global__ void __launch_bounds__(256)
vq_kernel(const float* __restrict__ Z, const float* __restrict__ CB,
          const float* __restrict__ CN, int* __restrict__ Codes,
          float* __restrict__ CommitPart)
{
    __shared__ float Zt[64][66];
    __shared__ float Cs[64][66];
    __shared__ float znS[64];
    __shared__ float cvals[64];

    const int pm0 = blockIdx.x * 64;
    const int tid = threadIdx.x;
    const int tx = tid & 15, ty = tid >> 4;

#pragma unroll
    for (int i = 0; i < 16; i++) {
        int idx = tid + i * 256;
        int m = idx >> 6, d = idx & 63;
        Zt[d][m] = Z[(size_t)(pm0 + m) * 64 + d];
    }
    __syncthreads();

    if (tid < 64) {
        const int m = tid;
        float s = 0.f;
        for (int d = 0; d < 64; d++) {
            float v = Zt[d][m];
            s = __fadd_rn(s, __fmul_rn(v, v));
        }
        znS[m] = s;
    }
    __syncthreads();

    float zm[4];
#pragma unroll
    for (int i = 0; i < 4; i++) zm[i] = znS[ty * 4 + i];

    float minv[4]; int mini[4];
#pragma unroll
    for (int i = 0; i < 4; i++) { minv[i] = 3.4e38f; mini[i] = 0; }

    for (int c0 = 0; c0 < KCODE; c0 += 64) {
        __syncthreads();
#pragma unroll
        for (int i = 0; i < 16; i++) {
            int idx = tid + i * 256;
            int c = idx >> 6, d = idx & 63;
            Cs[d][c] = CB[(size_t)(c0 + c) * 64 + d];
        }
        __syncthreads();

        float dot[4][4];
#pragma unroll
        for (int i = 0; i < 4; i++)
#pragma unroll
            for (int j = 0; j < 4; j++) dot[i][j] = 0.f;
#pragma unroll
        for (int kk = 0; kk < 64; kk++) {
            float a[4], b[4];
#pragma unroll
            for (int i = 0; i < 4; i++) a[i] = Zt[kk][ty * 4 + i];
#pragma unroll
            for (int j = 0; j < 4; j++) b[j] = Cs[kk][tx * 4 + j];
#pragma unroll
            for (int i = 0; i < 4; i++)
#pragma unroll
                for (int j = 0; j < 4; j++)
                    dot[i][j] = fmaf(a[i], b[j], dot[i][j]);
        }
#pragma unroll
        for (int j = 0; j < 4; j++) {
            const int c = c0 + tx * 4 + j;
            const float cn = CN[c];
#pragma unroll
            for (int i = 0; i < 4; i++) {
                float t    = __fadd_rn(zm[i], -__fmul_rn(2.f, dot[i][j]));
                float dist = __fadd_rn(t, cn);
                if (dist < minv[i]) { minv[i] = dist; mini[i] = c; }
            }
        }
    }
    __syncthreads();

    float* redv = &Cs[0][0];
    int*   redi = reinterpret_cast<int*>(&Cs[0][0]) + 1024;
#pragma unroll
    for (int i = 0; i < 4; i++) {
        const int m = ty * 4 + i;
        redv[m * 16 + tx] = minv[i];
        redi[m * 16 + tx] = mini[i];
    }
    __syncthreads();
    if (tid < 64) {
        const int m = tid;
        float bv = redv[m * 16];
        int   bi = redi[m * 16];
        for (int t = 1; t < 16; t++) {
            float v = redv[m * 16 + t];
            int  ix = redi[m * 16 + t];
            if (v < bv || (v == bv && ix < bi)) { bv = v; bi = ix; }
        }
        Codes[pm0 + m] = bi;
        cvals[m] = bv;
    }
    __syncthreads();
    if (tid == 0) {
        float s = 0.f;
        for (int m = 0; m < 64; m++) s += cvals[m];
        CommitPart[blockIdx.x] = s;
    }
}

// ---------------- gather z_q with fused bf16 hi/lo split ----------------------
__global__ void gather_zq_split(const int* __restrict__ codes,
                                const float* __restrict__ CB,
                                bf16* __restrict__ Hi, bf16* __restrict__ Lo)
{
    int idx = blockIdx.x * blockDim.x + threadIdx.x;   // NPOS*16 float4s
    int n = idx >> 4;
    int j = idx & 15;
    float4 v = reinterpret_cast<const float4*>(CB)[codes[n] * 16 + j];
    bf16 h0 = __float2bfloat16(v.x), h1 = __float2bfloat16(v.y);
    bf16 h2 = __float2bfloat16(v.z), h3 = __float2bfloat16(v.w);
    __nv_bfloat162 hh0; hh0.x = h0; hh0.y = h1;
    __nv_bfloat162 hh1; hh1.x = h2; hh1.y = h3;
    __nv_bfloat162 ll0; ll0.x = __float2bfloat16(v.x - __bfloat162float(h0));
    ll0.y = __float2bfloat16(v.y - __bfloat162float(h1));
    __nv_bfloat162 ll1; ll1.x = __float2bfloat16(v.z - __bfloat162float(h2));
    ll1.y = __float2bfloat16(v.w - __bfloat162float(h3));
    reinterpret_cast<__nv_bfloat162*>(Hi)[n * 32 + j * 2 + 0] = hh0;
    reinterpret_cast<__nv_bfloat162*>(Hi)[n * 32 + j * 2 + 1] = hh1;
    reinterpret_cast<__nv_bfloat162*>(Lo)[n * 32 + j * 2 + 0] = ll0;
    reinterpret_cast<__nv_bfloat162*>(Lo)[n * 32 + j * 2 + 1] = ll1;
}

// ---------------- LayerNorm over E=128 + fused split --------------------------
__global__ void ln128_split(const float* __restrict__ X,
                            const float* __restrict__ G,
                            const float* __restrict__ B,
                            bf16* __restrict__ Hi, bf16* __restrict__ Lo)
{
    const int w = threadIdx.x >> 5, lane = threadIdx.x & 31;
    const int p = blockIdx.x * 8 + w;
    float v[4];
#pragma unroll
    for (int i = 0; i < 4; i++) v[i] = X[(size_t)p * 128 + lane + 32 * i];
    float s = 0.f;
#pragma unroll
    for (int i = 0; i < 4; i++) s += v[i];
#pragma unroll
    for (int off = 16; off > 0; off >>= 1)
        s += __shfl_xor_sync(0xffffffffu, s, off);
    float mu = s * (1.f / 128.f);
    float d[4];
    float sq = 0.f;
#pragma unroll
    for (int i = 0; i < 4; i++) {
        d[i] = v[i] - mu;
        sq = __fadd_rn(sq, __fmul_rn(d[i], d[i]));
    }
#pragma unroll
    for (int off = 16; off > 0; off >>= 1)
        sq += __shfl_xor_sync(0xffffffffu, sq, off);
    float var = sq * (1.f / 128.f);
    float rs  = rsqrtf(var + LN_EPS);
#pragma unroll
    for (int i = 0; i < 4; i++) {
        const int c = lane + 32 * i;
        float y = d[i] * rs * G[c] + B[c];
        bf16 h = __float2bfloat16(y);
        Hi[(size_t)p * 128 + c] = h;
        Lo[(size_t)p * 128 + c] = __float2bfloat16(y - __bfloat162float(h));
    }
}

// ---------------- mma helpers -------------------------------------------------
__device__ __forceinline__ void ldsm_x4(uint32_t* r, uint32_t addr) {
    asm volatile("ldmatrix.sync.aligned.m8n8.x4.shared.b16 {%0,%1,%2,%3}, [%4];"
                 : "=r"(r[0]), "=r"(r[1]), "=r"(r[2]), "=r"(r[3]) : "r"(addr));
}
__device__ __forceinline__ void mma16816(float* d, const uint32_t* a,
                                         uint32_t b0, uint32_t b1) {
    asm volatile(
        "mma.sync.aligned.m16n8k16.row.col.f32.bf16.bf16.f32 "
        "{%0,%1,%2,%3}, {%4,%5,%6,%7}, {%8,%9}, {%0,%1,%2,%3};"
        : "+f"(d[0]), "+f"(d[1]), "+f"(d[2]), "+f"(d[3])
        : "r"(a[0]), "r"(a[1]), "r"(a[2]), "r"(a[3]), "r"(b0), "r"(b1));
}
__device__ __forceinline__ void mma16816h(float* d, const uint32_t* a,
                                          uint32_t b0, uint32_t b1) {
    asm volatile(
        "mma.sync.aligned.m16n8k16.row.col.f32.f16.f16.f32 "
        "{%0,%1,%2,%3}, {%4,%5,%6,%7}, {%8,%9}, {%0,%1,%2,%3};"
        : "+f"(d[0]), "+f"(d[1]), "+f"(d[2]), "+f"(d[3])
        : "r"(a[0]), "r"(a[1]), "r"(a[2]), "r"(a[3]), "r"(b0), "r"(b1));
}

// ---------------- generic bf16x3 (hi/lo) tensor conv/GEMM --------------------
#define TC_SMEM 65536

template<int CIN, int KW, int COUT, bool RELU, bool WF32, bool WSPLIT>
__global__ void __launch_bounds__(256)
tconv(const bf16* __restrict__ Ahi, const bf16* __restrict__ Alo,
      const bf16* __restrict__ Whi, const bf16* __restrict__ Wlo,
      const float* __restrict__ Bias,
      float* __restrict__ Yf, bf16* __restrict__ Yhi, bf16* __restrict__ Ylo)
{
    constexpr int KTOT = CIN * KW;
    constexpr int NCH  = KTOT / 64;
    constexpr int PAD  = (KW == 3) ? 1 : 0;

    extern __shared__ char smem[];
    char* sAhi = smem;
    char* sAlo = smem + 16384;
    char* sBhi = smem + 32768;
    char* sBlo = smem + 49152;

    const int tid = threadIdx.x;
    const int pm0 = blockIdx.x * 128;
    const int nv0 = blockIdx.y * 128;

    const int wid = tid >> 5, lane = tid & 31;
    const int wm = (wid >> 1) * 32;
    const int wn = (wid & 1) * 64;
    const int lr = lane & 7, lq = lane >> 3;

    float acc[2][8][4];
#pragma unroll
    for (int mi = 0; mi < 2; mi++)
#pragma unroll
        for (int ni = 0; ni < 8; ni++)
#pragma unroll
            for (int e = 0; e < 4; e++) acc[mi][ni][e] = 0.f;

    const uint4* A4h = reinterpret_cast<const uint4*>(Ahi);
    const uint4* A4l = reinterpret_cast<const uint4*>(Alo);
    const uint4* B4h = reinterpret_cast<const uint4*>(Whi);
    const uint4* B4l = reinterpret_cast<const uint4*>(Wlo);

    const uint32_t sb = smem_to_u32(smem);
    const uint32_t aB3[3] = { sb + 0u, sb + 0u, sb + 16384u };         // hi, hi, lo
    const uint32_t bB3[3] = { sb + 32768u, sb + 49152u, sb + 32768u }; // hi, lo, hi

    for (int ch = 0; ch < NCH; ch++) {
        const int tap = (ch * 64) / CIN;
        const int ci0 = (ch * 64) % CIN;
#pragma unroll
        for (int i = 0; i < 4; i++) {
            int idx = tid + i * 256;
            int row = idx >> 3, c = idx & 7;
            int p = pm0 + row;
            bool ok = true;
            if (KW == 3) {
                int ls = (p & (LSEQ - 1)) + tap - PAD;
                ok = ((unsigned)ls < (unsigned)LSEQ);
            }
            uint4 zz = make_uint4(0u, 0u, 0u, 0u);
            size_t gi = (size_t)(p + tap - PAD) * (CIN / 8) + (ci0 / 8) + c;
            uint4 vh = ok ? A4h[gi] : zz;
            uint4 vl = ok ? A4l[gi] : zz;
            int pc = (c ^ row) & 7;
            *reinterpret_cast<uint4*>(sAhi + row * 128 + pc * 16) = vh;
            *reinterpret_cast<uint4*>(sAlo + row * 128 + pc * 16) = vl;
        }
#pragma unroll
        for (int i = 0; i < 4; i++) {
            int idx = tid + i * 256;
            int row = idx >> 3, c = idx & 7;
            size_t gi = (size_t)(nv0 + row) * (KTOT / 8) + ch * 8 + c;
            uint4 vh = B4h[gi];
            uint4 vl = B4l[gi];
            int pc = (c ^ row) & 7;
            *reinterpret_cast<uint4*>(sBhi + row * 128 + pc * 16) = vh;
            *reinterpret_cast<uint4*>(sBlo + row * 128 + pc * 16) = vl;
        }
        __syncthreads();

#pragma unroll
        for (int s = 0; s < 3; s++) {
            const uint32_t aB = aB3[s];
            const uint32_t bB = bB3[s];
#pragma unroll
            for (int k16 = 0; k16 < 4; k16++) {
                const int kc0 = k16 * 2;
                uint32_t a[2][4];
#pragma unroll
                for (int mi = 0; mi < 2; mi++) {
                    int row = wm + mi * 16 + lr + (lq & 1) * 8;
                    int kc  = kc0 + (lq >> 1);
                    int pc  = (kc ^ row) & 7;
                    ldsm_x4(a[mi], aB + row * 128 + pc * 16);
                }
                uint32_t b[4][4];
#pragma unroll
                for (int nc = 0; nc < 4; nc++) {
                    int row = wn + nc * 16 + lr + (lq >> 1) * 8;
                    int kc  = kc0 + (lq & 1);
                    int pc  = (kc ^ row) & 7;
                    ldsm_x4(b[nc], bB + row * 128 + pc * 16);
                }
#pragma unroll
                for (int mi = 0; mi < 2; mi++)
#pragma unroll
                    for (int ni = 0; ni < 8; ni++)
                        mma16816(acc[mi][ni], a[mi],
                                 b[ni >> 1][(ni & 1) * 2 + 0],
                                 b[ni >> 1][(ni & 1) * 2 + 1]);
            }
        }
        __syncthreads();
    }

    const int gid = lane >> 2, tig = lane & 3;
#pragma unroll
    for (int mi = 0; mi < 2; mi++) {
        const int m0 = pm0 + wm + mi * 16 + gid;
#pragma unroll
        for (int ni = 0; ni < 8; ni++) {
            const int n = nv0 + wn + ni * 8 + tig * 2;
            const float2 bv = *reinterpret_cast<const float2*>(Bias + n);
            float v00 = acc[mi][ni][0] + bv.x;
            float v01 = acc[mi][ni][1] + bv.y;
            float v10 = acc[mi][ni][2] + bv.x;
            float v11 = acc[mi][ni][3] + bv.y;
            if (RELU) {
                v00 = fmaxf(v00, 0.f); v01 = fmaxf(v01, 0.f);
                v10 = fmaxf(v10, 0.f); v11 = fmaxf(v11, 0.f);
            }
            if (WF32) {
                float2 a0; a0.x = v00; a0.y = v01;
                float2 a1; a1.x = v10; a1.y = v11;
                *reinterpret_cast<float2*>(Yf + (size_t)m0 * COUT + n)       = a0;
                *reinterpret_cast<float2*>(Yf + (size_t)(m0 + 8) * COUT + n) = a1;
            }
            if (WSPLIT) {
                bf16 h00 = __float2bfloat16(v00), h01 = __float2bfloat16(v01);
                bf16 h10 = __float2bfloat16(v10), h11 = __float2bfloat16(v11);
                __nv_bfloat162 hh0; hh0.x = h00; hh0.y = h01;
                __nv_bfloat162 hh1; hh1.x = h10; hh1.y = h11;
                __nv_bfloat162 ll0;
                ll0.x = __float2bfloat16(v00 - __bfloat162float(h00));
                ll0.y = __float2bfloat16(v01 - __bfloat162float(h01));
                __nv_bfloat162 ll1;
                ll1.x = __float2bfloat16(v10 - __bfloat162float(h10));
                ll1.y = __float2bfloat16(v11 - __bfloat162float(h11));
                *reinterpret_cast<__nv_bfloat162*>(Yhi + (size_t)m0 * COUT + n)       = hh0;
                *reinterpret_cast<__nv_bfloat162*>(Yhi + (size_t)(m0 + 8) * COUT + n) = hh1;
                *reinterpret_cast<__nv_bfloat162*>(Ylo + (size_t)m0 * COUT + n)       = ll0;
                *reinterpret_cast<__nv_bfloat162*>(Ylo + (size_t)(m0 + 8) * COUT + n) = ll1;
            }
        }
    }
}

// ---------------- fp16 two-split tensor conv (encoder) -----------------------
// 3 products with dual accumulators: acc1 = hh;  acc2 = h*m' + m'*h
// final = acc1 + acc2/2048  (m' = (x-h)*2048, kept in fp16 normal range)
template<int CIN, int KW, int COUT, bool WF32>
__global__ void __launch_bounds__(256)
tconvh(const half* __restrict__ Ah, const half* __restrict__ Am,
       const half* __restrict__ Wh, const half* __restrict__ Wm,
       const float* __restrict__ Bias, float* __restrict__ Yf,
       half* __restrict__ Yh, half* __restrict__ Ym)
{
    constexpr int KTOT = CIN * KW;
    constexpr int NCH  = KTOT / 64;
    constexpr int PAD  = (KW == 3) ? 1 : 0;

    extern __shared__ char smem[];
    char* sAh = smem;
    char* sAm = smem + 16384;
    char* sBh = smem + 32768;
    char* sBm = smem + 49152;

    const int tid = threadIdx.x;
    const int pm0 = blockIdx.x * 128;
    const int nv0 = blockIdx.y * 128;

    const int wid = tid >> 5, lane = tid & 31;
    const int wm = (wid >> 1) * 32;
    const int wn = (wid & 1) * 64;
    const int lr = lane & 7, lq = lane >> 3;

    float acc1[2][8][4];
    float acc2[2][8][4];
#pragma unroll
    for (int mi = 0; mi < 2; mi++)
#pragma unroll
        for (int ni = 0; ni < 8; ni++)
#pragma unroll
            for (int e = 0; e < 4; e++) { acc1[mi][ni][e] = 0.f; acc2[mi][ni][e] = 0.f; }

    const uint4* A4h = reinterpret_cast<const uint4*>(Ah);
    const uint4* A4m = reinterpret_cast<const uint4*>(Am);
    const uint4* B4h = reinterpret_cast<const uint4*>(Wh);
    const uint4* B4m = reinterpret_cast<const uint4*>(Wm);

    const uint32_t sb = smem_to_u32(smem);
    // term s: A-sel, B-sel, acc-sel
    const uint32_t aB3[3] = { sb + 0u, sb + 0u, sb + 16384u };         // h, h, m
    const uint32_t bB3[3] = { sb + 32768u, sb + 49152u, sb + 32768u }; // h, m, h

    for (int ch = 0; ch < NCH; ch++) {
        const int tap = (ch * 64) / CIN;
        const int ci0 = (ch * 64) % CIN;
#pragma unroll
        for (int i = 0; i < 4; i++) {
            int idx = tid + i * 256;
            int row = idx >> 3, c = idx & 7;
            int p = pm0 + row;
            bool ok = true;
            if (KW == 3) {
                int ls = (p & (LSEQ - 1)) + tap - PAD;
                ok = ((unsigned)ls < (unsigned)LSEQ);
            }
            uint4 zz = make_uint4(0u, 0u, 0u, 0u);
            size_t gi = (size_t)(p + tap - PAD) * (CIN / 8) + (ci0 / 8) + c;
            uint4 vh = ok ? A4h[gi] : zz;
            uint4 vm = ok ? A4m[gi] : zz;
            int pc = (c ^ row) & 7;
            *reinterpret_cast<uint4*>(sAh + row * 128 + pc * 16) = vh;
            *reinterpret_cast<uint4*>(sAm + row * 128 + pc * 16) = vm;
        }
#pragma unroll
        for (int i = 0; i < 4; i++) {
            int idx = tid + i * 256;
            int row = idx >> 3, c = idx & 7;
            size_t gi = (size_t)(nv0 + row) * (KTOT / 8) + ch * 8 + c;
            uint4 vh = B4h[gi];
            uint4 vm = B4m[gi];
            int pc = (c ^ row) & 7;
            *reinterpret_cast<uint4*>(sBh + row * 128 + pc * 16) = vh;
            *reinterpret_cast<uint4*>(sBm + row * 128 + pc * 16) = vm;
        }
        __syncthreads();

#pragma unroll
        for (int s = 0; s < 3; s++) {
            const uint32_t aB = aB3[s];
            const uint32_t bB = bB3[s];
#pragma unroll
            for (int k16 = 0; k16 < 4; k16++) {
                const int kc0 = k16 * 2;
                uint32_t a[2][4];
#pragma unroll
                for (int mi = 0; mi < 2; mi++) {
                    int row = wm + mi * 16 + lr + (lq & 1) * 8;
                    int kc  = kc0 + (lq >> 1);
                    int pc  = (kc ^ row) & 7;
                    ldsm_x4(a[mi], aB + row * 128 + pc * 16);
                }
                uint32_t b[4][4];
#pragma unroll
                for (int nc = 0; nc < 4; nc++) {
                    int row = wn + nc * 16 + lr + (lq >> 1) * 8;
                    int kc  = kc0 + (lq & 1);
                    int pc  = (kc ^ row) & 7;
                    ldsm_x4(b[nc], bB + row * 128 + pc * 16);
                }
                float (*acc)[8][4] = (s == 0) ? acc1 : acc2;
#pragma unroll
                for (int mi = 0; mi < 2; mi++)
#pragma unroll
                    for (int ni = 0; ni < 8; ni++)
                        mma16816h(acc[mi][ni], a[mi],
                                  b[ni >> 1][(ni & 1) * 2 + 0],
                                  b[ni >> 1][(ni & 1) * 2 + 1]);
            }
        }
        __syncthreads();
    }

    // epilogue: combine, bias + relu; fp32 or fp16-split stores
    const int gid = lane >> 2, tig = lane & 3;
#pragma unroll
    for (int mi = 0; mi < 2; mi++) {
        const int m0 = pm0 + wm + mi * 16 + gid;
#pragma unroll
        for (int ni = 0; ni < 8; ni++) {
            const int n = nv0 + wn + ni * 8 + tig * 2;
            const float2 bv = *reinterpret_cast<const float2*>(Bias + n);
            float v00 = fmaxf(fmaf(acc2[mi][ni][0], LO_INV, acc1[mi][ni][0]) + bv.x, 0.f);
            float v01 = fmaxf(fmaf(acc2[mi][ni][1], LO_INV, acc1[mi][ni][1]) + bv.y, 0.f);
            float v10 = fmaxf(fmaf(acc2[mi][ni][2], LO_INV, acc1[mi][ni][2]) + bv.x, 0.f);
            float v11 = fmaxf(fmaf(acc2[mi][ni][3], LO_INV, acc1[mi][ni][3]) + bv.y, 0.f);
            if (WF32) {
                float2 a0; a0.x = v00; a0.y = v01;
                float2 a1; a1.x = v10; a1.y = v11;
                *reinterpret_cast<float2*>(Yf + (size_t)m0 * COUT + n)       = a0;
                *reinterpret_cast<float2*>(Yf + (size_t)(m0 + 8) * COUT + n) = a1;
            } else {
                half h00,m00,h01,m01,h10,m10,h11,m11;
                split2h(v00,h00,m00); split2h(v01,h01,m01);
                split2h(v10,h10,m10); split2h(v11,h11,m11);
                __half2 p0, p1;
                p0.x=h00; p0.y=h01; p1.x=h10; p1.y=h11;
                *reinterpret_cast<__half2*>(Yh + (size_t)m0 * COUT + n)       = p0;
                *reinterpret_cast<__half2*>(Yh + (size_t)(m0 + 8) * COUT + n) = p1;
                p0.x=m00; p0.y=m01; p1.x=m10; p1.y=m11;
                *reinterpret_cast<__half2*>(Ym + (size_t)m0 * COUT + n)       = p0;
                *reinterpret_cast<__half2*>(Ym + (size_t)(m0 + 8) * COUT + n) = p1;
            }
        }
    }
}

// ---------------- tail: loss scalar + codes ----------------------------------
__global__ void commit_final(const float* __restrict__ Part, float* __restrict__ slot)
{
    if (threadIdx.x == 0 && blockIdx.x == 0) {
        float s = 0.f;
        for (int i = 0; i < NPOS / 64; i++) s += Part[i];
        *slot = 0.1f * s / ((float)NPOS * (float)DDIM);
    }
}

__global__ void write_codes(const int* __restrict__ codes, float* __restrict__ out)
{
    int n = blockIdx.x * blockDim.x + threadIdx.x;
    if (n < NPOS) out[n] = (float)codes[n];
}

// ---------------- launch ------------------------------------------------------
extern "C" void kernel_launch(void* const* d_in, const int* in_sizes, int n_in,
                              void* d_out, int out_size)
{
    (void)in_sizes; (void)n_in;
    const int*   x    = (const int*)  d_in[0];
    const float* tok  = (const float*)d_in[1];
    const float* ew1  = (const float*)d_in[2];
    const float* eb1  = (const float*)d_in[3];
    const float* ew2  = (const float*)d_in[4];
    const float* eb2  = (const float*)d_in[5];
    const float* ew3  = (const float*)d_in[6];
    const float* eb3  = (const float*)d_in[7];
    const float* elg  = (const float*)d_in[8];
    const float* elb  = (const float*)d_in[9];
    const float* cb   = (const float*)d_in[10];
    const float* dw1  = (const float*)d_in[11];
    const float* db1  = (const float*)d_in[12];
    const float* dw2  = (const float*)d_in[13];
    const float* db2  = (const float*)d_in[14];
    const float* dw3  = (const float*)d_in[15];
    const float* db3  = (const float*)d_in[16];
    const float* dlg  = (const float*)d_in[17];
    const float* dlb  = (const float*)d_in[18];
    const float* ow   = (const float*)d_in[19];
    const float* ob   = (const float*)d_in[20];
    float* out = (float*)d_out;

    float *emb, *h2, *z, *cn, *cp;
    int* codes;
    half *ebh,*ebm,*e1h,*e1m,*w1eh,*w1em,*w2eh,*w2em;
    bf16 *zqhi,*zqlo,*d1hi,*d1lo,*d2hi,*d2lo,*ahi,*alo;
    bf16 *w1hi,*w1lo,*w2hi,*w2lo,*w3hi,*w3lo,*bhi,*blo;
    cudaGetSymbolAddress((void**)&emb,   g_emb);
    cudaGetSymbolAddress((void**)&h2,    g_h2);
    cudaGetSymbolAddress((void**)&z,     g_z);
    cudaGetSymbolAddress((void**)&codes, g_codes);
    cudaGetSymbolAddress((void**)&cn,    g_cnorm);
    cudaGetSymbolAddress((void**)&cp,    g_commit);
    cudaGetSymbolAddress((void**)&ebh,   g_ebh);
    cudaGetSymbolAddress((void**)&ebm,   g_ebm);
    cudaGetSymbolAddress((void**)&e1h,   g_e1h);
    cudaGetSymbolAddress((void**)&e1m,   g_e1m);
    cudaGetSymbolAddress((void**)&w1eh,  g_w1eh);
    cudaGetSymbolAddress((void**)&w1em,  g_w1em);
    cudaGetSymbolAddress((void**)&w2eh,  g_w2eh);
    cudaGetSymbolAddress((void**)&w2em,  g_w2em);
    cudaGetSymbolAddress((void**)&zqhi,  g_zqhi);
    cudaGetSymbolAddress((void**)&zqlo,  g_zqlo);
    cudaGetSymbolAddress((void**)&d1hi,  g_d1hi);
    cudaGetSymbolAddress((void**)&d1lo,  g_d1lo);
    cudaGetSymbolAddress((void**)&d2hi,  g_d2hi);
    cudaGetSymbolAddress((void**)&d2lo,  g_d2lo);
    cudaGetSymbolAddress((void**)&ahi,   g_ahi);
    cudaGetSymbolAddress((void**)&alo,   g_alo);
    cudaGetSymbolAddress((void**)&w1hi,  g_w1hi);
    cudaGetSymbolAddress((void**)&w1lo,  g_w1lo);
    cudaGetSymbolAddress((void**)&w2hi,  g_w2hi);
    cudaGetSymbolAddress((void**)&w2lo,  g_w2lo);
    cudaGetSymbolAddress((void**)&w3hi,  g_w3hi);
    cudaGetSymbolAddress((void**)&w3lo,  g_w3lo);
    cudaGetSymbolAddress((void**)&bhi,   g_bhi);
    cudaGetSymbolAddress((void**)&blo,   g_blo);

    cudaFuncSetAttribute((const void*)tconvh<128, 3, 256, false>,
                         cudaFuncAttributeMaxDynamicSharedMemorySize, TC_SMEM);
    cudaFuncSetAttribute((const void*)tconvh<256, 3, 256, true>,
                         cudaFuncAttributeMaxDynamicSharedMemorySize, TC_SMEM);
    cudaFuncSetAttribute((const void*)tconv< 64, 1, 256, true,  false, true >,
                         cudaFuncAttributeMaxDynamicSharedMemorySize, TC_SMEM);
    cudaFuncSetAttribute((const void*)tconv<256, 3, 256, true,  false, true >,
                         cudaFuncAttributeMaxDynamicSharedMemorySize, TC_SMEM);
    cudaFuncSetAttribute((const void*)tconv<256, 1, 128, true,  true,  false>,
                         cudaFuncAttributeMaxDynamicSharedMemorySize, TC_SMEM);
    cudaFuncSetAttribute((const void*)tconv<128, 1, VOCAB, false, true, false>,
                         cudaFuncAttributeMaxDynamicSharedMemorySize, TC_SMEM);

    // ---- weight packing/splitting ----
    pack_split2h<128, 3, 256><<<(256*384)  / 256, 256>>>(ew1, w1eh, w1em);
    pack_split2h<256, 3, 256><<<(256*768)  / 256, 256>>>(ew2, w2eh, w2em);
    pack_split< 64, 1, 256>  <<<(256*64)   / 256, 256>>>(dw1, w1hi, w1lo);
    pack_split<256, 3, 256>  <<<(256*768)  / 256, 256>>>(dw2, w2hi, w2lo);
    pack_split<256, 1, 128>  <<<(128*256)  / 256, 256>>>(dw3, w3hi, w3lo);
    pack_split<128, 1, VOCAB><<<(VOCAB*128)/ 256, 256>>>(ow,  bhi,  blo);

    // ---- encoder (fp16 two-split tensor cores; ~2^-23 accuracy) ----
    embed_split2h<<<NPOS * 32 / 256, 256>>>(x, tok, ebh, ebm);
    tconvh<128, 3, 256, false><<<dim3(NPOS/128, 2), 256, TC_SMEM>>>(
        ebh, ebm, w1eh, w1em, eb1, nullptr, e1h, e1m);
    tconvh<256, 3, 256, true ><<<dim3(NPOS/128, 2), 256, TC_SMEM>>>(
        e1h, e1m, w2eh, w2em, eb2, h2, nullptr, nullptr);
    enc_head_ln<<<NPOS / 64, 256>>>(h2, ew3, eb3, elg, elb, z);

    // ---- vector quantization ----
    cnorm_kernel<<<1, 512>>>(cb, cn);
    vq_kernel<<<NPOS / 64, 256>>>(z, cb, cn, codes, cp);
    gather_zq_split<<<NPOS * 16 / 256, 256>>>(codes, cb, zqhi, zqlo);

    // ---- decoder (bf16x3 tensor cores, fused split epilogues) ----
    tconv< 64, 1, 256, true,  false, true ><<<dim3(NPOS/128, 2),  256, TC_SMEM>>>(
        zqhi, zqlo, w1hi, w1lo, db1, nullptr, d1hi, d1lo);
    tconv<256, 3, 256, true,  false, true ><<<dim3(NPOS/128, 2),  256, TC_SMEM>>>(
        d1hi, d1lo, w2hi, w2lo, db2, nullptr, d2hi, d2lo);
    tconv<256, 1, 128, true,  true,  false><<<dim3(NPOS/128, 1),  256, TC_SMEM>>>(
        d2hi, d2lo, w3hi, w3lo, db3, emb, nullptr, nullptr);
    ln128_split<<<NPOS / 8, 256>>>(emb, dlg, dlb, ahi, alo);

    // ---- vocab projection (bf16x3) -> d_out ----
    tconv<128, 1, VOCAB, false, true, false><<<dim3(NPOS/128, VOCAB/128), 256, TC_SMEM>>>(
        ahi, alo, bhi, blo, ob, out, nullptr, nullptr);

    // ---- tail: loss scalar + codes ----
    const long long NV = (long long)NPOS * VOCAB;   // 134217728
    if ((long long)out_size >= NV + 1)
        commit_final<<<1, 32>>>(cp, out + NV);
    if ((long long)out_size >= NV + 1 + NPOS)
        write_codes<<<NPOS / 256, 256>>>(codes, out + NV + 1);
}

// round 8
// speedup vs baseline: 2.7690x; 1.0890x over previous
#include <cuda_runtime.h>
#include <cuda_bf16.h>
#include <cuda_fp16.h>
#include <cstdint>

// Problem constants
#define NPOS   32768          // B*L = 8*4096
#define LSEQ   4096
#define EDIM   128
#define HDIM   256
#define DDIM   64
#define KCODE  512
#define VOCAB  4096
#define LN_EPS 1e-5f

typedef __nv_bfloat16 bf16;

#define LO_SCALE   2048.0f
#define LO_INV     (1.0f / 2048.0f)

// ---------------- scratch (static device globals; no allocation) -------------
__device__ float g_emb[NPOS * EDIM];    // decoder conv3 output (fp32)
__device__ float g_h2 [NPOS * HDIM];    // encoder conv2 output (fp32)
__device__ float g_z  [NPOS * DDIM];    // z_e after LN
__device__ int   g_codes[NPOS];
__device__ float g_cnorm[KCODE];
__device__ float g_commit[NPOS / 64];
// encoder fp16 two-split activations (lo scaled by 2048)
__device__ __align__(16) half g_ebh[NPOS * EDIM];
__device__ __align__(16) half g_ebm[NPOS * EDIM];
__device__ __align__(16) half g_e1h[NPOS * HDIM];
__device__ __align__(16) half g_e1m[NPOS * HDIM];
// encoder fp16 two-split packed weights
__device__ __align__(16) half g_w1eh[HDIM * EDIM * 3];
__device__ __align__(16) half g_w1em[HDIM * EDIM * 3];
__device__ __align__(16) half g_w2eh[HDIM * HDIM * 3];
__device__ __align__(16) half g_w2em[HDIM * HDIM * 3];
// decoder bf16 hi/lo split activations
__device__ __align__(16) bf16 g_zqhi[NPOS * DDIM];
__device__ __align__(16) bf16 g_zqlo[NPOS * DDIM];
__device__ __align__(16) bf16 g_d1hi[NPOS * HDIM];
__device__ __align__(16) bf16 g_d1lo[NPOS * HDIM];
__device__ __align__(16) bf16 g_d2hi[NPOS * HDIM];
__device__ __align__(16) bf16 g_d2lo[NPOS * HDIM];
__device__ __align__(16) bf16 g_ahi[NPOS * EDIM];
__device__ __align__(16) bf16 g_alo[NPOS * EDIM];
// decoder bf16 hi/lo split packed weights
__device__ __align__(16) bf16 g_w1hi[HDIM * DDIM];
__device__ __align__(16) bf16 g_w1lo[HDIM * DDIM];
__device__ __align__(16) bf16 g_w2hi[HDIM * HDIM * 3];
__device__ __align__(16) bf16 g_w2lo[HDIM * HDIM * 3];
__device__ __align__(16) bf16 g_w3hi[EDIM * HDIM];
__device__ __align__(16) bf16 g_w3lo[EDIM * HDIM];
__device__ __align__(16) bf16 g_bhi[VOCAB * EDIM];
__device__ __align__(16) bf16 g_blo[VOCAB * EDIM];

__device__ __forceinline__ uint32_t smem_to_u32(const void* smem_ptr) {
    uint32_t addr;
    asm("{ .reg .u64 tmp; cvta.to.shared.u64 tmp, %1; cvt.u32.u64 %0, tmp; }"
        : "=r"(addr) : "l"(smem_ptr));
    return addr;
}

// fp16 two-split: x = h + (m/2048); m kept in normal fp16 range
__device__ __forceinline__ void split2h(float x, half& h, half& m) {
    h = __float2half_rn(x);
    m = __float2half_rn((x - __half2float(h)) * LO_SCALE);
}

// ---------------- embedding lookup with fused fp16 two-split ------------------
__global__ void embed_split2h(const int* __restrict__ x,
                              const float* __restrict__ tok,
                              half* __restrict__ H, half* __restrict__ M)
{
    int idx = blockIdx.x * blockDim.x + threadIdx.x;   // NPOS*32 float4s
    int n = idx >> 5;
    int j = idx & 31;
    int t = x[n];
    float4 v = reinterpret_cast<const float4*>(tok)[t * 32 + j];
    half h0,m0,h1,m1,h2,m2,h3,m3;
    split2h(v.x,h0,m0); split2h(v.y,h1,m1);
    split2h(v.z,h2,m2); split2h(v.w,h3,m3);
    __half2 p;
    p.x=h0; p.y=h1; reinterpret_cast<__half2*>(H)[n*64+j*2+0]=p;
    p.x=h2; p.y=h3; reinterpret_cast<__half2*>(H)[n*64+j*2+1]=p;
    p.x=m0; p.y=m1; reinterpret_cast<__half2*>(M)[n*64+j*2+0]=p;
    p.x=m2; p.y=m3; reinterpret_cast<__half2*>(M)[n*64+j*2+1]=p;
}

// ---------------- weight pack + splits ----------------------------------------
template<int CIN, int KW, int COUT>
__global__ void pack_split(const float* __restrict__ W,
                           bf16* __restrict__ Hi, bf16* __restrict__ Lo)
{
    int idx = blockIdx.x * blockDim.x + threadIdx.x;
    if (idx >= COUT * KW * CIN) return;
    int o   = idx / (KW * CIN);
    int rem = idx - o * (KW * CIN);
    int tap = rem / CIN;
    int ci  = rem - tap * CIN;
    float w = W[(size_t)o * CIN * KW + ci * KW + tap];
    bf16 h = __float2bfloat16(w);
    Hi[idx] = h;
    Lo[idx] = __float2bfloat16(w - __bfloat162float(h));
}

template<int CIN, int KW, int COUT>
__global__ void pack_split2h(const float* __restrict__ W,
                             half* __restrict__ H, half* __restrict__ M)
{
    int idx = blockIdx.x * blockDim.x + threadIdx.x;
    if (idx >= COUT * KW * CIN) return;
    int o   = idx / (KW * CIN);
    int rem = idx - o * (KW * CIN);
    int tap = rem / CIN;
    int ci  = rem - tap * CIN;
    float w = W[(size_t)o * CIN * KW + ci * KW + tap];
    half h, m;
    split2h(w, h, m);
    H[idx] = h; M[idx] = m;
}

// ---------------- encoder head: conv1x1 (256->64) + LayerNorm(D=64) ---------
__global__ void __launch_bounds__(256)
enc_head_ln(const float* __restrict__ X, const float* __restrict__ W,
            const float* __restrict__ Bias,
            const float* __restrict__ G, const float* __restrict__ Bt,
            float* __restrict__ Z)
{
    constexpr int CIN = 256;
    __shared__ float As[32][66];
    __shared__ float Bs[32][66];
    __shared__ float Zs[64][66];

    const int pm0 = blockIdx.x * 64;
    const int tid = threadIdx.x;
    const int tx = tid & 15, ty = tid >> 4;
    const int rr = tid & 31;
    const int mrow = tid >> 5;

    float acc[4][4];
#pragma unroll
    for (int i = 0; i < 4; i++)
#pragma unroll
        for (int j = 0; j < 4; j++) acc[i][j] = 0.f;

    for (int r0 = 0; r0 < CIN; r0 += 32) {
        const int ci = r0 + rr;
#pragma unroll
        for (int i = 0; i < 8; i++) {
            const int m = mrow + i * 8;
            As[rr][m] = X[(size_t)(pm0 + m) * CIN + ci];
        }
#pragma unroll
        for (int i = 0; i < 8; i++) {
            const int n = mrow + i * 8;
            Bs[rr][n] = W[(size_t)n * CIN + ci];
        }
        __syncthreads();
#pragma unroll
        for (int kk = 0; kk < 32; kk++) {
            float a[4], b[4];
#pragma unroll
            for (int i = 0; i < 4; i++) a[i] = As[kk][ty * 4 + i];
#pragma unroll
            for (int j = 0; j < 4; j++) b[j] = Bs[kk][tx * 4 + j];
#pragma unroll
            for (int i = 0; i < 4; i++)
#pragma unroll
                for (int j = 0; j < 4; j++)
                    acc[i][j] = fmaf(a[i], b[j], acc[i][j]);
        }
        __syncthreads();
    }
#pragma unroll
    for (int i = 0; i < 4; i++)
#pragma unroll
        for (int j = 0; j < 4; j++)
            Zs[ty * 4 + i][tx * 4 + j] = acc[i][j] + Bias[tx * 4 + j];
    __syncthreads();

    const int lane = tid & 31, w = tid >> 5;
#pragma unroll
    for (int q = 0; q < 8; q++) {
        const int m = w * 8 + q;
        float v0 = Zs[m][lane];
        float v1 = Zs[m][lane + 32];
        float s = v0 + v1;
#pragma unroll
        for (int off = 16; off > 0; off >>= 1)
            s += __shfl_xor_sync(0xffffffffu, s, off);
        float mu = s * (1.f / 64.f);
        float d0 = v0 - mu, d1 = v1 - mu;
        float sq = __fadd_rn(__fmul_rn(d0, d0), __fmul_rn(d1, d1));
#pragma unroll
        for (int off = 16; off > 0; off >>= 1)
            sq += __shfl_xor_sync(0xffffffffu, sq, off);
        float var = sq * (1.f / 64.f);
        float rs  = rsqrtf(var + LN_EPS);
        const int p = pm0 + m;
        Z[(size_t)p * 64 + lane]      = d0 * rs * G[lane]      + Bt[lane];
        Z[(size_t)p * 64 + lane + 32] = d1 * rs * G[lane + 32] + Bt[lane + 32];
    }
}

// ---------------- codebook norms (no FMA: match sum(c*c)) --------------------
__global__ void cnorm_kernel(const float* __restrict__ CB, float* __restrict__ CN)
{
    int c = blockIdx.x * blockDim.x + threadIdx.x;
    if (c < KCODE) {
        float s = 0.f;
        for (int d = 0; d < DDIM; d++) {
            float v = CB[c * DDIM + d];
            s = __fadd_rn(s, __fmul_rn(v, v));
        }
        CN[c] = s;
    }
}

// ---------------- VQ: argmin over codes + commit-loss partials ---------------
__global__ void __launch_bounds__(256)
vq_kernel(const float* __restrict__ Z, const float* __restrict__ CB,
          const float* __restrict__ CN, int* __restrict__ Codes,
          float* __restrict__ CommitPart)
{
    __shared__ float Zt[64][66];
    __shared__ float Cs[64][66];
    __shared__ float znS[64];
    __shared__ float cvals[64];

    const int pm0 = blockIdx.x * 64;
    const int tid = threadIdx.x;
    const int tx = tid & 15, ty = tid >> 4;

#pragma unroll
    for (int i = 0; i < 16; i++) {
        int idx = tid + i * 256;
        int m = idx >> 6, d = idx & 63;
        Zt[d][m] = Z[(size_t)(pm0 + m) * 64 + d];
    }
    __syncthreads();

    if (tid < 64) {
        const int m = tid;
        float s = 0.f;
        for (int d = 0; d < 64; d++) {
            float v = Zt[d][m];
            s = __fadd_rn(s, __fmul_rn(v, v));
        }
        znS[m] = s;
    }
    __syncthreads();

    float zm[4];
#pragma unroll
    for (int i = 0; i < 4; i++) zm[i] = znS[ty * 4 + i];

    float minv[4]; int mini[4];
#pragma unroll
    for (int i = 0; i < 4; i++) { minv[i] = 3.4e38f; mini[i] = 0; }

    for (int c0 = 0; c0 < KCODE; c0 += 64) {
        __syncthreads();
#pragma unroll
        for (int i = 0; i < 16; i++) {
            int idx = tid + i * 256;
            int c = idx >> 6, d = idx & 63;
            Cs[d][c] = CB[(size_t)(c0 + c) * 64 + d];
        }
        __syncthreads();

        float dot[4][4];
#pragma unroll
        for (int i = 0; i < 4; i++)
#pragma unroll
            for (int j = 0; j < 4; j++) dot[i][j] = 0.f;
#pragma unroll
        for (int kk = 0; kk < 64; kk++) {
            float a[4], b[4];
#pragma unroll
            for (int i = 0; i < 4; i++) a[i] = Zt[kk][ty * 4 + i];
#pragma unroll
            for (int j = 0; j < 4; j++) b[j] = Cs[kk][tx * 4 + j];
#pragma unroll
            for (int i = 0; i < 4; i++)
#pragma unroll
                for (int j = 0; j < 4; j++)
                    dot[i][j] = fmaf(a[i], b[j], dot[i][j]);
        }
#pragma unroll
        for (int j = 0; j < 4; j++) {
            const int c = c0 + tx * 4 + j;
            const float cn = CN[c];
#pragma unroll
            for (int i = 0; i < 4; i++) {
                float t    = __fadd_rn(zm[i], -__fmul_rn(2.f, dot[i][j]));
                float dist = __fadd_rn(t, cn);
                if (dist < minv[i]) { minv[i] = dist; mini[i] = c; }
            }
        }
    }
    __syncthreads();

    float* redv = &Cs[0][0];
    int*   redi = reinterpret_cast<int*>(&Cs[0][0]) + 1024;
#pragma unroll
    for (int i = 0; i < 4; i++) {
        const int m = ty * 4 + i;
        redv[m * 16 + tx] = minv[i];
        redi[m * 16 + tx] = mini[i];
    }
    __syncthreads();
    if (tid < 64) {
        const int m = tid;
        float bv = redv[m * 16];
        int   bi = redi[m * 16];
        for (int t = 1; t < 16; t++) {
            float v = redv[m * 16 + t];
            int  ix = redi[m * 16 + t];
            if (v < bv || (v == bv && ix < bi)) { bv = v; bi = ix; }
        }
        Codes[pm0 + m] = bi;
        cvals[m] = bv;
    }
    __syncthreads();
    if (tid == 0) {
        float s = 0.f;
        for (int m = 0; m < 64; m++) s += cvals[m];
        CommitPart[blockIdx.x] = s;
    }
}

// ---------------- gather z_q with fused bf16 hi/lo split ----------------------
__global__ void gather_zq_split(const int* __restrict__ codes,
                                const float* __restrict__ CB,
                                bf16* __restrict__ Hi, bf16* __restrict__ Lo)
{
    int idx = blockIdx.x * blockDim.x + threadIdx.x;   // NPOS*16 float4s
    int n = idx >> 4;
    int j = idx & 15;
    float4 v = reinterpret_cast<const float4*>(CB)[codes[n] * 16 + j];
    bf16 h0 = __float2bfloat16(v.x), h1 = __float2bfloat16(v.y);
    bf16 h2 = __float2bfloat16(v.z), h3 = __float2bfloat16(v.w);
    __nv_bfloat162 hh0; hh0.x = h0; hh0.y = h1;
    __nv_bfloat162 hh1; hh1.x = h2; hh1.y = h3;
    __nv_bfloat162 ll0; ll0.x = __float2bfloat16(v.x - __bfloat162float(h0));
    ll0.y = __float2bfloat16(v.y - __bfloat162float(h1));
    __nv_bfloat162 ll1; ll1.x = __float2bfloat16(v.z - __bfloat162float(h2));
    ll1.y = __float2bfloat16(v.w - __bfloat162float(h3));
    reinterpret_cast<__nv_bfloat162*>(Hi)[n * 32 + j * 2 + 0] = hh0;
    reinterpret_cast<__nv_bfloat162*>(Hi)[n * 32 + j * 2 + 1] = hh1;
    reinterpret_cast<__nv_bfloat162*>(Lo)[n * 32 + j * 2 + 0] = ll0;
    reinterpret_cast<__nv_bfloat162*>(Lo)[n * 32 + j * 2 + 1] = ll1;
}

// ---------------- LayerNorm over E=128 + fused split --------------------------
__global__ void ln128_split(const float* __restrict__ X,
                            const float* __restrict__ G,
                            const float* __restrict__ B,
                            bf16* __restrict__ Hi, bf16* __restrict__ Lo)
{
    const int w = threadIdx.x >> 5, lane = threadIdx.x & 31;
    const int p = blockIdx.x * 8 + w;
    float v[4];
#pragma unroll
    for (int i = 0; i < 4; i++) v[i] = X[(size_t)p * 128 + lane + 32 * i];
    float s = 0.f;
#pragma unroll
    for (int i = 0; i < 4; i++) s += v[i];
#pragma unroll
    for (int off = 16; off > 0; off >>= 1)
        s += __shfl_xor_sync(0xffffffffu, s, off);
    float mu = s * (1.f / 128.f);
    float d[4];
    float sq = 0.f;
#pragma unroll
    for (int i = 0; i < 4; i++) {
        d[i] = v[i] - mu;
        sq = __fadd_rn(sq, __fmul_rn(d[i], d[i]));
    }
#pragma unroll
    for (int off = 16; off > 0; off >>= 1)
        sq += __shfl_xor_sync(0xffffffffu, sq, off);
    float var = sq * (1.f / 128.f);
    float rs  = rsqrtf(var + LN_EPS);
#pragma unroll
    for (int i = 0; i < 4; i++) {
        const int c = lane + 32 * i;
        float y = d[i] * rs * G[c] + B[c];
        bf16 h = __float2bfloat16(y);
        Hi[(size_t)p * 128 + c] = h;
        Lo[(size_t)p * 128 + c] = __float2bfloat16(y - __bfloat162float(h));
    }
}

// ---------------- mma helpers -------------------------------------------------
__device__ __forceinline__ void ldsm_x4(uint32_t* r, uint32_t addr) {
    asm volatile("ldmatrix.sync.aligned.m8n8.x4.shared.b16 {%0,%1,%2,%3}, [%4];"
                 : "=r"(r[0]), "=r"(r[1]), "=r"(r[2]), "=r"(r[3]) : "r"(addr));
}
__device__ __forceinline__ void mma16816(float* d, const uint32_t* a,
                                         uint32_t b0, uint32_t b1) {
    asm volatile(
        "mma.sync.aligned.m16n8k16.row.col.f32.bf16.bf16.f32 "
        "{%0,%1,%2,%3}, {%4,%5,%6,%7}, {%8,%9}, {%0,%1,%2,%3};"
        : "+f"(d[0]), "+f"(d[1]), "+f"(d[2]), "+f"(d[3])
        : "r"(a[0]), "r"(a[1]), "r"(a[2]), "r"(a[3]), "r"(b0), "r"(b1));
}
__device__ __forceinline__ void mma16816h(float* d, const uint32_t* a,
                                          uint32_t b0, uint32_t b1) {
    asm volatile(
        "mma.sync.aligned.m16n8k16.row.col.f32.f16.f16.f32 "
        "{%0,%1,%2,%3}, {%4,%5,%6,%7}, {%8,%9}, {%0,%1,%2,%3};"
        : "+f"(d[0]), "+f"(d[1]), "+f"(d[2]), "+f"(d[3])
        : "r"(a[0]), "r"(a[1]), "r"(a[2]), "r"(a[3]), "r"(b0), "r"(b1));
}

// ---------------- generic bf16x3 (hi/lo) tensor conv/GEMM --------------------
#define TC_SMEM 65536

template<int CIN, int KW, int COUT, bool RELU, bool WF32, bool WSPLIT>
__global__ void __launch_bounds__(256)
tconv(const bf16* __restrict__ Ahi, const bf16* __restrict__ Alo,
      const bf16* __restrict__ Whi, const bf16* __restrict__ Wlo,
      const float* __restrict__ Bias,
      float* __restrict__ Yf, bf16* __restrict__ Yhi, bf16* __restrict__ Ylo)
{
    constexpr int KTOT = CIN * KW;
    constexpr int NCH  = KTOT / 64;
    constexpr int PAD  = (KW == 3) ? 1 : 0;

    extern __shared__ char smem[];
    char* sAhi = smem;
    char* sAlo = smem + 16384;
    char* sBhi = smem + 32768;
    char* sBlo = smem + 49152;

    const int tid = threadIdx.x;
    const int pm0 = blockIdx.x * 128;
    const int nv0 = blockIdx.y * 128;

    const int wid = tid >> 5, lane = tid & 31;
    const int wm = (wid >> 1) * 32;
    const int wn = (wid & 1) * 64;
    const int lr = lane & 7, lq = lane >> 3;

    float acc[2][8][4];
#pragma unroll
    for (int mi = 0; mi < 2; mi++)
#pragma unroll
        for (int ni = 0; ni < 8; ni++)
#pragma unroll
            for (int e = 0; e < 4; e++) acc[mi][ni][e] = 0.f;

    const uint4* A4h = reinterpret_cast<const uint4*>(Ahi);
    const uint4* A4l = reinterpret_cast<const uint4*>(Alo);
    const uint4* B4h = reinterpret_cast<const uint4*>(Whi);
    const uint4* B4l = reinterpret_cast<const uint4*>(Wlo);

    const uint32_t sb = smem_to_u32(smem);
    const uint32_t aB3[3] = { sb + 0u, sb + 0u, sb + 16384u };         // hi, hi, lo
    const uint32_t bB3[3] = { sb + 32768u, sb + 49152u, sb + 32768u }; // hi, lo, hi

    for (int ch = 0; ch < NCH; ch++) {
        const int tap = (ch * 64) / CIN;
        const int ci0 = (ch * 64) % CIN;
#pragma unroll
        for (int i = 0; i < 4; i++) {
            int idx = tid + i * 256;
            int row = idx >> 3, c = idx & 7;
            int p = pm0 + row;
            bool ok = true;
            if (KW == 3) {
                int ls = (p & (LSEQ - 1)) + tap - PAD;
                ok = ((unsigned)ls < (unsigned)LSEQ);
            }
            uint4 zz = make_uint4(0u, 0u, 0u, 0u);
            size_t gi = (size_t)(p + tap - PAD) * (CIN / 8) + (ci0 / 8) + c;
            uint4 vh = ok ? A4h[gi] : zz;
            uint4 vl = ok ? A4l[gi] : zz;
            int pc = (c ^ row) & 7;
            *reinterpret_cast<uint4*>(sAhi + row * 128 + pc * 16) = vh;
            *reinterpret_cast<uint4*>(sAlo + row * 128 + pc * 16) = vl;
        }
#pragma unroll
        for (int i = 0; i < 4; i++) {
            int idx = tid + i * 256;
            int row = idx >> 3, c = idx & 7;
            size_t gi = (size_t)(nv0 + row) * (KTOT / 8) + ch * 8 + c;
            uint4 vh = B4h[gi];
            uint4 vl = B4l[gi];
            int pc = (c ^ row) & 7;
            *reinterpret_cast<uint4*>(sBhi + row * 128 + pc * 16) = vh;
            *reinterpret_cast<uint4*>(sBlo + row * 128 + pc * 16) = vl;
        }
        __syncthreads();

#pragma unroll
        for (int s = 0; s < 3; s++) {
            const uint32_t aB = aB3[s];
            const uint32_t bB = bB3[s];
#pragma unroll
            for (int k16 = 0; k16 < 4; k16++) {
                const int kc0 = k16 * 2;
                uint32_t a[2][4];
#pragma unroll
                for (int mi = 0; mi < 2; mi++) {
                    int row = wm + mi * 16 + lr + (lq & 1) * 8;
                    int kc  = kc0 + (lq >> 1);
                    int pc  = (kc ^ row) & 7;
                    ldsm_x4(a[mi], aB + row * 128 + pc * 16);
                }
                uint32_t b[4][4];
#pragma unroll
                for (int nc = 0; nc < 4; nc++) {
                    int row = wn + nc * 16 + lr + (lq >> 1) * 8;
                    int kc  = kc0 + (lq & 1);
                    int pc  = (kc ^ row) & 7;
                    ldsm_x4(b[nc], bB + row * 128 + pc * 16);
                }
#pragma unroll
                for (int mi = 0; mi < 2; mi++)
#pragma unroll
                    for (int ni = 0; ni < 8; ni++)
                        mma16816(acc[mi][ni], a[mi],
                                 b[ni >> 1][(ni & 1) * 2 + 0],
                                 b[ni >> 1][(ni & 1) * 2 + 1]);
            }
        }
        __syncthreads();
    }

    const int gid = lane >> 2, tig = lane & 3;
#pragma unroll
    for (int mi = 0; mi < 2; mi++) {
        const int m0 = pm0 + wm + mi * 16 + gid;
#pragma unroll
        for (int ni = 0; ni < 8; ni++) {
            const int n = nv0 + wn + ni * 8 + tig * 2;
            const float2 bv = *reinterpret_cast<const float2*>(Bias + n);
            float v00 = acc[mi][ni][0] + bv.x;
            float v01 = acc[mi][ni][1] + bv.y;
            float v10 = acc[mi][ni][2] + bv.x;
            float v11 = acc[mi][ni][3] + bv.y;
            if (RELU) {
                v00 = fmaxf(v00, 0.f); v01 = fmaxf(v01, 0.f);
                v10 = fmaxf(v10, 0.f); v11 = fmaxf(v11, 0.f);
            }
            if (WF32) {
                float2 a0; a0.x = v00; a0.y = v01;
                float2 a1; a1.x = v10; a1.y = v11;
                *reinterpret_cast<float2*>(Yf + (size_t)m0 * COUT + n)       = a0;
                *reinterpret_cast<float2*>(Yf + (size_t)(m0 + 8) * COUT + n) = a1;
            }
            if (WSPLIT) {
                bf16 h00 = __float2bfloat16(v00), h01 = __float2bfloat16(v01);
                bf16 h10 = __float2bfloat16(v10), h11 = __float2bfloat16(v11);
                __nv_bfloat162 hh0; hh0.x = h00; hh0.y = h01;
                __nv_bfloat162 hh1; hh1.x = h10; hh1.y = h11;
                __nv_bfloat162 ll0;
                ll0.x = __float2bfloat16(v00 - __bfloat162float(h00));
                ll0.y = __float2bfloat16(v01 - __bfloat162float(h01));
                __nv_bfloat162 ll1;
                ll1.x = __float2bfloat16(v10 - __bfloat162float(h10));
                ll1.y = __float2bfloat16(v11 - __bfloat162float(h11));
                *reinterpret_cast<__nv_bfloat162*>(Yhi + (size_t)m0 * COUT + n)       = hh0;
                *reinterpret_cast<__nv_bfloat162*>(Yhi + (size_t)(m0 + 8) * COUT + n) = hh1;
                *reinterpret_cast<__nv_bfloat162*>(Ylo + (size_t)m0 * COUT + n)       = ll0;
                *reinterpret_cast<__nv_bfloat162*>(Ylo + (size_t)(m0 + 8) * COUT + n) = ll1;
            }
        }
    }
}

// ---------------- fp16 two-split tensor conv (encoder) -----------------------
template<int CIN, int KW, int COUT, bool WF32>
__global__ void __launch_bounds__(256)
tconvh(const half* __restrict__ Ah, const half* __restrict__ Am,
       const half* __restrict__ Wh, const half* __restrict__ Wm,
       const float* __restrict__ Bias, float* __restrict__ Yf,
       half* __restrict__ Yh, half* __restrict__ Ym)
{
    constexpr int KTOT = CIN * KW;
    constexpr int NCH  = KTOT / 64;
    constexpr int PAD  = (KW == 3) ? 1 : 0;

    extern __shared__ char smem[];
    char* sAh = smem;
    char* sAm = smem + 16384;
    char* sBh = smem + 32768;
    char* sBm = smem + 49152;

    const int tid = threadIdx.x;
    const int pm0 = blockIdx.x * 128;
    const int nv0 = blockIdx.y * 128;

    const int wid = tid >> 5, lane = tid & 31;
    const int wm = (wid >> 1) * 32;
    const int wn = (wid & 1) * 64;
    const int lr = lane & 7, lq = lane >> 3;

    float acc1[2][8][4];
    float acc2[2][8][4];
#pragma unroll
    for (int mi = 0; mi < 2; mi++)
#pragma unroll
        for (int ni = 0; ni < 8; ni++)
#pragma unroll
            for (int e = 0; e < 4; e++) { acc1[mi][ni][e] = 0.f; acc2[mi][ni][e] = 0.f; }

    const uint4* A4h = reinterpret_cast<const uint4*>(Ah);
    const uint4* A4m = reinterpret_cast<const uint4*>(Am);
    const uint4* B4h = reinterpret_cast<const uint4*>(Wh);
    const uint4* B4m = reinterpret_cast<const uint4*>(Wm);

    const uint32_t sb = smem_to_u32(smem);
    const uint32_t aB3[3] = { sb + 0u, sb + 0u, sb + 16384u };         // h, h, m
    const uint32_t bB3[3] = { sb + 32768u, sb + 49152u, sb + 32768u }; // h, m, h

    for (int ch = 0; ch < NCH; ch++) {
        const int tap = (ch * 64) / CIN;
        const int ci0 = (ch * 64) % CIN;
#pragma unroll
        for (int i = 0; i < 4; i++) {
            int idx = tid + i * 256;
            int row = idx >> 3, c = idx & 7;
            int p = pm0 + row;
            bool ok = true;
            if (KW == 3) {
                int ls = (p & (LSEQ - 1)) + tap - PAD;
                ok = ((unsigned)ls < (unsigned)LSEQ);
            }
            uint4 zz = make_uint4(0u, 0u, 0u, 0u);
            size_t gi = (size_t)(p + tap - PAD) * (CIN / 8) + (ci0 / 8) + c;
            uint4 vh = ok ? A4h[gi] : zz;
            uint4 vm = ok ? A4m[gi] : zz;
            int pc = (c ^ row) & 7;
            *reinterpret_cast<uint4*>(sAh + row * 128 + pc * 16) = vh;
            *reinterpret_cast<uint4*>(sAm + row * 128 + pc * 16) = vm;
        }
#pragma unroll
        for (int i = 0; i < 4; i++) {
            int idx = tid + i * 256;
            int row = idx >> 3, c = idx & 7;
            size_t gi = (size_t)(nv0 + row) * (KTOT / 8) + ch * 8 + c;
            uint4 vh = B4h[gi];
            uint4 vm = B4m[gi];
            int pc = (c ^ row) & 7;
            *reinterpret_cast<uint4*>(sBh + row * 128 + pc * 16) = vh;
            *reinterpret_cast<uint4*>(sBm + row * 128 + pc * 16) = vm;
        }
        __syncthreads();

#pragma unroll
        for (int s = 0; s < 3; s++) {
            const uint32_t aB = aB3[s];
            const uint32_t bB = bB3[s];
#pragma unroll
            for (int k16 = 0; k16 < 4; k16++) {
                const int kc0 = k16 * 2;
                uint32_t a[2][4];
#pragma unroll
                for (int mi = 0; mi < 2; mi++) {
                    int row = wm + mi * 16 + lr + (lq & 1) * 8;
                    int kc  = kc0 + (lq >> 1);
                    int pc  = (kc ^ row) & 7;
                    ldsm_x4(a[mi], aB + row * 128 + pc * 16);
                }
                uint32_t b[4][4];
#pragma unroll
                for (int nc = 0; nc < 4; nc++) {
                    int row = wn + nc * 16 + lr + (lq >> 1) * 8;
                    int kc  = kc0 + (lq & 1);
                    int pc  = (kc ^ row) & 7;
                    ldsm_x4(b[nc], bB + row * 128 + pc * 16);
                }
                float (*acc)[8][4] = (s == 0) ? acc1 : acc2;
#pragma unroll
                for (int mi = 0; mi < 2; mi++)
#pragma unroll
                    for (int ni = 0; ni < 8; ni++)
                        mma16816h(acc[mi][ni], a[mi],
                                  b[ni >> 1][(ni & 1) * 2 + 0],
                                  b[ni >> 1][(ni & 1) * 2 + 1]);
            }
        }
        __syncthreads();
    }

    const int gid = lane >> 2, tig = lane & 3;
#pragma unroll
    for (int mi = 0; mi < 2; mi++) {
        const int m0 = pm0 + wm + mi * 16 + gid;
#pragma unroll
        for (int ni = 0; ni < 8; ni++) {
            const int n = nv0 + wn + ni * 8 + tig * 2;
            const float2 bv = *reinterpret_cast<const float2*>(Bias + n);
            float v00 = fmaxf(fmaf(acc2[mi][ni][0], LO_INV, acc1[mi][ni][0]) + bv.x, 0.f);
            float v01 = fmaxf(fmaf(acc2[mi][ni][1], LO_INV, acc1[mi][ni][1]) + bv.y, 0.f);
            float v10 = fmaxf(fmaf(acc2[mi][ni][2], LO_INV, acc1[mi][ni][2]) + bv.x, 0.f);
            float v11 = fmaxf(fmaf(acc2[mi][ni][3], LO_INV, acc1[mi][ni][3]) + bv.y, 0.f);
            if (WF32) {
                float2 a0; a0.x = v00; a0.y = v01;
                float2 a1; a1.x = v10; a1.y = v11;
                *reinterpret_cast<float2*>(Yf + (size_t)m0 * COUT + n)       = a0;
                *reinterpret_cast<float2*>(Yf + (size_t)(m0 + 8) * COUT + n) = a1;
            } else {
                half h00,m00,h01,m01,h10,m10,h11,m11;
                split2h(v00,h00,m00); split2h(v01,h01,m01);
                split2h(v10,h10,m10); split2h(v11,h11,m11);
                __half2 p0, p1;
                p0.x=h00; p0.y=h01; p1.x=h10; p1.y=h11;
                *reinterpret_cast<__half2*>(Yh + (size_t)m0 * COUT + n)       = p0;
                *reinterpret_cast<__half2*>(Yh + (size_t)(m0 + 8) * COUT + n) = p1;
                p0.x=m00; p0.y=m01; p1.x=m10; p1.y=m11;
                *reinterpret_cast<__half2*>(Ym + (size_t)m0 * COUT + n)       = p0;
                *reinterpret_cast<__half2*>(Ym + (size_t)(m0 + 8) * COUT + n) = p1;
            }
        }
    }
}

// ---------------- wide full-K-resident bf16x3 logits GEMM --------------------
// CTA: 128 pos x 256 vocab; warp tile 32x128; all K=128 resident in smem.
// smem rows are 256B (16 chunks), swizzle pc = (c&8) | ((c^row)&7).
#define LGW_SMEM 196608

__global__ void __launch_bounds__(256, 1)
logits_wide(const bf16* __restrict__ Ahi, const bf16* __restrict__ Alo,
            const bf16* __restrict__ Bhi, const bf16* __restrict__ Blo,
            const float* __restrict__ Bias, float* __restrict__ Out)
{
    extern __shared__ char smem[];
    char* sAhi = smem;              // 128 rows x 256B = 32768
    char* sAlo = smem + 32768;
    char* sBhi = smem + 65536;      // 256 rows x 256B = 65536
    char* sBlo = smem + 131072;

    const int tid = threadIdx.x;
    const int pm0 = blockIdx.x * 128;
    const int nv0 = blockIdx.y * 256;

    {
        const uint4* A4h = reinterpret_cast<const uint4*>(Ahi);
        const uint4* A4l = reinterpret_cast<const uint4*>(Alo);
#pragma unroll
        for (int i = 0; i < 8; i++) {
            int idx = tid + i * 256;          // 0..2047
            int row = idx >> 4, c = idx & 15;
            uint4 vh = A4h[(size_t)(pm0 + row) * 16 + c];
            uint4 vl = A4l[(size_t)(pm0 + row) * 16 + c];
            int pc = (c & 8) | ((c ^ row) & 7);
            *reinterpret_cast<uint4*>(sAhi + row * 256 + pc * 16) = vh;
            *reinterpret_cast<uint4*>(sAlo + row * 256 + pc * 16) = vl;
        }
        const uint4* B4h = reinterpret_cast<const uint4*>(Bhi);
        const uint4* B4l = reinterpret_cast<const uint4*>(Blo);
#pragma unroll
        for (int i = 0; i < 16; i++) {
            int idx = tid + i * 256;          // 0..4095
            int row = idx >> 4, c = idx & 15;
            uint4 vh = B4h[(size_t)(nv0 + row) * 16 + c];
            uint4 vl = B4l[(size_t)(nv0 + row) * 16 + c];
            int pc = (c & 8) | ((c ^ row) & 7);
            *reinterpret_cast<uint4*>(sBhi + row * 256 + pc * 16) = vh;
            *reinterpret_cast<uint4*>(sBlo + row * 256 + pc * 16) = vl;
        }
    }
    __syncthreads();

    const int wid = tid >> 5, lane = tid & 31;
    const int wm = (wid >> 1) * 32;       // 0,32,64,96
    const int wn = (wid & 1) * 128;       // 0,128
    const int lr = lane & 7, lq = lane >> 3;

    float acc[2][16][4];
#pragma unroll
    for (int mi = 0; mi < 2; mi++)
#pragma unroll
        for (int ni = 0; ni < 16; ni++)
#pragma unroll
            for (int e = 0; e < 4; e++) acc[mi][ni][e] = 0.f;

    const uint32_t sb = smem_to_u32(smem);
    const uint32_t aB3[3] = { sb, sb, sb + 32768u };                 // hi, hi, lo
    const uint32_t bB3[3] = { sb + 65536u, sb + 131072u, sb + 65536u }; // hi, lo, hi

#pragma unroll
    for (int s = 0; s < 3; s++) {
        const uint32_t aB = aB3[s];
        const uint32_t bB = bB3[s];
#pragma unroll
        for (int k16 = 0; k16 < 8; k16++) {
            const int kc0 = k16 * 2;
            uint32_t a[2][4];
#pragma unroll
            for (int mi = 0; mi < 2; mi++) {
                int row = wm + mi * 16 + lr + (lq & 1) * 8;
                int kc  = kc0 + (lq >> 1);
                int pc  = (kc & 8) | ((kc ^ row) & 7);
                ldsm_x4(a[mi], aB + row * 256 + pc * 16);
            }
#pragma unroll
            for (int nc = 0; nc < 8; nc++) {
                uint32_t b[4];
                int row = wn + nc * 16 + lr + (lq >> 1) * 8;
                int kc  = kc0 + (lq & 1);
                int pc  = (kc & 8) | ((kc ^ row) & 7);
                ldsm_x4(b, bB + row * 256 + pc * 16);
                mma16816(acc[0][nc * 2 + 0], a[0], b[0], b[1]);
                mma16816(acc[0][nc * 2 + 1], a[0], b[2], b[3]);
                mma16816(acc[1][nc * 2 + 0], a[1], b[0], b[1]);
                mma16816(acc[1][nc * 2 + 1], a[1], b[2], b[3]);
            }
        }
    }

    const int gid = lane >> 2, tig = lane & 3;
#pragma unroll
    for (int mi = 0; mi < 2; mi++) {
        const int m0 = pm0 + wm + mi * 16 + gid;
#pragma unroll
        for (int ni = 0; ni < 16; ni++) {
            const int n = nv0 + wn + ni * 8 + tig * 2;
            const float2 bv = *reinterpret_cast<const float2*>(Bias + n);
            float2 v0, v1;
            v0.x = acc[mi][ni][0] + bv.x;  v0.y = acc[mi][ni][1] + bv.y;
            v1.x = acc[mi][ni][2] + bv.x;  v1.y = acc[mi][ni][3] + bv.y;
            *reinterpret_cast<float2*>(Out + (size_t)m0 * VOCAB + n)       = v0;
            *reinterpret_cast<float2*>(Out + (size_t)(m0 + 8) * VOCAB + n) = v1;
        }
    }
}

// ---------------- tail: loss scalar + codes ----------------------------------
__global__ void commit_final(const float* __restrict__ Part, float* __restrict__ slot)
{
    if (threadIdx.x == 0 && blockIdx.x == 0) {
        float s = 0.f;
        for (int i = 0; i < NPOS / 64; i++) s += Part[i];
        *slot = 0.1f * s / ((float)NPOS * (float)DDIM);
    }
}

__global__ void write_codes(const int* __restrict__ codes, float* __restrict__ out)
{
    int n = blockIdx.x * blockDim.x + threadIdx.x;
    if (n < NPOS) out[n] = (float)codes[n];
}

// ---------------- launch ------------------------------------------------------
extern "C" void kernel_launch(void* const* d_in, const int* in_sizes, int n_in,
                              void* d_out, int out_size)
{
    (void)in_sizes; (void)n_in;
    const int*   x    = (const int*)  d_in[0];
    const float* tok  = (const float*)d_in[1];
    const float* ew1  = (const float*)d_in[2];
    const float* eb1  = (const float*)d_in[3];
    const float* ew2  = (const float*)d_in[4];
    const float* eb2  = (const float*)d_in[5];
    const float* ew3  = (const float*)d_in[6];
    const float* eb3  = (const float*)d_in[7];
    const float* elg  = (const float*)d_in[8];
    const float* elb  = (const float*)d_in[9];
    const float* cb   = (const float*)d_in[10];
    const float* dw1  = (const float*)d_in[11];
    const float* db1  = (const float*)d_in[12];
    const float* dw2  = (const float*)d_in[13];
    const float* db2  = (const float*)d_in[14];
    const float* dw3  = (const float*)d_in[15];
    const float* db3  = (const float*)d_in[16];
    const float* dlg  = (const float*)d_in[17];
    const float* dlb  = (const float*)d_in[18];
    const float* ow   = (const float*)d_in[19];
    const float* ob   = (const float*)d_in[20];
    float* out = (float*)d_out;

    float *emb, *h2, *z, *cn, *cp;
    int* codes;
    half *ebh,*ebm,*e1h,*e1m,*w1eh,*w1em,*w2eh,*w2em;
    bf16 *zqhi,*zqlo,*d1hi,*d1lo,*d2hi,*d2lo,*ahi,*alo;
    bf16 *w1hi,*w1lo,*w2hi,*w2lo,*w3hi,*w3lo,*bhi,*blo;
    cudaGetSymbolAddress((void**)&emb,   g_emb);
    cudaGetSymbolAddress((void**)&h2,    g_h2);
    cudaGetSymbolAddress((void**)&z,     g_z);
    cudaGetSymbolAddress((void**)&codes, g_codes);
    cudaGetSymbolAddress((void**)&cn,    g_cnorm);
    cudaGetSymbolAddress((void**)&cp,    g_commit);
    cudaGetSymbolAddress((void**)&ebh,   g_ebh);
    cudaGetSymbolAddress((void**)&ebm,   g_ebm);
    cudaGetSymbolAddress((void**)&e1h,   g_e1h);
    cudaGetSymbolAddress((void**)&e1m,   g_e1m);
    cudaGetSymbolAddress((void**)&w1eh,  g_w1eh);
    cudaGetSymbolAddress((void**)&w1em,  g_w1em);
    cudaGetSymbolAddress((void**)&w2eh,  g_w2eh);
    cudaGetSymbolAddress((void**)&w2em,  g_w2em);
    cudaGetSymbolAddress((void**)&zqhi,  g_zqhi);
    cudaGetSymbolAddress((void**)&zqlo,  g_zqlo);
    cudaGetSymbolAddress((void**)&d1hi,  g_d1hi);
    cudaGetSymbolAddress((void**)&d1lo,  g_d1lo);
    cudaGetSymbolAddress((void**)&d2hi,  g_d2hi);
    cudaGetSymbolAddress((void**)&d2lo,  g_d2lo);
    cudaGetSymbolAddress((void**)&ahi,   g_ahi);
    cudaGetSymbolAddress((void**)&alo,   g_alo);
    cudaGetSymbolAddress((void**)&w1hi,  g_w1hi);
    cudaGetSymbolAddress((void**)&w1lo,  g_w1lo);
    cudaGetSymbolAddress((void**)&w2hi,  g_w2hi);
    cudaGetSymbolAddress((void**)&w2lo,  g_w2lo);
    cudaGetSymbolAddress((void**)&w3hi,  g_w3hi);
    cudaGetSymbolAddress((void**)&w3lo,  g_w3lo);
    cudaGetSymbolAddress((void**)&bhi,   g_bhi);
    cudaGetSymbolAddress((void**)&blo,   g_blo);

    cudaFuncSetAttribute((const void*)tconvh<128, 3, 256, false>,
                         cudaFuncAttributeMaxDynamicSharedMemorySize, TC_SMEM);
    cudaFuncSetAttribute((const void*)tconvh<256, 3, 256, true>,
                         cudaFuncAttributeMaxDynamicSharedMemorySize, TC_SMEM);
    cudaFuncSetAttribute((const void*)tconv< 64, 1, 256, true,  false, true >,
                         cudaFuncAttributeMaxDynamicSharedMemorySize, TC_SMEM);
    cudaFuncSetAttribute((const void*)tconv<256, 3, 256, true,  false, true >,
                         cudaFuncAttributeMaxDynamicSharedMemorySize, TC_SMEM);
    cudaFuncSetAttribute((const void*)tconv<256, 1, 128, true,  true,  false>,
                         cudaFuncAttributeMaxDynamicSharedMemorySize, TC_SMEM);
    cudaFuncSetAttribute((const void*)logits_wide,
                         cudaFuncAttributeMaxDynamicSharedMemorySize, LGW_SMEM);

    // ---- encoder (fp16 two-split tensor cores) ----
    pack_split2h<128, 3, 256><<<(256*384)  / 256, 256>>>(ew1, w1eh, w1em);
    pack_split2h<256, 3, 256><<<(256*768)  / 256, 256>>>(ew2, w2eh, w2em);
    embed_split2h<<<NPOS * 32 / 256, 256>>>(x, tok, ebh, ebm);
    tconvh<128, 3, 256, false><<<dim3(NPOS/128, 2), 256, TC_SMEM>>>(
        ebh, ebm, w1eh, w1em, eb1, nullptr, e1h, e1m);
    tconvh<256, 3, 256, true ><<<dim3(NPOS/128, 2), 256, TC_SMEM>>>(
        e1h, e1m, w2eh, w2em, eb2, h2, nullptr, nullptr);
    enc_head_ln<<<NPOS / 64, 256>>>(h2, ew3, eb3, elg, elb, z);

    // ---- vector quantization ----
    cnorm_kernel<<<1, 512>>>(cb, cn);
    vq_kernel<<<NPOS / 64, 256>>>(z, cb, cn, codes, cp);
    gather_zq_split<<<NPOS * 16 / 256, 256>>>(codes, cb, zqhi, zqlo);

    // ---- decoder weight packs + decoder (bf16x3 tensor cores) ----
    pack_split< 64, 1, 256>  <<<(256*64)   / 256, 256>>>(dw1, w1hi, w1lo);
    pack_split<256, 3, 256>  <<<(256*768)  / 256, 256>>>(dw2, w2hi, w2lo);
    pack_split<256, 1, 128>  <<<(128*256)  / 256, 256>>>(dw3, w3hi, w3lo);
    pack_split<128, 1, VOCAB><<<(VOCAB*128)/ 256, 256>>>(ow,  bhi,  blo);

    tconv< 64, 1, 256, true,  false, true ><<<dim3(NPOS/128, 2),  256, TC_SMEM>>>(
        zqhi, zqlo, w1hi, w1lo, db1, nullptr, d1hi, d1lo);
    tconv<256, 3, 256, true,  false, true ><<<dim3(NPOS/128, 2),  256, TC_SMEM>>>(
        d1hi, d1lo, w2hi, w2lo, db2, nullptr, d2hi, d2lo);
    tconv<256, 1, 128, true,  true,  false><<<dim3(NPOS/128, 1),  256, TC_SMEM>>>(
        d2hi, d2lo, w3hi, w3lo, db3, emb, nullptr, nullptr);
    ln128_split<<<NPOS / 8, 256>>>(emb, dlg, dlb, ahi, alo);

    // ---- vocab projection (wide full-K bf16x3) -> d_out ----
    logits_wide<<<dim3(NPOS/128, VOCAB/256), 256, LGW_SMEM>>>(
        ahi, alo, bhi, blo, ob, out);

    // ---- tail: loss scalar + codes ----
    const long long NV = (long long)NPOS * VOCAB;   // 134217728
    if ((long long)out_size >= NV + 1)
        commit_final<<<1, 32>>>(cp, out + NV);
    if ((long long)out_size >= NV + 1 + NPOS)
        write_codes<<<NPOS / 256, 256>>>(codes, out + NV + 1);
}

// round 9
// speedup vs baseline: 2.9949x; 1.0816x over previous
#include <cuda_runtime.h>
#include <cuda_bf16.h>
#include <cuda_fp16.h>
#include <cstdint>

// Problem constants
#define NPOS   32768          // B*L = 8*4096
#define LSEQ   4096
#define EDIM   128
#define HDIM   256
#define DDIM   64
#define KCODE  512
#define VOCAB  4096
#define LN_EPS 1e-5f

typedef __nv_bfloat16 bf16;

#define LO_SCALE   2048.0f
#define LO_INV     (1.0f / 2048.0f)

// ---------------- scratch (static device globals; no allocation) -------------
__device__ float g_emb[NPOS * EDIM];    // decoder conv3 output (fp32)
__device__ float g_h2 [NPOS * HDIM];    // encoder conv2 output (fp32)
__device__ float g_z  [NPOS * DDIM];    // z_e after LN
__device__ int   g_codes[NPOS];
__device__ float g_cnorm[KCODE];
__device__ float g_commit[NPOS / 64];
// encoder fp16 two-split activations (lo scaled by 2048)
__device__ __align__(16) half g_ebh[NPOS * EDIM];
__device__ __align__(16) half g_ebm[NPOS * EDIM];
__device__ __align__(16) half g_e1h[NPOS * HDIM];
__device__ __align__(16) half g_e1m[NPOS * HDIM];
// encoder fp16 two-split packed weights
__device__ __align__(16) half g_w1eh[HDIM * EDIM * 3];
__device__ __align__(16) half g_w1em[HDIM * EDIM * 3];
__device__ __align__(16) half g_w2eh[HDIM * HDIM * 3];
__device__ __align__(16) half g_w2em[HDIM * HDIM * 3];
// decoder bf16 hi/lo split activations
__device__ __align__(16) bf16 g_zqhi[NPOS * DDIM];
__device__ __align__(16) bf16 g_zqlo[NPOS * DDIM];
__device__ __align__(16) bf16 g_d1hi[NPOS * HDIM];
__device__ __align__(16) bf16 g_d1lo[NPOS * HDIM];
__device__ __align__(16) bf16 g_d2hi[NPOS * HDIM];
__device__ __align__(16) bf16 g_d2lo[NPOS * HDIM];
__device__ __align__(16) bf16 g_ahi[NPOS * EDIM];
__device__ __align__(16) bf16 g_alo[NPOS * EDIM];
// decoder bf16 hi/lo split packed weights
__device__ __align__(16) bf16 g_w1hi[HDIM * DDIM];
__device__ __align__(16) bf16 g_w1lo[HDIM * DDIM];
__device__ __align__(16) bf16 g_w2hi[HDIM * HDIM * 3];
__device__ __align__(16) bf16 g_w2lo[HDIM * HDIM * 3];
__device__ __align__(16) bf16 g_w3hi[EDIM * HDIM];
__device__ __align__(16) bf16 g_w3lo[EDIM * HDIM];
__device__ __align__(16) bf16 g_bhi[VOCAB * EDIM];
__device__ __align__(16) bf16 g_blo[VOCAB * EDIM];

__device__ __forceinline__ uint32_t smem_to_u32(const void* smem_ptr) {
    uint32_t addr;
    asm("{ .reg .u64 tmp; cvta.to.shared.u64 tmp, %1; cvt.u32.u64 %0, tmp; }"
        : "=r"(addr) : "l"(smem_ptr));
    return addr;
}

__device__ __forceinline__ void cp_async16(uint32_t saddr, const void* gptr, int src_bytes) {
    asm volatile("cp.async.cg.shared.global [%0], [%1], 16, %2;"
                 :: "r"(saddr), "l"(gptr), "r"(src_bytes));
}

// fp16 two-split: x = h + (m/2048); m kept in normal fp16 range
__device__ __forceinline__ void split2h(float x, half& h, half& m) {
    h = __float2half_rn(x);
    m = __float2half_rn((x - __half2float(h)) * LO_SCALE);
}

// ---------------- embedding lookup with fused fp16 two-split ------------------
__global__ void embed_split2h(const int* __restrict__ x,
                              const float* __restrict__ tok,
                              half* __restrict__ H, half* __restrict__ M)
{
    int idx = blockIdx.x * blockDim.x + threadIdx.x;   // NPOS*32 float4s
    int n = idx >> 5;
    int j = idx & 31;
    int t = x[n];
    float4 v = reinterpret_cast<const float4*>(tok)[t * 32 + j];
    half h0,m0,h1,m1,h2,m2,h3,m3;
    split2h(v.x,h0,m0); split2h(v.y,h1,m1);
    split2h(v.z,h2,m2); split2h(v.w,h3,m3);
    __half2 p;
    p.x=h0; p.y=h1; reinterpret_cast<__half2*>(H)[n*64+j*2+0]=p;
    p.x=h2; p.y=h3; reinterpret_cast<__half2*>(H)[n*64+j*2+1]=p;
    p.x=m0; p.y=m1; reinterpret_cast<__half2*>(M)[n*64+j*2+0]=p;
    p.x=m2; p.y=m3; reinterpret_cast<__half2*>(M)[n*64+j*2+1]=p;
}

// ---------------- weight pack + splits ----------------------------------------
template<int CIN, int KW, int COUT>
__global__ void pack_split(const float* __restrict__ W,
                           bf16* __restrict__ Hi, bf16* __restrict__ Lo)
{
    int idx = blockIdx.x * blockDim.x + threadIdx.x;
    if (idx >= COUT * KW * CIN) return;
    int o   = idx / (KW * CIN);
    int rem = idx - o * (KW * CIN);
    int tap = rem / CIN;
    int ci  = rem - tap * CIN;
    float w = W[(size_t)o * CIN * KW + ci * KW + tap];
    bf16 h = __float2bfloat16(w);
    Hi[idx] = h;
    Lo[idx] = __float2bfloat16(w - __bfloat162float(h));
}

template<int CIN, int KW, int COUT>
__global__ void pack_split2h(const float* __restrict__ W,
                             half* __restrict__ H, half* __restrict__ M)
{
    int idx = blockIdx.x * blockDim.x + threadIdx.x;
    if (idx >= COUT * KW * CIN) return;
    int o   = idx / (KW * CIN);
    int rem = idx - o * (KW * CIN);
    int tap = rem / CIN;
    int ci  = rem - tap * CIN;
    float w = W[(size_t)o * CIN * KW + ci * KW + tap];
    half h, m;
    split2h(w, h, m);
    H[idx] = h; M[idx] = m;
}

// ---------------- encoder head: conv1x1 (256->64) + LayerNorm(D=64) ---------
__global__ void __launch_bounds__(256)
enc_head_ln(const float* __restrict__ X, const float* __restrict__ W,
            const float* __restrict__ Bias,
            const float* __restrict__ G, const float* __restrict__ Bt,
            float* __restrict__ Z)
{
    constexpr int CIN = 256;
    __shared__ float As[32][66];
    __shared__ float Bs[32][66];
    __shared__ float Zs[64][66];

    const int pm0 = blockIdx.x * 64;
    const int tid = threadIdx.x;
    const int tx = tid & 15, ty = tid >> 4;
    const int rr = tid & 31;
    const int mrow = tid >> 5;

    float acc[4][4];
#pragma unroll
    for (int i = 0; i < 4; i++)
#pragma unroll
        for (int j = 0; j < 4; j++) acc[i][j] = 0.f;

    for (int r0 = 0; r0 < CIN; r0 += 32) {
        const int ci = r0 + rr;
#pragma unroll
        for (int i = 0; i < 8; i++) {
            const int m = mrow + i * 8;
            As[rr][m] = X[(size_t)(pm0 + m) * CIN + ci];
        }
#pragma unroll
        for (int i = 0; i < 8; i++) {
            const int n = mrow + i * 8;
            Bs[rr][n] = W[(size_t)n * CIN + ci];
        }
        __syncthreads();
#pragma unroll
        for (int kk = 0; kk < 32; kk++) {
            float a[4], b[4];
#pragma unroll
            for (int i = 0; i < 4; i++) a[i] = As[kk][ty * 4 + i];
#pragma unroll
            for (int j = 0; j < 4; j++) b[j] = Bs[kk][tx * 4 + j];
#pragma unroll
            for (int i = 0; i < 4; i++)
#pragma unroll
                for (int j = 0; j < 4; j++)
                    acc[i][j] = fmaf(a[i], b[j], acc[i][j]);
        }
        __syncthreads();
    }
#pragma unroll
    for (int i = 0; i < 4; i++)
#pragma unroll
        for (int j = 0; j < 4; j++)
            Zs[ty * 4 + i][tx * 4 + j] = acc[i][j] + Bias[tx * 4 + j];
    __syncthreads();

    const int lane = tid & 31, w = tid >> 5;
#pragma unroll
    for (int q = 0; q < 8; q++) {
        const int m = w * 8 + q;
        float v0 = Zs[m][lane];
        float v1 = Zs[m][lane + 32];
        float s = v0 + v1;
#pragma unroll
        for (int off = 16; off > 0; off >>= 1)
            s += __shfl_xor_sync(0xffffffffu, s, off);
        float mu = s * (1.f / 64.f);
        float d0 = v0 - mu, d1 = v1 - mu;
        float sq = __fadd_rn(__fmul_rn(d0, d0), __fmul_rn(d1, d1));
#pragma unroll
        for (int off = 16; off > 0; off >>= 1)
            sq += __shfl_xor_sync(0xffffffffu, sq, off);
        float var = sq * (1.f / 64.f);
        float rs  = rsqrtf(var + LN_EPS);
        const int p = pm0 + m;
        Z[(size_t)p * 64 + lane]      = d0 * rs * G[lane]      + Bt[lane];
        Z[(size_t)p * 64 + lane + 32] = d1 * rs * G[lane + 32] + Bt[lane + 32];
    }
}

// ---------------- codebook norms (no FMA: match sum(c*c)) --------------------
__global__ void cnorm_kernel(const float* __restrict__ CB, float* __restrict__ CN)
{
    int c = blockIdx.x * blockDim.x + threadIdx.x;
    if (c < KCODE) {
        float s = 0.f;
        for (int d = 0; d < DDIM; d++) {
            float v = CB[c * DDIM + d];
            s = __fadd_rn(s, __fmul_rn(v, v));
        }
        CN[c] = s;
    }
}

// ---------------- VQ: argmin over codes + commit-loss partials ---------------
__global__ void __launch_bounds__(256)
vq_kernel(const float* __restrict__ Z, const float* __restrict__ CB,
          const float* __restrict__ CN, int* __restrict__ Codes,
          float* __restrict__ CommitPart)
{
    __shared__ float Zt[64][66];
    __shared__ float Cs[64][66];
    __shared__ float znS[64];
    __shared__ float cvals[64];

    const int pm0 = blockIdx.x * 64;
    const int tid = threadIdx.x;
    const int tx = tid & 15, ty = tid >> 4;

#pragma unroll
    for (int i = 0; i < 16; i++) {
        int idx = tid + i * 256;
        int m = idx >> 6, d = idx & 63;
        Zt[d][m] = Z[(size_t)(pm0 + m) * 64 + d];
    }
    __syncthreads();

    if (tid < 64) {
        const int m = tid;
        float s = 0.f;
        for (int d = 0; d < 64; d++) {
            float v = Zt[d][m];
            s = __fadd_rn(s, __fmul_rn(v, v));
        }
        znS[m] = s;
    }
    __syncthreads();

    float zm[4];
#pragma unroll
    for (int i = 0; i < 4; i++) zm[i] = znS[ty * 4 + i];

    float minv[4]; int mini[4];
#pragma unroll
    for (int i = 0; i < 4; i++) { minv[i] = 3.4e38f; mini[i] = 0; }

    for (int c0 = 0; c0 < KCODE; c0 += 64) {
        __syncthreads();
#pragma unroll
        for (int i = 0; i < 16; i++) {
            int idx = tid + i * 256;
            int c = idx >> 6, d = idx & 63;
            Cs[d][c] = CB[(size_t)(c0 + c) * 64 + d];
        }
        __syncthreads();

        float dot[4][4];
#pragma unroll
        for (int i = 0; i < 4; i++)
#pragma unroll
            for (int j = 0; j < 4; j++) dot[i][j] = 0.f;
#pragma unroll
        for (int kk = 0; kk < 64; kk++) {
            float a[4], b[4];
#pragma unroll
            for (int i = 0; i < 4; i++) a[i] = Zt[kk][ty * 4 + i];
#pragma unroll
            for (int j = 0; j < 4; j++) b[j] = Cs[kk][tx * 4 + j];
#pragma unroll
            for (int i = 0; i < 4; i++)
#pragma unroll
                for (int j = 0; j < 4; j++)
                    dot[i][j] = fmaf(a[i], b[j], dot[i][j]);
        }
#pragma unroll
        for (int j = 0; j < 4; j++) {
            const int c = c0 + tx * 4 + j;
            const float cn = CN[c];
#pragma unroll
            for (int i = 0; i < 4; i++) {
                float t    = __fadd_rn(zm[i], -__fmul_rn(2.f, dot[i][j]));
                float dist = __fadd_rn(t, cn);
                if (dist < minv[i]) { minv[i] = dist; mini[i] = c; }
            }
        }
    }
    __syncthreads();

    float* redv = &Cs[0][0];
    int*   redi = reinterpret_cast<int*>(&Cs[0][0]) + 1024;
#pragma unroll
    for (int i = 0; i < 4; i++) {
        const int m = ty * 4 + i;
        redv[m * 16 + tx] = minv[i];
        redi[m * 16 + tx] = mini[i];
    }
    __syncthreads();
    if (tid < 64) {
        const int m = tid;
        float bv = redv[m * 16];
        int   bi = redi[m * 16];
        for (int t = 1; t < 16; t++) {
            float v = redv[m * 16 + t];
            int  ix = redi[m * 16 + t];
            if (v < bv || (v == bv && ix < bi)) { bv = v; bi = ix; }
        }
        Codes[pm0 + m] = bi;
        cvals[m] = bv;
    }
    __syncthreads();
    if (tid == 0) {
        float s = 0.f;
        for (int m = 0; m < 64; m++) s += cvals[m];
        CommitPart[blockIdx.x] = s;
    }
}

// ---------------- gather z_q with fused bf16 hi/lo split ----------------------
__global__ void gather_zq_split(const int* __restrict__ codes,
                                const float* __restrict__ CB,
                                bf16* __restrict__ Hi, bf16* __restrict__ Lo)
{
    int idx = blockIdx.x * blockDim.x + threadIdx.x;   // NPOS*16 float4s
    int n = idx >> 4;
    int j = idx & 15;
    float4 v = reinterpret_cast<const float4*>(CB)[codes[n] * 16 + j];
    bf16 h0 = __float2bfloat16(v.x), h1 = __float2bfloat16(v.y);
    bf16 h2 = __float2bfloat16(v.z), h3 = __float2bfloat16(v.w);
    __nv_bfloat162 hh0; hh0.x = h0; hh0.y = h1;
    __nv_bfloat162 hh1; hh1.x = h2; hh1.y = h3;
    __nv_bfloat162 ll0; ll0.x = __float2bfloat16(v.x - __bfloat162float(h0));
    ll0.y = __float2bfloat16(v.y - __bfloat162float(h1));
    __nv_bfloat162 ll1; ll1.x = __float2bfloat16(v.z - __bfloat162float(h2));
    ll1.y = __float2bfloat16(v.w - __bfloat162float(h3));
    reinterpret_cast<__nv_bfloat162*>(Hi)[n * 32 + j * 2 + 0] = hh0;
    reinterpret_cast<__nv_bfloat162*>(Hi)[n * 32 + j * 2 + 1] = hh1;
    reinterpret_cast<__nv_bfloat162*>(Lo)[n * 32 + j * 2 + 0] = ll0;
    reinterpret_cast<__nv_bfloat162*>(Lo)[n * 32 + j * 2 + 1] = ll1;
}

// ---------------- LayerNorm over E=128 + fused split --------------------------
__global__ void ln128_split(const float* __restrict__ X,
                            const float* __restrict__ G,
                            const float* __restrict__ B,
                            bf16* __restrict__ Hi, bf16* __restrict__ Lo)
{
    const int w = threadIdx.x >> 5, lane = threadIdx.x & 31;
    const int p = blockIdx.x * 8 + w;
    float v[4];
#pragma unroll
    for (int i = 0; i < 4; i++) v[i] = X[(size_t)p * 128 + lane + 32 * i];
    float s = 0.f;
#pragma unroll
    for (int i = 0; i < 4; i++) s += v[i];
#pragma unroll
    for (int off = 16; off > 0; off >>= 1)
        s += __shfl_xor_sync(0xffffffffu, s, off);
    float mu = s * (1.f / 128.f);
    float d[4];
    float sq = 0.f;
#pragma unroll
    for (int i = 0; i < 4; i++) {
        d[i] = v[i] - mu;
        sq = __fadd_rn(sq, __fmul_rn(d[i], d[i]));
    }
#pragma unroll
    for (int off = 16; off > 0; off >>= 1)
        sq += __shfl_xor_sync(0xffffffffu, sq, off);
    float var = sq * (1.f / 128.f);
    float rs  = rsqrtf(var + LN_EPS);
#pragma unroll
    for (int i = 0; i < 4; i++) {
        const int c = lane + 32 * i;
        float y = d[i] * rs * G[c] + B[c];
        bf16 h = __float2bfloat16(y);
        Hi[(size_t)p * 128 + c] = h;
        Lo[(size_t)p * 128 + c] = __float2bfloat16(y - __bfloat162float(h));
    }
}

// ---------------- mma helpers -------------------------------------------------
__device__ __forceinline__ void ldsm_x4(uint32_t* r, uint32_t addr) {
    asm volatile("ldmatrix.sync.aligned.m8n8.x4.shared.b16 {%0,%1,%2,%3}, [%4];"
                 : "=r"(r[0]), "=r"(r[1]), "=r"(r[2]), "=r"(r[3]) : "r"(addr));
}
__device__ __forceinline__ void mma16816(float* d, const uint32_t* a,
                                         uint32_t b0, uint32_t b1) {
    asm volatile(
        "mma.sync.aligned.m16n8k16.row.col.f32.bf16.bf16.f32 "
        "{%0,%1,%2,%3}, {%4,%5,%6,%7}, {%8,%9}, {%0,%1,%2,%3};"
        : "+f"(d[0]), "+f"(d[1]), "+f"(d[2]), "+f"(d[3])
        : "r"(a[0]), "r"(a[1]), "r"(a[2]), "r"(a[3]), "r"(b0), "r"(b1));
}
__device__ __forceinline__ void mma16816h(float* d, const uint32_t* a,
                                          uint32_t b0, uint32_t b1) {
    asm volatile(
        "mma.sync.aligned.m16n8k16.row.col.f32.f16.f16.f32 "
        "{%0,%1,%2,%3}, {%4,%5,%6,%7}, {%8,%9}, {%0,%1,%2,%3};"
        : "+f"(d[0]), "+f"(d[1]), "+f"(d[2]), "+f"(d[3])
        : "r"(a[0]), "r"(a[1]), "r"(a[2]), "r"(a[3]), "r"(b0), "r"(b1));
}

// ---------------- generic bf16x3 (hi/lo) tensor conv, double-buffered --------
// Two 64KB smem buffers; cp.async loads chunk c+1 while MMAs run on chunk c.
#define TC_SMEM 131072

template<int CIN, int KW, int COUT, bool RELU, bool WF32, bool WSPLIT>
__global__ void __launch_bounds__(256)
tconv(const bf16* __restrict__ Ahi, const bf16* __restrict__ Alo,
      const bf16* __restrict__ Whi, const bf16* __restrict__ Wlo,
      const float* __restrict__ Bias,
      float* __restrict__ Yf, bf16* __restrict__ Yhi, bf16* __restrict__ Ylo)
{
    constexpr int KTOT = CIN * KW;
    constexpr int NCH  = KTOT / 64;
    constexpr int PAD  = (KW == 3) ? 1 : 0;

    extern __shared__ char smem[];
    const int tid = threadIdx.x;
    const int pm0 = blockIdx.x * 128;
    const int nv0 = blockIdx.y * 128;

    const int wid = tid >> 5, lane = tid & 31;
    const int wm = (wid >> 1) * 32;
    const int wn = (wid & 1) * 64;
    const int lr = lane & 7, lq = lane >> 3;

    float acc[2][8][4];
#pragma unroll
    for (int mi = 0; mi < 2; mi++)
#pragma unroll
        for (int ni = 0; ni < 8; ni++)
#pragma unroll
            for (int e = 0; e < 4; e++) acc[mi][ni][e] = 0.f;

    const uint4* A4h = reinterpret_cast<const uint4*>(Ahi);
    const uint4* A4l = reinterpret_cast<const uint4*>(Alo);
    const uint4* B4h = reinterpret_cast<const uint4*>(Whi);
    const uint4* B4l = reinterpret_cast<const uint4*>(Wlo);

    const uint32_t sb = smem_to_u32(smem);

    auto load_chunk = [&](int ch, int buf) {
        const uint32_t bo = (uint32_t)buf * 65536u;
        const int tap = (ch * 64) / CIN;
        const int ci0 = (ch * 64) % CIN;
#pragma unroll
        for (int i = 0; i < 4; i++) {
            int idx = tid + i * 256;
            int row = idx >> 3, c = idx & 7;
            int p = pm0 + row;
            bool ok = true;
            if (KW == 3) {
                int ls = (p & (LSEQ - 1)) + tap - PAD;
                ok = ((unsigned)ls < (unsigned)LSEQ);
            }
            size_t gi = ok ? ((size_t)(p + tap - PAD) * (CIN / 8) + (ci0 / 8) + c) : 0;
            int nb = ok ? 16 : 0;
            int pc = (c ^ row) & 7;
            uint32_t so = (uint32_t)(row * 128 + pc * 16);
            cp_async16(sb + bo + so,          A4h + gi, nb);
            cp_async16(sb + bo + 16384u + so, A4l + gi, nb);
        }
#pragma unroll
        for (int i = 0; i < 4; i++) {
            int idx = tid + i * 256;
            int row = idx >> 3, c = idx & 7;
            size_t gi = (size_t)(nv0 + row) * (KTOT / 8) + ch * 8 + c;
            int pc = (c ^ row) & 7;
            uint32_t so = (uint32_t)(row * 128 + pc * 16);
            cp_async16(sb + bo + 32768u + so, B4h + gi, 16);
            cp_async16(sb + bo + 49152u + so, B4l + gi, 16);
        }
        asm volatile("cp.async.commit_group;");
    };

    load_chunk(0, 0);

    for (int ch = 0; ch < NCH; ch++) {
        if (ch + 1 < NCH) {
            load_chunk(ch + 1, (ch + 1) & 1);
            asm volatile("cp.async.wait_group 1;");
        } else {
            asm volatile("cp.async.wait_group 0;");
        }
        __syncthreads();

        const uint32_t bo = (uint32_t)(ch & 1) * 65536u;
        const uint32_t aB3[3] = { sb + bo, sb + bo, sb + bo + 16384u };
        const uint32_t bB3[3] = { sb + bo + 32768u, sb + bo + 49152u, sb + bo + 32768u };
#pragma unroll
        for (int s = 0; s < 3; s++) {
            const uint32_t aB = aB3[s];
            const uint32_t bB = bB3[s];
#pragma unroll
            for (int k16 = 0; k16 < 4; k16++) {
                const int kc0 = k16 * 2;
                uint32_t a[2][4];
#pragma unroll
                for (int mi = 0; mi < 2; mi++) {
                    int row = wm + mi * 16 + lr + (lq & 1) * 8;
                    int kc  = kc0 + (lq >> 1);
                    int pc  = (kc ^ row) & 7;
                    ldsm_x4(a[mi], aB + row * 128 + pc * 16);
                }
                uint32_t b[4][4];
#pragma unroll
                for (int nc = 0; nc < 4; nc++) {
                    int row = wn + nc * 16 + lr + (lq >> 1) * 8;
                    int kc  = kc0 + (lq & 1);
                    int pc  = (kc ^ row) & 7;
                    ldsm_x4(b[nc], bB + row * 128 + pc * 16);
                }
#pragma unroll
                for (int mi = 0; mi < 2; mi++)
#pragma unroll
                    for (int ni = 0; ni < 8; ni++)
                        mma16816(acc[mi][ni], a[mi],
                                 b[ni >> 1][(ni & 1) * 2 + 0],
                                 b[ni >> 1][(ni & 1) * 2 + 1]);
            }
        }
        __syncthreads();
    }

    const int gid = lane >> 2, tig = lane & 3;
#pragma unroll
    for (int mi = 0; mi < 2; mi++) {
        const int m0 = pm0 + wm + mi * 16 + gid;
#pragma unroll
        for (int ni = 0; ni < 8; ni++) {
            const int n = nv0 + wn + ni * 8 + tig * 2;
            const float2 bv = *reinterpret_cast<const float2*>(Bias + n);
            float v00 = acc[mi][ni][0] + bv.x;
            float v01 = acc[mi][ni][1] + bv.y;
            float v10 = acc[mi][ni][2] + bv.x;
            float v11 = acc[mi][ni][3] + bv.y;
            if (RELU) {
                v00 = fmaxf(v00, 0.f); v01 = fmaxf(v01, 0.f);
                v10 = fmaxf(v10, 0.f); v11 = fmaxf(v11, 0.f);
            }
            if (WF32) {
                float2 a0; a0.x = v00; a0.y = v01;
                float2 a1; a1.x = v10; a1.y = v11;
                *reinterpret_cast<float2*>(Yf + (size_t)m0 * COUT + n)       = a0;
                *reinterpret_cast<float2*>(Yf + (size_t)(m0 + 8) * COUT + n) = a1;
            }
            if (WSPLIT) {
                bf16 h00 = __float2bfloat16(v00), h01 = __float2bfloat16(v01);
                bf16 h10 = __float2bfloat16(v10), h11 = __float2bfloat16(v11);
                __nv_bfloat162 hh0; hh0.x = h00; hh0.y = h01;
                __nv_bfloat162 hh1; hh1.x = h10; hh1.y = h11;
                __nv_bfloat162 ll0;
                ll0.x = __float2bfloat16(v00 - __bfloat162float(h00));
                ll0.y = __float2bfloat16(v01 - __bfloat162float(h01));
                __nv_bfloat162 ll1;
                ll1.x = __float2bfloat16(v10 - __bfloat162float(h10));
                ll1.y = __float2bfloat16(v11 - __bfloat162float(h11));
                *reinterpret_cast<__nv_bfloat162*>(Yhi + (size_t)m0 * COUT + n)       = hh0;
                *reinterpret_cast<__nv_bfloat162*>(Yhi + (size_t)(m0 + 8) * COUT + n) = hh1;
                *reinterpret_cast<__nv_bfloat162*>(Ylo + (size_t)m0 * COUT + n)       = ll0;
                *reinterpret_cast<__nv_bfloat162*>(Ylo + (size_t)(m0 + 8) * COUT + n) = ll1;
            }
        }
    }
}

// ---------------- fp16 two-split tensor conv (encoder), double-buffered ------
template<int CIN, int KW, int COUT, bool WF32>
__global__ void __launch_bounds__(256)
tconvh(const half* __restrict__ Ah, const half* __restrict__ Am,
       const half* __restrict__ Wh, const half* __restrict__ Wm,
       const float* __restrict__ Bias, float* __restrict__ Yf,
       half* __restrict__ Yh, half* __restrict__ Ym)
{
    constexpr int KTOT = CIN * KW;
    constexpr int NCH  = KTOT / 64;
    constexpr int PAD  = (KW == 3) ? 1 : 0;

    extern __shared__ char smem[];
    const int tid = threadIdx.x;
    const int pm0 = blockIdx.x * 128;
    const int nv0 = blockIdx.y * 128;

    const int wid = tid >> 5, lane = tid & 31;
    const int wm = (wid >> 1) * 32;
    const int wn = (wid & 1) * 64;
    const int lr = lane & 7, lq = lane >> 3;

    float acc1[2][8][4];
    float acc2[2][8][4];
#pragma unroll
    for (int mi = 0; mi < 2; mi++)
#pragma unroll
        for (int ni = 0; ni < 8; ni++)
#pragma unroll
            for (int e = 0; e < 4; e++) { acc1[mi][ni][e] = 0.f; acc2[mi][ni][e] = 0.f; }

    const uint4* A4h = reinterpret_cast<const uint4*>(Ah);
    const uint4* A4m = reinterpret_cast<const uint4*>(Am);
    const uint4* B4h = reinterpret_cast<const uint4*>(Wh);
    const uint4* B4m = reinterpret_cast<const uint4*>(Wm);

    const uint32_t sb = smem_to_u32(smem);

    auto load_chunk = [&](int ch, int buf) {
        const uint32_t bo = (uint32_t)buf * 65536u;
        const int tap = (ch * 64) / CIN;
        const int ci0 = (ch * 64) % CIN;
#pragma unroll
        for (int i = 0; i < 4; i++) {
            int idx = tid + i * 256;
            int row = idx >> 3, c = idx & 7;
            int p = pm0 + row;
            bool ok = true;
            if (KW == 3) {
                int ls = (p & (LSEQ - 1)) + tap - PAD;
                ok = ((unsigned)ls < (unsigned)LSEQ);
            }
            size_t gi = ok ? ((size_t)(p + tap - PAD) * (CIN / 8) + (ci0 / 8) + c) : 0;
            int nb = ok ? 16 : 0;
            int pc = (c ^ row) & 7;
            uint32_t so = (uint32_t)(row * 128 + pc * 16);
            cp_async16(sb + bo + so,          A4h + gi, nb);
            cp_async16(sb + bo + 16384u + so, A4m + gi, nb);
        }
#pragma unroll
        for (int i = 0; i < 4; i++) {
            int idx = tid + i * 256;
            int row = idx >> 3, c = idx & 7;
            size_t gi = (size_t)(nv0 + row) * (KTOT / 8) + ch * 8 + c;
            int pc = (c ^ row) & 7;
            uint32_t so = (uint32_t)(row * 128 + pc * 16);
            cp_async16(sb + bo + 32768u + so, B4h + gi, 16);
            cp_async16(sb + bo + 49152u + so, B4m + gi, 16);
        }
        asm volatile("cp.async.commit_group;");
    };

    load_chunk(0, 0);

    for (int ch = 0; ch < NCH; ch++) {
        if (ch + 1 < NCH) {
            load_chunk(ch + 1, (ch + 1) & 1);
            asm volatile("cp.async.wait_group 1;");
        } else {
            asm volatile("cp.async.wait_group 0;");
        }
        __syncthreads();

        const uint32_t bo = (uint32_t)(ch & 1) * 65536u;
        const uint32_t aB3[3] = { sb + bo, sb + bo, sb + bo + 16384u };
        const uint32_t bB3[3] = { sb + bo + 32768u, sb + bo + 49152u, sb + bo + 32768u };
#pragma unroll
        for (int s = 0; s < 3; s++) {
            const uint32_t aB = aB3[s];
            const uint32_t bB = bB3[s];
#pragma unroll
            for (int k16 = 0; k16 < 4; k16++) {
                const int kc0 = k16 * 2;
                uint32_t a[2][4];
#pragma unroll
                for (int mi = 0; mi < 2; mi++) {
                    int row = wm + mi * 16 + lr + (lq & 1) * 8;
                    int kc  = kc0 + (lq >> 1);
                    int pc  = (kc ^ row) & 7;
                    ldsm_x4(a[mi], aB + row * 128 + pc * 16);
                }
                uint32_t b[4][4];
#pragma unroll
                for (int nc = 0; nc < 4; nc++) {
                    int row = wn + nc * 16 + lr + (lq >> 1) * 8;
                    int kc  = kc0 + (lq & 1);
                    int pc  = (kc ^ row) & 7;
                    ldsm_x4(b[nc], bB + row * 128 + pc * 16);
                }
                float (*acc)[8][4] = (s == 0) ? acc1 : acc2;
#pragma unroll
                for (int mi = 0; mi < 2; mi++)
#pragma unroll
                    for (int ni = 0; ni < 8; ni++)
                        mma16816h(acc[mi][ni], a[mi],
                                  b[ni >> 1][(ni & 1) * 2 + 0],
                                  b[ni >> 1][(ni & 1) * 2 + 1]);
            }
        }
        __syncthreads();
    }

    const int gid = lane >> 2, tig = lane & 3;
#pragma unroll
    for (int mi = 0; mi < 2; mi++) {
        const int m0 = pm0 + wm + mi * 16 + gid;
#pragma unroll
        for (int ni = 0; ni < 8; ni++) {
            const int n = nv0 + wn + ni * 8 + tig * 2;
            const float2 bv = *reinterpret_cast<const float2*>(Bias + n);
            float v00 = fmaxf(fmaf(acc2[mi][ni][0], LO_INV, acc1[mi][ni][0]) + bv.x, 0.f);
            float v01 = fmaxf(fmaf(acc2[mi][ni][1], LO_INV, acc1[mi][ni][1]) + bv.y, 0.f);
            float v10 = fmaxf(fmaf(acc2[mi][ni][2], LO_INV, acc1[mi][ni][2]) + bv.x, 0.f);
            float v11 = fmaxf(fmaf(acc2[mi][ni][3], LO_INV, acc1[mi][ni][3]) + bv.y, 0.f);
            if (WF32) {
                float2 a0; a0.x = v00; a0.y = v01;
                float2 a1; a1.x = v10; a1.y = v11;
                *reinterpret_cast<float2*>(Yf + (size_t)m0 * COUT + n)       = a0;
                *reinterpret_cast<float2*>(Yf + (size_t)(m0 + 8) * COUT + n) = a1;
            } else {
                half h00,m00,h01,m01,h10,m10,h11,m11;
                split2h(v00,h00,m00); split2h(v01,h01,m01);
                split2h(v10,h10,m10); split2h(v11,h11,m11);
                __half2 p0, p1;
                p0.x=h00; p0.y=h01; p1.x=h10; p1.y=h11;
                *reinterpret_cast<__half2*>(Yh + (size_t)m0 * COUT + n)       = p0;
                *reinterpret_cast<__half2*>(Yh + (size_t)(m0 + 8) * COUT + n) = p1;
                p0.x=m00; p0.y=m01; p1.x=m10; p1.y=m11;
                *reinterpret_cast<__half2*>(Ym + (size_t)m0 * COUT + n)       = p0;
                *reinterpret_cast<__half2*>(Ym + (size_t)(m0 + 8) * COUT + n) = p1;
            }
        }
    }
}

// ---------------- wide full-K-resident bf16x3 logits GEMM --------------------
#define LGW_SMEM 196608

__global__ void __launch_bounds__(256, 1)
logits_wide(const bf16* __restrict__ Ahi, const bf16* __restrict__ Alo,
            const bf16* __restrict__ Bhi, const bf16* __restrict__ Blo,
            const float* __restrict__ Bias, float* __restrict__ Out)
{
    extern __shared__ char smem[];
    char* sAhi = smem;              // 128 rows x 256B = 32768
    char* sAlo = smem + 32768;
    char* sBhi = smem + 65536;      // 256 rows x 256B = 65536
    char* sBlo = smem + 131072;

    const int tid = threadIdx.x;
    const int pm0 = blockIdx.x * 128;
    const int nv0 = blockIdx.y * 256;

    {
        const uint4* A4h = reinterpret_cast<const uint4*>(Ahi);
        const uint4* A4l = reinterpret_cast<const uint4*>(Alo);
#pragma unroll
        for (int i = 0; i < 8; i++) {
            int idx = tid + i * 256;          // 0..2047
            int row = idx >> 4, c = idx & 15;
            uint4 vh = A4h[(size_t)(pm0 + row) * 16 + c];
            uint4 vl = A4l[(size_t)(pm0 + row) * 16 + c];
            int pc = (c & 8) | ((c ^ row) & 7);
            *reinterpret_cast<uint4*>(sAhi + row * 256 + pc * 16) = vh;
            *reinterpret_cast<uint4*>(sAlo + row * 256 + pc * 16) = vl;
        }
        const uint4* B4h = reinterpret_cast<const uint4*>(Bhi);
        const uint4* B4l = reinterpret_cast<const uint4*>(Blo);
#pragma unroll
        for (int i = 0; i < 16; i++) {
            int idx = tid + i * 256;          // 0..4095
            int row = idx >> 4, c = idx & 15;
            uint4 vh = B4h[(size_t)(nv0 + row) * 16 + c];
            uint4 vl = B4l[(size_t)(nv0 + row) * 16 + c];
            int pc = (c & 8) | ((c ^ row) & 7);
            *reinterpret_cast<uint4*>(sBhi + row * 256 + pc * 16) = vh;
            *reinterpret_cast<uint4*>(sBlo + row * 256 + pc * 16) = vl;
        }
    }
    __syncthreads();

    const int wid = tid >> 5, lane = tid & 31;
    const int wm = (wid >> 1) * 32;       // 0,32,64,96
    const int wn = (wid & 1) * 128;       // 0,128
    const int lr = lane & 7, lq = lane >> 3;

    float acc[2][16][4];
#pragma unroll
    for (int mi = 0; mi < 2; mi++)
#pragma unroll
        for (int ni = 0; ni < 16; ni++)
#pragma unroll
            for (int e = 0; e < 4; e++) acc[mi][ni][e] = 0.f;

    const uint32_t sb = smem_to_u32(smem);
    const uint32_t aB3[3] = { sb, sb, sb + 32768u };                 // hi, hi, lo
    const uint32_t bB3[3] = { sb + 65536u, sb + 131072u, sb + 65536u }; // hi, lo, hi

#pragma unroll
    for (int s = 0; s < 3; s++) {
        const uint32_t aB = aB3[s];
        const uint32_t bB = bB3[s];
#pragma unroll
        for (int k16 = 0; k16 < 8; k16++) {
            const int kc0 = k16 * 2;
            uint32_t a[2][4];
#pragma unroll
            for (int mi = 0; mi < 2; mi++) {
                int row = wm + mi * 16 + lr + (lq & 1) * 8;
                int kc  = kc0 + (lq >> 1);
                int pc  = (kc & 8) | ((kc ^ row) & 7);
                ldsm_x4(a[mi], aB + row * 256 + pc * 16);
            }
#pragma unroll
            for (int nc = 0; nc < 8; nc++) {
                uint32_t b[4];
                int row = wn + nc * 16 + lr + (lq >> 1) * 8;
                int kc  = kc0 + (lq & 1);
                int pc  = (kc & 8) | ((kc ^ row) & 7);
                ldsm_x4(b, bB + row * 256 + pc * 16);
                mma16816(acc[0][nc * 2 + 0], a[0], b[0], b[1]);
                mma16816(acc[0][nc * 2 + 1], a[0], b[2], b[3]);
                mma16816(acc[1][nc * 2 + 0], a[1], b[0], b[1]);
                mma16816(acc[1][nc * 2 + 1], a[1], b[2], b[3]);
            }
        }
    }

    const int gid = lane >> 2, tig = lane & 3;
#pragma unroll
    for (int mi = 0; mi < 2; mi++) {
        const int m0 = pm0 + wm + mi * 16 + gid;
#pragma unroll
        for (int ni = 0; ni < 16; ni++) {
            const int n = nv0 + wn + ni * 8 + tig * 2;
            const float2 bv = *reinterpret_cast<const float2*>(Bias + n);
            float2 v0, v1;
            v0.x = acc[mi][ni][0] + bv.x;  v0.y = acc[mi][ni][1] + bv.y;
            v1.x = acc[mi][ni][2] + bv.x;  v1.y = acc[mi][ni][3] + bv.y;
            *reinterpret_cast<float2*>(Out + (size_t)m0 * VOCAB + n)       = v0;
            *reinterpret_cast<float2*>(Out + (size_t)(m0 + 8) * VOCAB + n) = v1;
        }
    }
}

// ---------------- tail: loss scalar + codes ----------------------------------
__global__ void commit_final(const float* __restrict__ Part, float* __restrict__ slot)
{
    if (threadIdx.x == 0 && blockIdx.x == 0) {
        float s = 0.f;
        for (int i = 0; i < NPOS / 64; i++) s += Part[i];
        *slot = 0.1f * s / ((float)NPOS * (float)DDIM);
    }
}

__global__ void write_codes(const int* __restrict__ codes, float* __restrict__ out)
{
    int n = blockIdx.x * blockDim.x + threadIdx.x;
    if (n < NPOS) out[n] = (float)codes[n];
}

// ---------------- launch ------------------------------------------------------
extern "C" void kernel_launch(void* const* d_in, const int* in_sizes, int n_in,
                              void* d_out, int out_size)
{
    (void)in_sizes; (void)n_in;
    const int*   x    = (const int*)  d_in[0];
    const float* tok  = (const float*)d_in[1];
    const float* ew1  = (const float*)d_in[2];
    const float* eb1  = (const float*)d_in[3];
    const float* ew2  = (const float*)d_in[4];
    const float* eb2  = (const float*)d_in[5];
    const float* ew3  = (const float*)d_in[6];
    const float* eb3  = (const float*)d_in[7];
    const float* elg  = (const float*)d_in[8];
    const float* elb  = (const float*)d_in[9];
    const float* cb   = (const float*)d_in[10];
    const float* dw1  = (const float*)d_in[11];
    const float* db1  = (const float*)d_in[12];
    const float* dw2  = (const float*)d_in[13];
    const float* db2  = (const float*)d_in[14];
    const float* dw3  = (const float*)d_in[15];
    const float* db3  = (const float*)d_in[16];
    const float* dlg  = (const float*)d_in[17];
    const float* dlb  = (const float*)d_in[18];
    const float* ow   = (const float*)d_in[19];
    const float* ob   = (const float*)d_in[20];
    float* out = (float*)d_out;

    float *emb, *h2, *z, *cn, *cp;
    int* codes;
    half *ebh,*ebm,*e1h,*e1m,*w1eh,*w1em,*w2eh,*w2em;
    bf16 *zqhi,*zqlo,*d1hi,*d1lo,*d2hi,*d2lo,*ahi,*alo;
    bf16 *w1hi,*w1lo,*w2hi,*w2lo,*w3hi,*w3lo,*bhi,*blo;
    cudaGetSymbolAddress((void**)&emb,   g_emb);
    cudaGetSymbolAddress((void**)&h2,    g_h2);
    cudaGetSymbolAddress((void**)&z,     g_z);
    cudaGetSymbolAddress((void**)&codes, g_codes);
    cudaGetSymbolAddress((void**)&cn,    g_cnorm);
    cudaGetSymbolAddress((void**)&cp,    g_commit);
    cudaGetSymbolAddress((void**)&ebh,   g_ebh);
    cudaGetSymbolAddress((void**)&ebm,   g_ebm);
    cudaGetSymbolAddress((void**)&e1h,   g_e1h);
    cudaGetSymbolAddress((void**)&e1m,   g_e1m);
    cudaGetSymbolAddress((void**)&w1eh,  g_w1eh);
    cudaGetSymbolAddress((void**)&w1em,  g_w1em);
    cudaGetSymbolAddress((void**)&w2eh,  g_w2eh);
    cudaGetSymbolAddress((void**)&w2em,  g_w2em);
    cudaGetSymbolAddress((void**)&zqhi,  g_zqhi);
    cudaGetSymbolAddress((void**)&zqlo,  g_zqlo);
    cudaGetSymbolAddress((void**)&d1hi,  g_d1hi);
    cudaGetSymbolAddress((void**)&d1lo,  g_d1lo);
    cudaGetSymbolAddress((void**)&d2hi,  g_d2hi);
    cudaGetSymbolAddress((void**)&d2lo,  g_d2lo);
    cudaGetSymbolAddress((void**)&ahi,   g_ahi);
    cudaGetSymbolAddress((void**)&alo,   g_alo);
    cudaGetSymbolAddress((void**)&w1hi,  g_w1hi);
    cudaGetSymbolAddress((void**)&w1lo,  g_w1lo);
    cudaGetSymbolAddress((void**)&w2hi,  g_w2hi);
    cudaGetSymbolAddress((void**)&w2lo,  g_w2lo);
    cudaGetSymbolAddress((void**)&w3hi,  g_w3hi);
    cudaGetSymbolAddress((void**)&w3lo,  g_w3lo);
    cudaGetSymbolAddress((void**)&bhi,   g_bhi);
    cudaGetSymbolAddress((void**)&blo,   g_blo);

    cudaFuncSetAttribute((const void*)tconvh<128, 3, 256, false>,
                         cudaFuncAttributeMaxDynamicSharedMemorySize, TC_SMEM);
    cudaFuncSetAttribute((const void*)tconvh<256, 3, 256, true>,
                         cudaFuncAttributeMaxDynamicSharedMemorySize, TC_SMEM);
    cudaFuncSetAttribute((const void*)tconv< 64, 1, 256, true,  false, true >,
                         cudaFuncAttributeMaxDynamicSharedMemorySize, TC_SMEM);
    cudaFuncSetAttribute((const void*)tconv<256, 3, 256, true,  false, true >,
                         cudaFuncAttributeMaxDynamicSharedMemorySize, TC_SMEM);
    cudaFuncSetAttribute((const void*)tconv<256, 1, 128, true,  true,  false>,
                         cudaFuncAttributeMaxDynamicSharedMemorySize, TC_SMEM);
    cudaFuncSetAttribute((const void*)logits_wide,
                         cudaFuncAttributeMaxDynamicSharedMemorySize, LGW_SMEM);

    // ---- encoder (fp16 two-split tensor cores, pipelined) ----
    pack_split2h<128, 3, 256><<<(256*384)  / 256, 256>>>(ew1, w1eh, w1em);
    pack_split2h<256, 3, 256><<<(256*768)  / 256, 256>>>(ew2, w2eh, w2em);
    embed_split2h<<<NPOS * 32 / 256, 256>>>(x, tok, ebh, ebm);
    tconvh<128, 3, 256, false><<<dim3(NPOS/128, 2), 256, TC_SMEM>>>(
        ebh, ebm, w1eh, w1em, eb1, nullptr, e1h, e1m);
    tconvh<256, 3, 256, true ><<<dim3(NPOS/128, 2), 256, TC_SMEM>>>(
        e1h, e1m, w2eh, w2em, eb2, h2, nullptr, nullptr);
    enc_head_ln<<<NPOS / 64, 256>>>(h2, ew3, eb3, elg, elb, z);

    // ---- vector quantization ----
    cnorm_kernel<<<1, 512>>>(cb, cn);
    vq_kernel<<<NPOS / 64, 256>>>(z, cb, cn, codes, cp);
    gather_zq_split<<<NPOS * 16 / 256, 256>>>(codes, cb, zqhi, zqlo);

    // ---- decoder weight packs + decoder (bf16x3 tensor cores, pipelined) ----
    pack_split< 64, 1, 256>  <<<(256*64)   / 256, 256>>>(dw1, w1hi, w1lo);
    pack_split<256, 3, 256>  <<<(256*768)  / 256, 256>>>(dw2, w2hi, w2lo);
    pack_split<256, 1, 128>  <<<(128*256)  / 256, 256>>>(dw3, w3hi, w3lo);
    pack_split<128, 1, VOCAB><<<(VOCAB*128)/ 256, 256>>>(ow,  bhi,  blo);

    tconv< 64, 1, 256, true,  false, true ><<<dim3(NPOS/128, 2),  256, TC_SMEM>>>(
        zqhi, zqlo, w1hi, w1lo, db1, nullptr, d1hi, d1lo);
    tconv<256, 3, 256, true,  false, true ><<<dim3(NPOS/128, 2),  256, TC_SMEM>>>(
        d1hi, d1lo, w2hi, w2lo, db2, nullptr, d2hi, d2lo);
    tconv<256, 1, 128, true,  true,  false><<<dim3(NPOS/128, 1),  256, TC_SMEM>>>(
        d2hi, d2lo, w3hi, w3lo, db3, emb, nullptr, nullptr);
    ln128_split<<<NPOS / 8, 256>>>(emb, dlg, dlb, ahi, alo);

    // ---- vocab projection (wide full-K bf16x3) -> d_out ----
    logits_wide<<<dim3(NPOS/128, VOCAB/256), 256, LGW_SMEM>>>(
        ahi, alo, bhi, blo, ob, out);

    // ---- tail: loss scalar + codes ----
    const long long NV = (long long)NPOS * VOCAB;   // 134217728
    if ((long long)out_size >= NV + 1)
        commit_final<<<1, 32>>>(cp, out + NV);
    if ((long long)out_size >= NV + 1 + NPOS)
        write_codes<<<NPOS / 256, 256>>>(codes, out + NV + 1);
}

// round 10
// speedup vs baseline: 3.1213x; 1.0422x over previous
#include <cuda_runtime.h>
#include <cuda_bf16.h>
#include <cuda_fp16.h>
#include <cstdint>

// Problem constants
#define NPOS   32768          // B*L = 8*4096
#define LSEQ   4096
#define EDIM   128
#define HDIM   256
#define DDIM   64
#define KCODE  512
#define VOCAB  4096
#define LN_EPS 1e-5f

typedef __nv_bfloat16 bf16;

#define LO_SCALE   2048.0f
#define LO_INV     (1.0f / 2048.0f)

// ---------------- scratch (static device globals; no allocation) -------------
__device__ float g_emb[NPOS * EDIM];    // decoder conv3 output (fp32)
__device__ float g_h2 [NPOS * HDIM];    // encoder conv2 output (fp32)
__device__ float g_z  [NPOS * DDIM];    // z_e after LN
__device__ int   g_codes[NPOS];
__device__ float g_cnorm[KCODE];
__device__ float g_commit[NPOS / 64];
// encoder fp16 two-split activations (lo scaled by 2048)
__device__ __align__(16) half g_ebh[NPOS * EDIM];
__device__ __align__(16) half g_ebm[NPOS * EDIM];
__device__ __align__(16) half g_e1h[NPOS * HDIM];
__device__ __align__(16) half g_e1m[NPOS * HDIM];
// encoder fp16 two-split packed weights
__device__ __align__(16) half g_w1eh[HDIM * EDIM * 3];
__device__ __align__(16) half g_w1em[HDIM * EDIM * 3];
__device__ __align__(16) half g_w2eh[HDIM * HDIM * 3];
__device__ __align__(16) half g_w2em[HDIM * HDIM * 3];
// decoder bf16 hi/lo split activations
__device__ __align__(16) bf16 g_zqhi[NPOS * DDIM];
__device__ __align__(16) bf16 g_zqlo[NPOS * DDIM];
__device__ __align__(16) bf16 g_d1hi[NPOS * HDIM];
__device__ __align__(16) bf16 g_d1lo[NPOS * HDIM];
__device__ __align__(16) bf16 g_d2hi[NPOS * HDIM];
__device__ __align__(16) bf16 g_d2lo[NPOS * HDIM];
__device__ __align__(16) bf16 g_ahi[NPOS * EDIM];
__device__ __align__(16) bf16 g_alo[NPOS * EDIM];
// decoder bf16 hi/lo split packed weights
__device__ __align__(16) bf16 g_w1hi[HDIM * DDIM];
__device__ __align__(16) bf16 g_w1lo[HDIM * DDIM];
__device__ __align__(16) bf16 g_w2hi[HDIM * HDIM * 3];
__device__ __align__(16) bf16 g_w2lo[HDIM * HDIM * 3];
__device__ __align__(16) bf16 g_w3hi[EDIM * HDIM];
__device__ __align__(16) bf16 g_w3lo[EDIM * HDIM];
__device__ __align__(16) bf16 g_bhi[VOCAB * EDIM];
__device__ __align__(16) bf16 g_blo[VOCAB * EDIM];

__device__ __forceinline__ uint32_t smem_to_u32(const void* smem_ptr) {
    uint32_t addr;
    asm("{ .reg .u64 tmp; cvta.to.shared.u64 tmp, %1; cvt.u32.u64 %0, tmp; }"
        : "=r"(addr) : "l"(smem_ptr));
    return addr;
}

__device__ __forceinline__ void cp_async16(uint32_t saddr, const void* gptr, int src_bytes) {
    asm volatile("cp.async.cg.shared.global [%0], [%1], 16, %2;"
                 :: "r"(saddr), "l"(gptr), "r"(src_bytes));
}

// fp16 two-split: x = h + (m/2048); m kept in normal fp16 range
__device__ __forceinline__ void split2h(float x, half& h, half& m) {
    h = __float2half_rn(x);
    m = __float2half_rn((x - __half2float(h)) * LO_SCALE);
}

// ---------------- embedding lookup with fused fp16 two-split ------------------
__global__ void embed_split2h(const int* __restrict__ x,
                              const float* __restrict__ tok,
                              half* __restrict__ H, half* __restrict__ M)
{
    int idx = blockIdx.x * blockDim.x + threadIdx.x;   // NPOS*32 float4s
    int n = idx >> 5;
    int j = idx & 31;
    int t = x[n];
    float4 v = reinterpret_cast<const float4*>(tok)[t * 32 + j];
    half h0,m0,h1,m1,h2,m2,h3,m3;
    split2h(v.x,h0,m0); split2h(v.y,h1,m1);
    split2h(v.z,h2,m2); split2h(v.w,h3,m3);
    __half2 p;
    p.x=h0; p.y=h1; reinterpret_cast<__half2*>(H)[n*64+j*2+0]=p;
    p.x=h2; p.y=h3; reinterpret_cast<__half2*>(H)[n*64+j*2+1]=p;
    p.x=m0; p.y=m1; reinterpret_cast<__half2*>(M)[n*64+j*2+0]=p;
    p.x=m2; p.y=m3; reinterpret_cast<__half2*>(M)[n*64+j*2+1]=p;
}

// ---------------- weight pack + splits ----------------------------------------
template<int CIN, int KW, int COUT>
__global__ void pack_split(const float* __restrict__ W,
                           bf16* __restrict__ Hi, bf16* __restrict__ Lo)
{
    int idx = blockIdx.x * blockDim.x + threadIdx.x;
    if (idx >= COUT * KW * CIN) return;
    int o   = idx / (KW * CIN);
    int rem = idx - o * (KW * CIN);
    int tap = rem / CIN;
    int ci  = rem - tap * CIN;
    float w = W[(size_t)o * CIN * KW + ci * KW + tap];
    bf16 h = __float2bfloat16(w);
    Hi[idx] = h;
    Lo[idx] = __float2bfloat16(w - __bfloat162float(h));
}

template<int CIN, int KW, int COUT>
__global__ void pack_split2h(const float* __restrict__ W,
                             half* __restrict__ H, half* __restrict__ M)
{
    int idx = blockIdx.x * blockDim.x + threadIdx.x;
    if (idx >= COUT * KW * CIN) return;
    int o   = idx / (KW * CIN);
    int rem = idx - o * (KW * CIN);
    int tap = rem / CIN;
    int ci  = rem - tap * CIN;
    float w = W[(size_t)o * CIN * KW + ci * KW + tap];
    half h, m;
    split2h(w, h, m);
    H[idx] = h; M[idx] = m;
}

// ---------------- encoder head: conv1x1 (256->64) + LayerNorm(D=64) ---------
__global__ void __launch_bounds__(256)
enc_head_ln(const float* __restrict__ X, const float* __restrict__ W,
            const float* __restrict__ Bias,
            const float* __restrict__ G, const float* __restrict__ Bt,
            float* __restrict__ Z)
{
    constexpr int CIN = 256;
    __shared__ float As[32][66];
    __shared__ float Bs[32][66];
    __shared__ float Zs[64][66];

    const int pm0 = blockIdx.x * 64;
    const int tid = threadIdx.x;
    const int tx = tid & 15, ty = tid >> 4;
    const int rr = tid & 31;
    const int mrow = tid >> 5;

    float acc[4][4];
#pragma unroll
    for (int i = 0; i < 4; i++)
#pragma unroll
        for (int j = 0; j < 4; j++) acc[i][j] = 0.f;

    for (int r0 = 0; r0 < CIN; r0 += 32) {
        const int ci = r0 + rr;
#pragma unroll
        for (int i = 0; i < 8; i++) {
            const int m = mrow + i * 8;
            As[rr][m] = X[(size_t)(pm0 + m) * CIN + ci];
        }
#pragma unroll
        for (int i = 0; i < 8; i++) {
            const int n = mrow + i * 8;
            Bs[rr][n] = W[(size_t)n * CIN + ci];
        }
        __syncthreads();
#pragma unroll
        for (int kk = 0; kk < 32; kk++) {
            float a[4], b[4];
#pragma unroll
            for (int i = 0; i < 4; i++) a[i] = As[kk][ty * 4 + i];
#pragma unroll
            for (int j = 0; j < 4; j++) b[j] = Bs[kk][tx * 4 + j];
#pragma unroll
            for (int i = 0; i < 4; i++)
#pragma unroll
                for (int j = 0; j < 4; j++)
                    acc[i][j] = fmaf(a[i], b[j], acc[i][j]);
        }
        __syncthreads();
    }
#pragma unroll
    for (int i = 0; i < 4; i++)
#pragma unroll
        for (int j = 0; j < 4; j++)
            Zs[ty * 4 + i][tx * 4 + j] = acc[i][j] + Bias[tx * 4 + j];
    __syncthreads();

    const int lane = tid & 31, w = tid >> 5;
#pragma unroll
    for (int q = 0; q < 8; q++) {
        const int m = w * 8 + q;
        float v0 = Zs[m][lane];
        float v1 = Zs[m][lane + 32];
        float s = v0 + v1;
#pragma unroll
        for (int off = 16; off > 0; off >>= 1)
            s += __shfl_xor_sync(0xffffffffu, s, off);
        float mu = s * (1.f / 64.f);
        float d0 = v0 - mu, d1 = v1 - mu;
        float sq = __fadd_rn(__fmul_rn(d0, d0), __fmul_rn(d1, d1));
#pragma unroll
        for (int off = 16; off > 0; off >>= 1)
            sq += __shfl_xor_sync(0xffffffffu, sq, off);
        float var = sq * (1.f / 64.f);
        float rs  = rsqrtf(var + LN_EPS);
        const int p = pm0 + m;
        Z[(size_t)p * 64 + lane]      = d0 * rs * G[lane]      + Bt[lane];
        Z[(size_t)p * 64 + lane + 32] = d1 * rs * G[lane + 32] + Bt[lane + 32];
    }
}

// ---------------- codebook norms (no FMA: match sum(c*c)) --------------------
__global__ void cnorm_kernel(const float* __restrict__ CB, float* __restrict__ CN)
{
    int c = blockIdx.x * blockDim.x + threadIdx.x;
    if (c < KCODE) {
        float s = 0.f;
        for (int d = 0; d < DDIM; d++) {
            float v = CB[c * DDIM + d];
            s = __fadd_rn(s, __fmul_rn(v, v));
        }
        CN[c] = s;
    }
}

// ---------------- VQ: argmin over codes + commit-loss partials ---------------
__global__ void __launch_bounds__(256)
vq_kernel(const float* __restrict__ Z, const float* __restrict__ CB,
          const float* __restrict__ CN, int* __restrict__ Codes,
          float* __restrict__ CommitPart)
{
    __shared__ float Zt[64][66];
    __shared__ float Cs[64][66];
    __shared__ float znS[64];
    __shared__ float cvals[64];

    const int pm0 = blockIdx.x * 64;
    const int tid = threadIdx.x;
    const int tx = tid & 15, ty = tid >> 4;

#pragma unroll
    for (int i = 0; i < 16; i++) {
        int idx = tid + i * 256;
        int m = idx >> 6, d = idx & 63;
        Zt[d][m] = Z[(size_t)(pm0 + m) * 64 + d];
    }
    __syncthreads();

    if (tid < 64) {
        const int m = tid;
        float s = 0.f;
        for (int d = 0; d < 64; d++) {
            float v = Zt[d][m];
            s = __fadd_rn(s, __fmul_rn(v, v));
        }
        znS[m] = s;
    }
    __syncthreads();

    float zm[4];
#pragma unroll
    for (int i = 0; i < 4; i++) zm[i] = znS[ty * 4 + i];

    float minv[4]; int mini[4];
#pragma unroll
    for (int i = 0; i < 4; i++) { minv[i] = 3.4e38f; mini[i] = 0; }

    for (int c0 = 0; c0 < KCODE; c0 += 64) {
        __syncthreads();
#pragma unroll
        for (int i = 0; i < 16; i++) {
            int idx = tid + i * 256;
            int c = idx >> 6, d = idx & 63;
            Cs[d][c] = CB[(size_t)(c0 + c) * 64 + d];
        }
        __syncthreads();

        float dot[4][4];
#pragma unroll
        for (int i = 0; i < 4; i++)
#pragma unroll
            for (int j = 0; j < 4; j++) dot[i][j] = 0.f;
#pragma unroll
        for (int kk = 0; kk < 64; kk++) {
            float a[4], b[4];
#pragma unroll
            for (int i = 0; i < 4; i++) a[i] = Zt[kk][ty * 4 + i];
#pragma unroll
            for (int j = 0; j < 4; j++) b[j] = Cs[kk][tx * 4 + j];
#pragma unroll
            for (int i = 0; i < 4; i++)
#pragma unroll
                for (int j = 0; j < 4; j++)
                    dot[i][j] = fmaf(a[i], b[j], dot[i][j]);
        }
#pragma unroll
        for (int j = 0; j < 4; j++) {
            const int c = c0 + tx * 4 + j;
            const float cn = CN[c];
#pragma unroll
            for (int i = 0; i < 4; i++) {
                float t    = __fadd_rn(zm[i], -__fmul_rn(2.f, dot[i][j]));
                float dist = __fadd_rn(t, cn);
                if (dist < minv[i]) { minv[i] = dist; mini[i] = c; }
            }
        }
    }
    __syncthreads();

    float* redv = &Cs[0][0];
    int*   redi = reinterpret_cast<int*>(&Cs[0][0]) + 1024;
#pragma unroll
    for (int i = 0; i < 4; i++) {
        const int m = ty * 4 + i;
        redv[m * 16 + tx] = minv[i];
        redi[m * 16 + tx] = mini[i];
    }
    __syncthreads();
    if (tid < 64) {
        const int m = tid;
        float bv = redv[m * 16];
        int   bi = redi[m * 16];
        for (int t = 1; t < 16; t++) {
            float v = redv[m * 16 + t];
            int  ix = redi[m * 16 + t];
            if (v < bv || (v == bv && ix < bi)) { bv = v; bi = ix; }
        }
        Codes[pm0 + m] = bi;
        cvals[m] = bv;
    }
    __syncthreads();
    if (tid == 0) {
        float s = 0.f;
        for (int m = 0; m < 64; m++) s += cvals[m];
        CommitPart[blockIdx.x] = s;
    }
}

// ---------------- gather z_q with fused bf16 hi/lo split ----------------------
__global__ void gather_zq_split(const int* __restrict__ codes,
                                const float* __restrict__ CB,
                                bf16* __restrict__ Hi, bf16* __restrict__ Lo)
{
    int idx = blockIdx.x * blockDim.x + threadIdx.x;   // NPOS*16 float4s
    int n = idx >> 4;
    int j = idx & 15;
    float4 v = reinterpret_cast<const float4*>(CB)[codes[n] * 16 + j];
    bf16 h0 = __float2bfloat16(v.x), h1 = __float2bfloat16(v.y);
    bf16 h2 = __float2bfloat16(v.z), h3 = __float2bfloat16(v.w);
    __nv_bfloat162 hh0; hh0.x = h0; hh0.y = h1;
    __nv_bfloat162 hh1; hh1.x = h2; hh1.y = h3;
    __nv_bfloat162 ll0; ll0.x = __float2bfloat16(v.x - __bfloat162float(h0));
    ll0.y = __float2bfloat16(v.y - __bfloat162float(h1));
    __nv_bfloat162 ll1; ll1.x = __float2bfloat16(v.z - __bfloat162float(h2));
    ll1.y = __float2bfloat16(v.w - __bfloat162float(h3));
    reinterpret_cast<__nv_bfloat162*>(Hi)[n * 32 + j * 2 + 0] = hh0;
    reinterpret_cast<__nv_bfloat162*>(Hi)[n * 32 + j * 2 + 1] = hh1;
    reinterpret_cast<__nv_bfloat162*>(Lo)[n * 32 + j * 2 + 0] = ll0;
    reinterpret_cast<__nv_bfloat162*>(Lo)[n * 32 + j * 2 + 1] = ll1;
}

// ---------------- LayerNorm over E=128 + fused split --------------------------
__global__ void ln128_split(const float* __restrict__ X,
                            const float* __restrict__ G,
                            const float* __restrict__ B,
                            bf16* __restrict__ Hi, bf16* __restrict__ Lo)
{
    const int w = threadIdx.x >> 5, lane = threadIdx.x & 31;
    const int p = blockIdx.x * 8 + w;
    float v[4];
#pragma unroll
    for (int i = 0; i < 4; i++) v[i] = X[(size_t)p * 128 + lane + 32 * i];
    float s = 0.f;
#pragma unroll
    for (int i = 0; i < 4; i++) s += v[i];
#pragma unroll
    for (int off = 16; off > 0; off >>= 1)
        s += __shfl_xor_sync(0xffffffffu, s, off);
    float mu = s * (1.f / 128.f);
    float d[4];
    float sq = 0.f;
#pragma unroll
    for (int i = 0; i < 4; i++) {
        d[i] = v[i] - mu;
        sq = __fadd_rn(sq, __fmul_rn(d[i], d[i]));
    }
#pragma unroll
    for (int off = 16; off > 0; off >>= 1)
        sq += __shfl_xor_sync(0xffffffffu, sq, off);
    float var = sq * (1.f / 128.f);
    float rs  = rsqrtf(var + LN_EPS);
#pragma unroll
    for (int i = 0; i < 4; i++) {
        const int c = lane + 32 * i;
        float y = d[i] * rs * G[c] + B[c];
        bf16 h = __float2bfloat16(y);
        Hi[(size_t)p * 128 + c] = h;
        Lo[(size_t)p * 128 + c] = __float2bfloat16(y - __bfloat162float(h));
    }
}

// ---------------- mma helpers -------------------------------------------------
__device__ __forceinline__ void ldsm_x4(uint32_t* r, uint32_t addr) {
    asm volatile("ldmatrix.sync.aligned.m8n8.x4.shared.b16 {%0,%1,%2,%3}, [%4];"
                 : "=r"(r[0]), "=r"(r[1]), "=r"(r[2]), "=r"(r[3]) : "r"(addr));
}
__device__ __forceinline__ void mma16816(float* d, const uint32_t* a,
                                         uint32_t b0, uint32_t b1) {
    asm volatile(
        "mma.sync.aligned.m16n8k16.row.col.f32.bf16.bf16.f32 "
        "{%0,%1,%2,%3}, {%4,%5,%6,%7}, {%8,%9}, {%0,%1,%2,%3};"
        : "+f"(d[0]), "+f"(d[1]), "+f"(d[2]), "+f"(d[3])
        : "r"(a[0]), "r"(a[1]), "r"(a[2]), "r"(a[3]), "r"(b0), "r"(b1));
}
__device__ __forceinline__ void mma16816h(float* d, const uint32_t* a,
                                          uint32_t b0, uint32_t b1) {
    asm volatile(
        "mma.sync.aligned.m16n8k16.row.col.f32.f16.f16.f32 "
        "{%0,%1,%2,%3}, {%4,%5,%6,%7}, {%8,%9}, {%0,%1,%2,%3};"
        : "+f"(d[0]), "+f"(d[1]), "+f"(d[2]), "+f"(d[3])
        : "r"(a[0]), "r"(a[1]), "r"(a[2]), "r"(a[3]), "r"(b0), "r"(b1));
}

// ---------------- generic bf16x3 (hi/lo) tensor conv, 3-buffer pipeline ------
// Three 64KB smem buffers; ONE __syncthreads per chunk. Load of chunk ch+2
// lands in the buffer of ch-1, whose compute finished before this iteration's
// barrier.
#define TC_SMEM 196608

template<int CIN, int KW, int COUT, bool RELU, bool WF32, bool WSPLIT>
__global__ void __launch_bounds__(256)
tconv(const bf16* __restrict__ Ahi, const bf16* __restrict__ Alo,
      const bf16* __restrict__ Whi, const bf16* __restrict__ Wlo,
      const float* __restrict__ Bias,
      float* __restrict__ Yf, bf16* __restrict__ Yhi, bf16* __restrict__ Ylo)
{
    constexpr int KTOT = CIN * KW;
    constexpr int NCH  = KTOT / 64;
    constexpr int PAD  = (KW == 3) ? 1 : 0;

    extern __shared__ char smem[];
    const int tid = threadIdx.x;
    const int pm0 = blockIdx.x * 128;
    const int nv0 = blockIdx.y * 128;

    const int wid = tid >> 5, lane = tid & 31;
    const int wm = (wid >> 1) * 32;
    const int wn = (wid & 1) * 64;
    const int lr = lane & 7, lq = lane >> 3;

    float acc[2][8][4];
#pragma unroll
    for (int mi = 0; mi < 2; mi++)
#pragma unroll
        for (int ni = 0; ni < 8; ni++)
#pragma unroll
            for (int e = 0; e < 4; e++) acc[mi][ni][e] = 0.f;

    const uint4* A4h = reinterpret_cast<const uint4*>(Ahi);
    const uint4* A4l = reinterpret_cast<const uint4*>(Alo);
    const uint4* B4h = reinterpret_cast<const uint4*>(Whi);
    const uint4* B4l = reinterpret_cast<const uint4*>(Wlo);

    const uint32_t sb = smem_to_u32(smem);

    auto load_chunk = [&](int ch, int buf) {
        const uint32_t bo = (uint32_t)buf * 65536u;
        const int tap = (ch * 64) / CIN;
        const int ci0 = (ch * 64) % CIN;
#pragma unroll
        for (int i = 0; i < 4; i++) {
            int idx = tid + i * 256;
            int row = idx >> 3, c = idx & 7;
            int p = pm0 + row;
            bool ok = true;
            if (KW == 3) {
                int ls = (p & (LSEQ - 1)) + tap - PAD;
                ok = ((unsigned)ls < (unsigned)LSEQ);
            }
            size_t gi = ok ? ((size_t)(p + tap - PAD) * (CIN / 8) + (ci0 / 8) + c) : 0;
            int nb = ok ? 16 : 0;
            int pc = (c ^ row) & 7;
            uint32_t so = (uint32_t)(row * 128 + pc * 16);
            cp_async16(sb + bo + so,          A4h + gi, nb);
            cp_async16(sb + bo + 16384u + so, A4l + gi, nb);
        }
#pragma unroll
        for (int i = 0; i < 4; i++) {
            int idx = tid + i * 256;
            int row = idx >> 3, c = idx & 7;
            size_t gi = (size_t)(nv0 + row) * (KTOT / 8) + ch * 8 + c;
            int pc = (c ^ row) & 7;
            uint32_t so = (uint32_t)(row * 128 + pc * 16);
            cp_async16(sb + bo + 32768u + so, B4h + gi, 16);
            cp_async16(sb + bo + 49152u + so, B4l + gi, 16);
        }
        asm volatile("cp.async.commit_group;");
    };

    load_chunk(0, 0);
    if (1 < NCH) load_chunk(1, 1);

    for (int ch = 0; ch < NCH; ch++) {
        if (ch + 1 < NCH)
            asm volatile("cp.async.wait_group 1;");
        else
            asm volatile("cp.async.wait_group 0;");
        __syncthreads();
        if (ch + 2 < NCH) load_chunk(ch + 2, (ch + 2) % 3);

        const uint32_t bo = (uint32_t)(ch % 3) * 65536u;
        const uint32_t aB3[3] = { sb + bo, sb + bo, sb + bo + 16384u };
        const uint32_t bB3[3] = { sb + bo + 32768u, sb + bo + 49152u, sb + bo + 32768u };
#pragma unroll
        for (int s = 0; s < 3; s++) {
            const uint32_t aB = aB3[s];
            const uint32_t bB = bB3[s];
#pragma unroll
            for (int k16 = 0; k16 < 4; k16++) {
                const int kc0 = k16 * 2;
                uint32_t a[2][4];
#pragma unroll
                for (int mi = 0; mi < 2; mi++) {
                    int row = wm + mi * 16 + lr + (lq & 1) * 8;
                    int kc  = kc0 + (lq >> 1);
                    int pc  = (kc ^ row) & 7;
                    ldsm_x4(a[mi], aB + row * 128 + pc * 16);
                }
                uint32_t b[4][4];
#pragma unroll
                for (int nc = 0; nc < 4; nc++) {
                    int row = wn + nc * 16 + lr + (lq >> 1) * 8;
                    int kc  = kc0 + (lq & 1);
                    int pc  = (kc ^ row) & 7;
                    ldsm_x4(b[nc], bB + row * 128 + pc * 16);
                }
#pragma unroll
                for (int mi = 0; mi < 2; mi++)
#pragma unroll
                    for (int ni = 0; ni < 8; ni++)
                        mma16816(acc[mi][ni], a[mi],
                                 b[ni >> 1][(ni & 1) * 2 + 0],
                                 b[ni >> 1][(ni & 1) * 2 + 1]);
            }
        }
    }

    const int gid = lane >> 2, tig = lane & 3;
#pragma unroll
    for (int mi = 0; mi < 2; mi++) {
        const int m0 = pm0 + wm + mi * 16 + gid;
#pragma unroll
        for (int ni = 0; ni < 8; ni++) {
            const int n = nv0 + wn + ni * 8 + tig * 2;
            const float2 bv = *reinterpret_cast<const float2*>(Bias + n);
            float v00 = acc[mi][ni][0] + bv.x;
            float v01 = acc[mi][ni][1] + bv.y;
            float v10 = acc[mi][ni][2] + bv.x;
            float v11 = acc[mi][ni][3] + bv.y;
            if (RELU) {
                v00 = fmaxf(v00, 0.f); v01 = fmaxf(v01, 0.f);
                v10 = fmaxf(v10, 0.f); v11 = fmaxf(v11, 0.f);
            }
            if (WF32) {
                float2 a0; a0.x = v00; a0.y = v01;
                float2 a1; a1.x = v10; a1.y = v11;
                *reinterpret_cast<float2*>(Yf + (size_t)m0 * COUT + n)       = a0;
                *reinterpret_cast<float2*>(Yf + (size_t)(m0 + 8) * COUT + n) = a1;
            }
            if (WSPLIT) {
                bf16 h00 = __float2bfloat16(v00), h01 = __float2bfloat16(v01);
                bf16 h10 = __float2bfloat16(v10), h11 = __float2bfloat16(v11);
                __nv_bfloat162 hh0; hh0.x = h00; hh0.y = h01;
                __nv_bfloat162 hh1; hh1.x = h10; hh1.y = h11;
                __nv_bfloat162 ll0;
                ll0.x = __float2bfloat16(v00 - __bfloat162float(h00));
                ll0.y = __float2bfloat16(v01 - __bfloat162float(h01));
                __nv_bfloat162 ll1;
                ll1.x = __float2bfloat16(v10 - __bfloat162float(h10));
                ll1.y = __float2bfloat16(v11 - __bfloat162float(h11));
                *reinterpret_cast<__nv_bfloat162*>(Yhi + (size_t)m0 * COUT + n)       = hh0;
                *reinterpret_cast<__nv_bfloat162*>(Yhi + (size_t)(m0 + 8) * COUT + n) = hh1;
                *reinterpret_cast<__nv_bfloat162*>(Ylo + (size_t)m0 * COUT + n)       = ll0;
                *reinterpret_cast<__nv_bfloat162*>(Ylo + (size_t)(m0 + 8) * COUT + n) = ll1;
            }
        }
    }
}

// ---------------- fp16 two-split tensor conv (encoder), 3-buffer pipeline ----
template<int CIN, int KW, int COUT, bool WF32>
__global__ void __launch_bounds__(256)
tconvh(const half* __restrict__ Ah, const half* __restrict__ Am,
       const half* __restrict__ Wh, const half* __restrict__ Wm,
       const float* __restrict__ Bias, float* __restrict__ Yf,
       half* __restrict__ Yh, half* __restrict__ Ym)
{
    constexpr int KTOT = CIN * KW;
    constexpr int NCH  = KTOT / 64;
    constexpr int PAD  = (KW == 3) ? 1 : 0;

    extern __shared__ char smem[];
    const int tid = threadIdx.x;
    const int pm0 = blockIdx.x * 128;
    const int nv0 = blockIdx.y * 128;

    const int wid = tid >> 5, lane = tid & 31;
    const int wm = (wid >> 1) * 32;
    const int wn = (wid & 1) * 64;
    const int lr = lane & 7, lq = lane >> 3;

    float acc1[2][8][4];
    float acc2[2][8][4];
#pragma unroll
    for (int mi = 0; mi < 2; mi++)
#pragma unroll
        for (int ni = 0; ni < 8; ni++)
#pragma unroll
            for (int e = 0; e < 4; e++) { acc1[mi][ni][e] = 0.f; acc2[mi][ni][e] = 0.f; }

    const uint4* A4h = reinterpret_cast<const uint4*>(Ah);
    const uint4* A4m = reinterpret_cast<const uint4*>(Am);
    const uint4* B4h = reinterpret_cast<const uint4*>(Wh);
    const uint4* B4m = reinterpret_cast<const uint4*>(Wm);

    const uint32_t sb = smem_to_u32(smem);

    auto load_chunk = [&](int ch, int buf) {
        const uint32_t bo = (uint32_t)buf * 65536u;
        const int tap = (ch * 64) / CIN;
        const int ci0 = (ch * 64) % CIN;
#pragma unroll
        for (int i = 0; i < 4; i++) {
            int idx = tid + i * 256;
            int row = idx >> 3, c = idx & 7;
            int p = pm0 + row;
            bool ok = true;
            if (KW == 3) {
                int ls = (p & (LSEQ - 1)) + tap - PAD;
                ok = ((unsigned)ls < (unsigned)LSEQ);
            }
            size_t gi = ok ? ((size_t)(p + tap - PAD) * (CIN / 8) + (ci0 / 8) + c) : 0;
            int nb = ok ? 16 : 0;
            int pc = (c ^ row) & 7;
            uint32_t so = (uint32_t)(row * 128 + pc * 16);
            cp_async16(sb + bo + so,          A4h + gi, nb);
            cp_async16(sb + bo + 16384u + so, A4m + gi, nb);
        }
#pragma unroll
        for (int i = 0; i < 4; i++) {
            int idx = tid + i * 256;
            int row = idx >> 3, c = idx & 7;
            size_t gi = (size_t)(nv0 + row) * (KTOT / 8) + ch * 8 + c;
            int pc = (c ^ row) & 7;
            uint32_t so = (uint32_t)(row * 128 + pc * 16);
            cp_async16(sb + bo + 32768u + so, B4h + gi, 16);
            cp_async16(sb + bo + 49152u + so, B4m + gi, 16);
        }
        asm volatile("cp.async.commit_group;");
    };

    load_chunk(0, 0);
    if (1 < NCH) load_chunk(1, 1);

    for (int ch = 0; ch < NCH; ch++) {
        if (ch + 1 < NCH)
            asm volatile("cp.async.wait_group 1;");
        else
            asm volatile("cp.async.wait_group 0;");
        __syncthreads();
        if (ch + 2 < NCH) load_chunk(ch + 2, (ch + 2) % 3);

        const uint32_t bo = (uint32_t)(ch % 3) * 65536u;
        const uint32_t aB3[3] = { sb + bo, sb + bo, sb + bo + 16384u };
        const uint32_t bB3[3] = { sb + bo + 32768u, sb + bo + 49152u, sb + bo + 32768u };
#pragma unroll
        for (int s = 0; s < 3; s++) {
            const uint32_t aB = aB3[s];
            const uint32_t bB = bB3[s];
#pragma unroll
            for (int k16 = 0; k16 < 4; k16++) {
                const int kc0 = k16 * 2;
                uint32_t a[2][4];
#pragma unroll
                for (int mi = 0; mi < 2; mi++) {
                    int row = wm + mi * 16 + lr + (lq & 1) * 8;
                    int kc  = kc0 + (lq >> 1);
                    int pc  = (kc ^ row) & 7;
                    ldsm_x4(a[mi], aB + row * 128 + pc * 16);
                }
                uint32_t b[4][4];
#pragma unroll
                for (int nc = 0; nc < 4; nc++) {
                    int row = wn + nc * 16 + lr + (lq >> 1) * 8;
                    int kc  = kc0 + (lq & 1);
                    int pc  = (kc ^ row) & 7;
                    ldsm_x4(b[nc], bB + row * 128 + pc * 16);
                }
                float (*acc)[8][4] = (s == 0) ? acc1 : acc2;
#pragma unroll
                for (int mi = 0; mi < 2; mi++)
#pragma unroll
                    for (int ni = 0; ni < 8; ni++)
                        mma16816h(acc[mi][ni], a[mi],
                                  b[ni >> 1][(ni & 1) * 2 + 0],
                                  b[ni >> 1][(ni & 1) * 2 + 1]);
            }
        }
    }

    const int gid = lane >> 2, tig = lane & 3;
#pragma unroll
    for (int mi = 0; mi < 2; mi++) {
        const int m0 = pm0 + wm + mi * 16 + gid;
#pragma unroll
        for (int ni = 0; ni < 8; ni++) {
            const int n = nv0 + wn + ni * 8 + tig * 2;
            const float2 bv = *reinterpret_cast<const float2*>(Bias + n);
            float v00 = fmaxf(fmaf(acc2[mi][ni][0], LO_INV, acc1[mi][ni][0]) + bv.x, 0.f);
            float v01 = fmaxf(fmaf(acc2[mi][ni][1], LO_INV, acc1[mi][ni][1]) + bv.y, 0.f);
            float v10 = fmaxf(fmaf(acc2[mi][ni][2], LO_INV, acc1[mi][ni][2]) + bv.x, 0.f);
            float v11 = fmaxf(fmaf(acc2[mi][ni][3], LO_INV, acc1[mi][ni][3]) + bv.y, 0.f);
            if (WF32) {
                float2 a0; a0.x = v00; a0.y = v01;
                float2 a1; a1.x = v10; a1.y = v11;
                *reinterpret_cast<float2*>(Yf + (size_t)m0 * COUT + n)       = a0;
                *reinterpret_cast<float2*>(Yf + (size_t)(m0 + 8) * COUT + n) = a1;
            } else {
                half h00,m00,h01,m01,h10,m10,h11,m11;
                split2h(v00,h00,m00); split2h(v01,h01,m01);
                split2h(v10,h10,m10); split2h(v11,h11,m11);
                __half2 p0, p1;
                p0.x=h00; p0.y=h01; p1.x=h10; p1.y=h11;
                *reinterpret_cast<__half2*>(Yh + (size_t)m0 * COUT + n)       = p0;
                *reinterpret_cast<__half2*>(Yh + (size_t)(m0 + 8) * COUT + n) = p1;
                p0.x=m00; p0.y=m01; p1.x=m10; p1.y=m11;
                *reinterpret_cast<__half2*>(Ym + (size_t)m0 * COUT + n)       = p0;
                *reinterpret_cast<__half2*>(Ym + (size_t)(m0 + 8) * COUT + n) = p1;
            }
        }
    }
}

// ---------------- wide full-K-resident bf16x3 logits GEMM --------------------
// Term-staged cp.async: hi tiles (group0) -> compute hh while lo tiles land.
#define LGW_SMEM 196608

__global__ void __launch_bounds__(256, 1)
logits_wide(const bf16* __restrict__ Ahi, const bf16* __restrict__ Alo,
            const bf16* __restrict__ Bhi, const bf16* __restrict__ Blo,
            const float* __restrict__ Bias, float* __restrict__ Out)
{
    extern __shared__ char smem[];
    const int tid = threadIdx.x;
    const int pm0 = blockIdx.x * 128;
    const int nv0 = blockIdx.y * 256;

    const uint32_t sb = smem_to_u32(smem);
    // layout: sAhi 0..32K, sAlo 32K..64K, sBhi 64K..128K, sBlo 128K..192K

    // group 0: hi tiles
    {
        const uint4* A4h = reinterpret_cast<const uint4*>(Ahi);
#pragma unroll
        for (int i = 0; i < 8; i++) {
            int idx = tid + i * 256;
            int row = idx >> 4, c = idx & 15;
            int pc = (c & 8) | ((c ^ row) & 7);
            cp_async16(sb + (uint32_t)(row * 256 + pc * 16),
                       A4h + (size_t)(pm0 + row) * 16 + c, 16);
        }
        const uint4* B4h = reinterpret_cast<const uint4*>(Bhi);
#pragma unroll
        for (int i = 0; i < 16; i++) {
            int idx = tid + i * 256;
            int row = idx >> 4, c = idx & 15;
            int pc = (c & 8) | ((c ^ row) & 7);
            cp_async16(sb + 65536u + (uint32_t)(row * 256 + pc * 16),
                       B4h + (size_t)(nv0 + row) * 16 + c, 16);
        }
        asm volatile("cp.async.commit_group;");
    }
    // group 1: lo tiles
    {
        const uint4* A4l = reinterpret_cast<const uint4*>(Alo);
#pragma unroll
        for (int i = 0; i < 8; i++) {
            int idx = tid + i * 256;
            int row = idx >> 4, c = idx & 15;
            int pc = (c & 8) | ((c ^ row) & 7);
            cp_async16(sb + 32768u + (uint32_t)(row * 256 + pc * 16),
                       A4l + (size_t)(pm0 + row) * 16 + c, 16);
        }
        const uint4* B4l = reinterpret_cast<const uint4*>(Blo);
#pragma unroll
        for (int i = 0; i < 16; i++) {
            int idx = tid + i * 256;
            int row = idx >> 4, c = idx & 15;
            int pc = (c & 8) | ((c ^ row) & 7);
            cp_async16(sb + 131072u + (uint32_t)(row * 256 + pc * 16),
                       B4l + (size_t)(nv0 + row) * 16 + c, 16);
        }
        asm volatile("cp.async.commit_group;");
    }

    const int wid = tid >> 5, lane = tid & 31;
    const int wm = (wid >> 1) * 32;       // 0,32,64,96
    const int wn = (wid & 1) * 128;       // 0,128
    const int lr = lane & 7, lq = lane >> 3;

    float acc[2][16][4];
#pragma unroll
    for (int mi = 0; mi < 2; mi++)
#pragma unroll
        for (int ni = 0; ni < 16; ni++)
#pragma unroll
            for (int e = 0; e < 4; e++) acc[mi][ni][e] = 0.f;

    const uint32_t aB3[3] = { sb, sb, sb + 32768u };                   // hi, hi, lo
    const uint32_t bB3[3] = { sb + 65536u, sb + 131072u, sb + 65536u };// hi, lo, hi

    asm volatile("cp.async.wait_group 1;");
    __syncthreads();

#pragma unroll
    for (int s = 0; s < 3; s++) {
        if (s == 1) {
            asm volatile("cp.async.wait_group 0;");
            __syncthreads();
        }
        const uint32_t aB = aB3[s];
        const uint32_t bB = bB3[s];
#pragma unroll
        for (int k16 = 0; k16 < 8; k16++) {
            const int kc0 = k16 * 2;
            uint32_t a[2][4];
#pragma unroll
            for (int mi = 0; mi < 2; mi++) {
                int row = wm + mi * 16 + lr + (lq & 1) * 8;
                int kc  = kc0 + (lq >> 1);
                int pc  = (kc & 8) | ((kc ^ row) & 7);
                ldsm_x4(a[mi], aB + row * 256 + pc * 16);
            }
#pragma unroll
            for (int nc = 0; nc < 8; nc++) {
                uint32_t b[4];
                int row = wn + nc * 16 + lr + (lq >> 1) * 8;
                int kc  = kc0 + (lq & 1);
                int pc  = (kc & 8) | ((kc ^ row) & 7);
                ldsm_x4(b, bB + row * 256 + pc * 16);
                mma16816(acc[0][nc * 2 + 0], a[0], b[0], b[1]);
                mma16816(acc[0][nc * 2 + 1], a[0], b[2], b[3]);
                mma16816(acc[1][nc * 2 + 0], a[1], b[0], b[1]);
                mma16816(acc[1][nc * 2 + 1], a[1], b[2], b[3]);
            }
        }
    }

    const int gid = lane >> 2, tig = lane & 3;
#pragma unroll
    for (int mi = 0; mi < 2; mi++) {
        const int m0 = pm0 + wm + mi * 16 + gid;
#pragma unroll
        for (int ni = 0; ni < 16; ni++) {
            const int n = nv0 + wn + ni * 8 + tig * 2;
            const float2 bv = *reinterpret_cast<const float2*>(Bias + n);
            float2 v0, v1;
            v0.x = acc[mi][ni][0] + bv.x;  v0.y = acc[mi][ni][1] + bv.y;
            v1.x = acc[mi][ni][2] + bv.x;  v1.y = acc[mi][ni][3] + bv.y;
            *reinterpret_cast<float2*>(Out + (size_t)m0 * VOCAB + n)       = v0;
            *reinterpret_cast<float2*>(Out + (size_t)(m0 + 8) * VOCAB + n) = v1;
        }
    }
}

// ---------------- tail: loss scalar + codes ----------------------------------
__global__ void commit_final(const float* __restrict__ Part, float* __restrict__ slot)
{
    if (threadIdx.x == 0 && blockIdx.x == 0) {
        float s = 0.f;
        for (int i = 0; i < NPOS / 64; i++) s += Part[i];
        *slot = 0.1f * s / ((float)NPOS * (float)DDIM);
    }
}

__global__ void write_codes(const int* __restrict__ codes, float* __restrict__ out)
{
    int n = blockIdx.x * blockDim.x + threadIdx.x;
    if (n < NPOS) out[n] = (float)codes[n];
}

// ---------------- launch ------------------------------------------------------
extern "C" void kernel_launch(void* const* d_in, const int* in_sizes, int n_in,
                              void* d_out, int out_size)
{
    (void)in_sizes; (void)n_in;
    const int*   x    = (const int*)  d_in[0];
    const float* tok  = (const float*)d_in[1];
    const float* ew1  = (const float*)d_in[2];
    const float* eb1  = (const float*)d_in[3];
    const float* ew2  = (const float*)d_in[4];
    const float* eb2  = (const float*)d_in[5];
    const float* ew3  = (const float*)d_in[6];
    const float* eb3  = (const float*)d_in[7];
    const float* elg  = (const float*)d_in[8];
    const float* elb  = (const float*)d_in[9];
    const float* cb   = (const float*)d_in[10];
    const float* dw1  = (const float*)d_in[11];
    const float* db1  = (const float*)d_in[12];
    const float* dw2  = (const float*)d_in[13];
    const float* db2  = (const float*)d_in[14];
    const float* dw3  = (const float*)d_in[15];
    const float* db3  = (const float*)d_in[16];
    const float* dlg  = (const float*)d_in[17];
    const float* dlb  = (const float*)d_in[18];
    const float* ow   = (const float*)d_in[19];
    const float* ob   = (const float*)d_in[20];
    float* out = (float*)d_out;

    float *emb, *h2, *z, *cn, *cp;
    int* codes;
    half *ebh,*ebm,*e1h,*e1m,*w1eh,*w1em,*w2eh,*w2em;
    bf16 *zqhi,*zqlo,*d1hi,*d1lo,*d2hi,*d2lo,*ahi,*alo;
    bf16 *w1hi,*w1lo,*w2hi,*w2lo,*w3hi,*w3lo,*bhi,*blo;
    cudaGetSymbolAddress((void**)&emb,   g_emb);
    cudaGetSymbolAddress((void**)&h2,    g_h2);
    cudaGetSymbolAddress((void**)&z,     g_z);
    cudaGetSymbolAddress((void**)&codes, g_codes);
    cudaGetSymbolAddress((void**)&cn,    g_cnorm);
    cudaGetSymbolAddress((void**)&cp,    g_commit);
    cudaGetSymbolAddress((void**)&ebh,   g_ebh);
    cudaGetSymbolAddress((void**)&ebm,   g_ebm);
    cudaGetSymbolAddress((void**)&e1h,   g_e1h);
    cudaGetSymbolAddress((void**)&e1m,   g_e1m);
    cudaGetSymbolAddress((void**)&w1eh,  g_w1eh);
    cudaGetSymbolAddress((void**)&w1em,  g_w1em);
    cudaGetSymbolAddress((void**)&w2eh,  g_w2eh);
    cudaGetSymbolAddress((void**)&w2em,  g_w2em);
    cudaGetSymbolAddress((void**)&zqhi,  g_zqhi);
    cudaGetSymbolAddress((void**)&zqlo,  g_zqlo);
    cudaGetSymbolAddress((void**)&d1hi,  g_d1hi);
    cudaGetSymbolAddress((void**)&d1lo,  g_d1lo);
    cudaGetSymbolAddress((void**)&d2hi,  g_d2hi);
    cudaGetSymbolAddress((void**)&d2lo,  g_d2lo);
    cudaGetSymbolAddress((void**)&ahi,   g_ahi);
    cudaGetSymbolAddress((void**)&alo,   g_alo);
    cudaGetSymbolAddress((void**)&w1hi,  g_w1hi);
    cudaGetSymbolAddress((void**)&w1lo,  g_w1lo);
    cudaGetSymbolAddress((void**)&w2hi,  g_w2hi);
    cudaGetSymbolAddress((void**)&w2lo,  g_w2lo);
    cudaGetSymbolAddress((void**)&w3hi,  g_w3hi);
    cudaGetSymbolAddress((void**)&w3lo,  g_w3lo);
    cudaGetSymbolAddress((void**)&bhi,   g_bhi);
    cudaGetSymbolAddress((void**)&blo,   g_blo);

    cudaFuncSetAttribute((const void*)tconvh<128, 3, 256, false>,
                         cudaFuncAttributeMaxDynamicSharedMemorySize, TC_SMEM);
    cudaFuncSetAttribute((const void*)tconvh<256, 3, 256, true>,
                         cudaFuncAttributeMaxDynamicSharedMemorySize, TC_SMEM);
    cudaFuncSetAttribute((const void*)tconv< 64, 1, 256, true,  false, true >,
                         cudaFuncAttributeMaxDynamicSharedMemorySize, TC_SMEM);
    cudaFuncSetAttribute((const void*)tconv<256, 3, 256, true,  false, true >,
                         cudaFuncAttributeMaxDynamicSharedMemorySize, TC_SMEM);
    cudaFuncSetAttribute((const void*)tconv<256, 1, 128, true,  true,  false>,
                         cudaFuncAttributeMaxDynamicSharedMemorySize, TC_SMEM);
    cudaFuncSetAttribute((const void*)logits_wide,
                         cudaFuncAttributeMaxDynamicSharedMemorySize, LGW_SMEM);

    // ---- encoder (fp16 two-split tensor cores, pipelined) ----
    pack_split2h<128, 3, 256><<<(256*384)  / 256, 256>>>(ew1, w1eh, w1em);
    pack_split2h<256, 3, 256><<<(256*768)  / 256, 256>>>(ew2, w2eh, w2em);
    embed_split2h<<<NPOS * 32 / 256, 256>>>(x, tok, ebh, ebm);
    tconvh<128, 3, 256, false><<<dim3(NPOS/128, 2), 256, TC_SMEM>>>(
        ebh, ebm, w1eh, w1em, eb1, nullptr, e1h, e1m);
    tconvh<256, 3, 256, true ><<<dim3(NPOS/128, 2), 256, TC_SMEM>>>(
        e1h, e1m, w2eh, w2em, eb2, h2, nullptr, nullptr);
    enc_head_ln<<<NPOS / 64, 256>>>(h2, ew3, eb3, elg, elb, z);

    // ---- vector quantization ----
    cnorm_kernel<<<1, 512>>>(cb, cn);
    vq_kernel<<<NPOS / 64, 256>>>(z, cb, cn, codes, cp);
    gather_zq_split<<<NPOS * 16 / 256, 256>>>(codes, cb, zqhi, zqlo);

    // ---- decoder weight packs + decoder (bf16x3 tensor cores, pipelined) ----
    pack_split< 64, 1, 256>  <<<(256*64)   / 256, 256>>>(dw1, w1hi, w1lo);
    pack_split<256, 3, 256>  <<<(256*768)  / 256, 256>>>(dw2, w2hi, w2lo);
    pack_split<256, 1, 128>  <<<(128*256)  / 256, 256>>>(dw3, w3hi, w3lo);
    pack_split<128, 1, VOCAB><<<(VOCAB*128)/ 256, 256>>>(ow,  bhi,  blo);

    tconv< 64, 1, 256, true,  false, true ><<<dim3(NPOS/128, 2),  256, TC_SMEM>>>(
        zqhi, zqlo, w1hi, w1lo, db1, nullptr, d1hi, d1lo);
    tconv<256, 3, 256, true,  false, true ><<<dim3(NPOS/128, 2),  256, TC_SMEM>>>(
        d1hi, d1lo, w2hi, w2lo, db2, nullptr, d2hi, d2lo);
    tconv<256, 1, 128, true,  true,  false><<<dim3(NPOS/128, 1),  256, TC_SMEM>>>(
        d2hi, d2lo, w3hi, w3lo, db3, emb, nullptr, nullptr);
    ln128_split<<<NPOS / 8, 256>>>(emb, dlg, dlb, ahi, alo);

    // ---- vocab projection (wide full-K bf16x3, term-staged) -> d_out ----
    logits_wide<<<dim3(NPOS/128, VOCAB/256), 256, LGW_SMEM>>>(
        ahi, alo, bhi, blo, ob, out);

    // ---- tail: loss scalar + codes ----
    const long long NV = (long long)NPOS * VOCAB;   // 134217728
    if ((long long)out_size >= NV + 1)
        commit_final<<<1, 32>>>(cp, out + NV);
    if ((long long)out_size >= NV + 1 + NPOS)
        write_codes<<<NPOS / 256, 256>>>(codes, out + NV + 1);
}